// round 1
// baseline (speedup 1.0000x reference)
#include <cuda_runtime.h>
#include <math.h>
#include <stdint.h>

// ----------------------------------------------------------------------------
// Problem constants
// ----------------------------------------------------------------------------
#define LH 512      // hidden size
#define DI 512      // input size
#define NA 1000     // num actions
#define BB 256      // batch
#define TBMAX 65536 // T*B

// ----------------------------------------------------------------------------
// Scratch (static device allocations; no cudaMalloc anywhere)
// ----------------------------------------------------------------------------
__device__ float g_buf1[(size_t)TBMAX * LH];     // H1 / A1 / CH (sequentially reused)
__device__ float g_h2  [(size_t)TBMAX * LH];     // trunk output (residual source)
__device__ float g_xg  [(size_t)TBMAX * 4 * LH]; // x@Wih^T + bih + bhh
__device__ float g_nh  [(size_t)TBMAX * LH];     // new_hidden
__device__ float g_logits[(size_t)TBMAX * NA];
__device__ float g_hbuf[2 * BB * LH];            // h ping-pong
__device__ float g_cbuf[BB * LH];                // c (in place)

__device__ __forceinline__ float sigm(float x) { return 1.0f / (1.0f + expf(-x)); }

// ----------------------------------------------------------------------------
// Generic tiled fp32 GEMM:  C[M,N] = A[M,K] @ W[N,K]^T + b1 (+ b2) ; opt tanh
// BM=BN=128, BK=16, 256 threads, 8x8 per thread. M % 128 == 0 assumed.
// ----------------------------------------------------------------------------
__global__ __launch_bounds__(256)
void gemm_kernel(const float* __restrict__ A, const float* __restrict__ W,
                 const float* __restrict__ b1, const float* __restrict__ b2,
                 float* __restrict__ C, int M, int N, int K, int act)
{
    __shared__ float As[16][132];
    __shared__ float Bs[16][132];

    const int tid = threadIdx.x;
    const int m0 = blockIdx.y * 128;
    const int n0 = blockIdx.x * 128;

    const int tr = (tid / 16) * 8;
    const int tc = (tid % 16) * 8;

    float acc[8][8];
#pragma unroll
    for (int i = 0; i < 8; i++)
#pragma unroll
        for (int j = 0; j < 8; j++) acc[i][j] = 0.0f;

    const int nkt = K / 16;
    for (int kt = 0; kt < nkt; kt++) {
        const int k0 = kt * 16;
        // load A tile (128 x 16), transpose-store
#pragma unroll
        for (int l = 0; l < 2; l++) {
            int id = tid + l * 256;          // 0..511
            int row = id >> 2;               // 0..127
            int f   = id & 3;                // float4 index in k
            float4 v = *(const float4*)&A[(size_t)(m0 + row) * K + k0 + f * 4];
            As[f * 4 + 0][row] = v.x;
            As[f * 4 + 1][row] = v.y;
            As[f * 4 + 2][row] = v.z;
            As[f * 4 + 3][row] = v.w;
        }
        // load W tile (128 rows of W = output cols), transpose-store, N-bounded
#pragma unroll
        for (int l = 0; l < 2; l++) {
            int id = tid + l * 256;
            int row = id >> 2;
            int f   = id & 3;
            int nn  = n0 + row;
            float4 v = make_float4(0.f, 0.f, 0.f, 0.f);
            if (nn < N) v = *(const float4*)&W[(size_t)nn * K + k0 + f * 4];
            Bs[f * 4 + 0][row] = v.x;
            Bs[f * 4 + 1][row] = v.y;
            Bs[f * 4 + 2][row] = v.z;
            Bs[f * 4 + 3][row] = v.w;
        }
        __syncthreads();
#pragma unroll
        for (int k = 0; k < 16; k++) {
            float4 a0 = *(const float4*)&As[k][tr];
            float4 a1 = *(const float4*)&As[k][tr + 4];
            float4 c0 = *(const float4*)&Bs[k][tc];
            float4 c1 = *(const float4*)&Bs[k][tc + 4];
            float ar[8] = {a0.x, a0.y, a0.z, a0.w, a1.x, a1.y, a1.z, a1.w};
            float br[8] = {c0.x, c0.y, c0.z, c0.w, c1.x, c1.y, c1.z, c1.w};
#pragma unroll
            for (int i = 0; i < 8; i++)
#pragma unroll
                for (int j = 0; j < 8; j++) acc[i][j] = fmaf(ar[i], br[j], acc[i][j]);
        }
        __syncthreads();
    }

#pragma unroll
    for (int i = 0; i < 8; i++) {
        const size_t rowb = (size_t)(m0 + tr + i) * N;
#pragma unroll
        for (int j = 0; j < 8; j++) {
            int col = n0 + tc + j;
            if (col < N) {
                float v = acc[i][j] + b1[col];
                if (b2) v += b2[col];
                if (act) v = tanhf(v);
                C[rowb + col] = v;
            }
        }
    }
}

// ----------------------------------------------------------------------------
// Fused LSTM step:
//   gates = Xg[t] + (h_prev * (1-done)) @ Whh^T ; cell update; residual write.
// Grid: (16 l-chunks, 8 row-chunks of 32). Block computes 32 rows x 128 gate
// cols where col j -> global gate col (j/32)*512 + lbase + (j%32), i.e. block
// owns i,f,g,o for its 32x32 (b,l) cells.
// ----------------------------------------------------------------------------
__global__ __launch_bounds__(256)
void lstm_step_kernel(const float* __restrict__ Whh,
                      const float* __restrict__ xg_t,   // (B,2048) at step t
                      const int*   __restrict__ done_t, // (B,) at step t
                      const float* __restrict__ h_in,
                      float* __restrict__ h_out,
                      float* __restrict__ c_buf,
                      const float* __restrict__ h2_t,   // residual (B,512) at t
                      float* __restrict__ nh_t)         // output (B,512) at t
{
    __shared__ float Hs[16][36];
    __shared__ float Ws[16][132];
    __shared__ float gsm[32][132];
    __shared__ float msk[32];

    const int tid = threadIdx.x;
    const int lbase = blockIdx.x * 32;
    const int r0 = blockIdx.y * 32;

    if (tid < 32) msk[tid] = 1.0f - (float)done_t[r0 + tid];
    __syncthreads();

    const int tr = (tid / 32) * 4;
    const int tc = (tid % 32) * 4;
    float acc[4][4];
#pragma unroll
    for (int i = 0; i < 4; i++)
#pragma unroll
        for (int j = 0; j < 4; j++) acc[i][j] = 0.0f;

    for (int kt = 0; kt < 32; kt++) {
        const int k0 = kt * 16;
        // Hs: 32 rows x 16 k = 128 float4
        if (tid < 128) {
            int row = tid >> 2;
            int f = tid & 3;
            float4 v = *(const float4*)&h_in[(size_t)(r0 + row) * LH + k0 + f * 4];
            float m = msk[row];
            Hs[f * 4 + 0][row] = v.x * m;
            Hs[f * 4 + 1][row] = v.y * m;
            Hs[f * 4 + 2][row] = v.z * m;
            Hs[f * 4 + 3][row] = v.w * m;
        }
        // Ws: 128 gate-cols x 16 k = 512 float4
#pragma unroll
        for (int l = 0; l < 2; l++) {
            int id = tid + l * 256;
            int row = id >> 2;   // 0..127 -> block-local gate col
            int f = id & 3;
            int ng = (row >> 5) * 512 + lbase + (row & 31);
            float4 v = *(const float4*)&Whh[(size_t)ng * LH + k0 + f * 4];
            Ws[f * 4 + 0][row] = v.x;
            Ws[f * 4 + 1][row] = v.y;
            Ws[f * 4 + 2][row] = v.z;
            Ws[f * 4 + 3][row] = v.w;
        }
        __syncthreads();
#pragma unroll
        for (int k = 0; k < 16; k++) {
            float4 a4 = *(const float4*)&Hs[k][tr];
            float4 b4 = *(const float4*)&Ws[k][tc];
            float ar[4] = {a4.x, a4.y, a4.z, a4.w};
            float br[4] = {b4.x, b4.y, b4.z, b4.w};
#pragma unroll
            for (int i = 0; i < 4; i++)
#pragma unroll
                for (int j = 0; j < 4; j++) acc[i][j] = fmaf(ar[i], br[j], acc[i][j]);
        }
        __syncthreads();
    }

    // add precomputed x-gates, stage to SMEM
#pragma unroll
    for (int i = 0; i < 4; i++) {
#pragma unroll
        for (int j = 0; j < 4; j++) {
            int jj = tc + j;
            int ng = (jj >> 5) * 512 + lbase + (jj & 31);
            gsm[tr + i][jj] = acc[i][j] + xg_t[(size_t)(r0 + tr + i) * (4 * LH) + ng];
        }
    }
    __syncthreads();

    // cell update: 32x32 cells, 4 per thread
#pragma unroll
    for (int q = 0; q < 4; q++) {
        int cell = tid + q * 256;
        int r = cell >> 5;
        int li = cell & 31;
        float iv = gsm[r][li];
        float fv = gsm[r][32 + li];
        float gv = gsm[r][64 + li];
        float ov = gsm[r][96 + li];
        size_t gi = (size_t)(r0 + r) * LH + lbase + li;
        float cp = c_buf[gi] * msk[r];
        float cn = sigm(fv) * cp + sigm(iv) * tanhf(gv);
        float hn = sigm(ov) * tanhf(cn);
        c_buf[gi] = cn;
        h_out[gi] = hn;
        nh_t[gi] = hn + h2_t[gi];
    }
}

// ----------------------------------------------------------------------------
// init h/c from h0/c0
// ----------------------------------------------------------------------------
__global__ void init_state_kernel(const float* __restrict__ h0,
                                  const float* __restrict__ c0,
                                  float* __restrict__ h, float* __restrict__ c)
{
    int idx = blockIdx.x * blockDim.x + threadIdx.x;
    if (idx < BB * LH) { h[idx] = h0[idx]; c[idx] = c0[idx]; }
}

// ----------------------------------------------------------------------------
// log-softmax head: lp + entropy. One block per row (1000 logits).
// ----------------------------------------------------------------------------
__global__ __launch_bounds__(256)
void softmax_kernel(const float* __restrict__ logits,
                    const int* __restrict__ action,
                    float* __restrict__ out, int TBn)
{
    __shared__ float red[256];
    __shared__ float red2[256];
    const int row = blockIdx.x;
    const int tid = threadIdx.x;
    const float* lr = logits + (size_t)row * NA;

    float m = -3.402823e38f;
    for (int j = tid; j < NA; j += 256) m = fmaxf(m, lr[j]);
    red[tid] = m;
    __syncthreads();
    for (int s = 128; s > 0; s >>= 1) {
        if (tid < s) red[tid] = fmaxf(red[tid], red[tid + s]);
        __syncthreads();
    }
    m = red[0];
    __syncthreads();

    float s = 0.f, t = 0.f;
    for (int j = tid; j < NA; j += 256) {
        float l = lr[j];
        float e = expf(l - m);
        s += e;
        t += e * l;
    }
    red[tid] = s;
    red2[tid] = t;
    __syncthreads();
    for (int st = 128; st > 0; st >>= 1) {
        if (tid < st) { red[tid] += red[tid + st]; red2[tid] += red2[tid + st]; }
        __syncthreads();
    }
    if (tid == 0) {
        float ssum = red[0], tsum = red2[0];
        float lse = m + logf(ssum);
        float la = lr[action[row]];
        out[row] = la - lse;                 // log-prob
        out[TBn + row] = lse - tsum / ssum;  // entropy
    }
}

// ----------------------------------------------------------------------------
// critic final: v = ch . Wc2 + bc2.  One warp per row.
// ----------------------------------------------------------------------------
__global__ __launch_bounds__(256)
void critic_kernel(const float* __restrict__ ch, const float* __restrict__ Wc2,
                   const float* __restrict__ bc2, float* __restrict__ vout)
{
    __shared__ float w[LH];
    const int tid = threadIdx.x;
    for (int j = tid; j < LH; j += 256) w[j] = Wc2[j];
    __syncthreads();
    const int warp = tid >> 5, lane = tid & 31;
    const int row = blockIdx.x * 8 + warp;
    const float* r = ch + (size_t)row * LH;
    float s = 0.f;
    for (int k = lane; k < LH; k += 32) s += r[k] * w[k];
#pragma unroll
    for (int off = 16; off > 0; off >>= 1) s += __shfl_down_sync(0xFFFFFFFFu, s, off);
    if (lane == 0) vout[row] = s + bc2[0];
}

// ----------------------------------------------------------------------------
// host launcher
// ----------------------------------------------------------------------------
extern "C" void kernel_launch(void* const* d_in, const int* in_sizes, int n_in,
                              void* d_out, int out_size)
{
    const float* x    = (const float*)d_in[0];
    const int*   done = (const int*)d_in[1];
    const int*   act  = (const int*)d_in[2];
    // d_in[3] = B (constant 256)
    const float* W_t1 = (const float*)d_in[4];
    const float* b_t1 = (const float*)d_in[5];
    const float* W_t2 = (const float*)d_in[6];
    const float* b_t2 = (const float*)d_in[7];
    const float* Wih  = (const float*)d_in[8];
    const float* Whh  = (const float*)d_in[9];
    const float* bih  = (const float*)d_in[10];
    const float* bhh  = (const float*)d_in[11];
    const float* Wa1  = (const float*)d_in[12];
    const float* ba1  = (const float*)d_in[13];
    const float* Wa2  = (const float*)d_in[14];
    const float* ba2  = (const float*)d_in[15];
    const float* Wc1  = (const float*)d_in[16];
    const float* bc1  = (const float*)d_in[17];
    const float* Wc2  = (const float*)d_in[18];
    const float* bc2  = (const float*)d_in[19];
    const float* h0   = (const float*)d_in[20];
    const float* c0   = (const float*)d_in[21];

    const int TBn = in_sizes[0] / DI;   // 65536
    const int T = TBn / BB;             // 256
    float* out = (float*)d_out;

    float *buf1, *h2, *xg, *nh, *logits, *hbuf, *cbuf;
    cudaGetSymbolAddress((void**)&buf1,   g_buf1);
    cudaGetSymbolAddress((void**)&h2,     g_h2);
    cudaGetSymbolAddress((void**)&xg,     g_xg);
    cudaGetSymbolAddress((void**)&nh,     g_nh);
    cudaGetSymbolAddress((void**)&logits, g_logits);
    cudaGetSymbolAddress((void**)&hbuf,   g_hbuf);
    cudaGetSymbolAddress((void**)&cbuf,   g_cbuf);

    const dim3 blk(256);

    // trunk
    gemm_kernel<<<dim3(LH / 128, TBn / 128), blk>>>(x,    W_t1, b_t1, nullptr, buf1, TBn, LH, DI, 1);
    gemm_kernel<<<dim3(LH / 128, TBn / 128), blk>>>(buf1, W_t2, b_t2, nullptr, h2,   TBn, LH, LH, 1);
    // batched x-gates: Xg = H2 @ Wih^T + bih + bhh
    gemm_kernel<<<dim3(4 * LH / 128, TBn / 128), blk>>>(h2, Wih, bih, bhh, xg, TBn, 4 * LH, LH, 0);

    // lstm scan
    init_state_kernel<<<(BB * LH + 255) / 256, blk>>>(h0, c0, hbuf, cbuf);
    for (int t = 0; t < T; t++) {
        lstm_step_kernel<<<dim3(16, 8), blk>>>(
            Whh,
            xg + (size_t)t * BB * 4 * LH,
            done + (size_t)t * BB,
            hbuf + (size_t)(t & 1) * BB * LH,
            hbuf + (size_t)((t + 1) & 1) * BB * LH,
            cbuf,
            h2 + (size_t)t * BB * LH,
            nh + (size_t)t * BB * LH);
    }

    // actor head
    gemm_kernel<<<dim3(LH / 128, TBn / 128), blk>>>(nh,   Wa1, ba1, nullptr, buf1,   TBn, LH, LH, 1);
    gemm_kernel<<<dim3((NA + 127) / 128, TBn / 128), blk>>>(buf1, Wa2, ba2, nullptr, logits, TBn, NA, LH, 0);
    softmax_kernel<<<TBn, blk>>>(logits, act, out, TBn);

    // critic head
    gemm_kernel<<<dim3(LH / 128, TBn / 128), blk>>>(nh, Wc1, bc1, nullptr, buf1, TBn, LH, LH, 1);
    critic_kernel<<<TBn / 8, blk>>>(buf1, Wc2, bc2, out + (size_t)2 * TBn);
}

// round 4
// speedup vs baseline: 1.4003x; 1.4003x over previous
#include <cuda_runtime.h>
#include <cuda_fp16.h>
#include <math.h>
#include <stdint.h>

// ----------------------------------------------------------------------------
// Problem constants
// ----------------------------------------------------------------------------
#define LH 512      // hidden size
#define DI 512      // input size
#define NA 1000     // num actions
#define NAP 1024    // padded num actions
#define BB 256      // batch
#define TBMAX 65536 // T*B

// ----------------------------------------------------------------------------
// PTX helpers (base-target-safe: mma.sync / ldmatrix / cp.async only)
// ----------------------------------------------------------------------------
__device__ __forceinline__ uint32_t smem_u32(const void* p) {
    uint32_t a;
    asm("{ .reg .u64 t; cvta.to.shared.u64 t, %1; cvt.u32.u64 %0, t; }" : "=r"(a) : "l"(p));
    return a;
}

__device__ __forceinline__ void ldsm_x4(uint32_t (&r)[4], uint32_t addr) {
    asm volatile("ldmatrix.sync.aligned.m8n8.x4.shared.b16 {%0,%1,%2,%3}, [%4];"
                 : "=r"(r[0]), "=r"(r[1]), "=r"(r[2]), "=r"(r[3]) : "r"(addr));
}
__device__ __forceinline__ void mma16816(float (&d)[4], const uint32_t (&a)[4],
                                         uint32_t b0, uint32_t b1) {
    asm volatile(
        "mma.sync.aligned.m16n8k16.row.col.f32.f16.f16.f32 "
        "{%0,%1,%2,%3},{%4,%5,%6,%7},{%8,%9},{%0,%1,%2,%3};"
        : "+f"(d[0]), "+f"(d[1]), "+f"(d[2]), "+f"(d[3])
        : "r"(a[0]), "r"(a[1]), "r"(a[2]), "r"(a[3]), "r"(b0), "r"(b1));
}
__device__ __forceinline__ void cp16(uint32_t dst, const void* src) {
    asm volatile("cp.async.cg.shared.global [%0], [%1], 16;" :: "r"(dst), "l"(src) : "memory");
}
#define CP_COMMIT() asm volatile("cp.async.commit_group;" ::: "memory")
#define CP_WAIT1()  asm volatile("cp.async.wait_group 1;" ::: "memory")
#define CP_WAIT0()  asm volatile("cp.async.wait_group 0;" ::: "memory")

// ----------------------------------------------------------------------------
// Scratch (static device allocations)
// ----------------------------------------------------------------------------
__device__ float g_buf1[(size_t)TBMAX * LH];
__device__ float g_h2  [(size_t)TBMAX * LH];
__device__ float g_xg  [(size_t)TBMAX * 4 * LH];
__device__ float g_nh  [(size_t)TBMAX * LH];
__device__ float g_logits[(size_t)TBMAX * NA];
__device__ float g_hbuf[2 * BB * LH];
__device__ float g_cbuf[BB * LH];

// fp16 hi/lo operand arrays (16B-aligned for cp.async)
__device__ __align__(16) __half g_x_hi [(size_t)TBMAX * DI], g_x_lo [(size_t)TBMAX * DI];
__device__ __align__(16) __half g_b1_hi[(size_t)TBMAX * LH], g_b1_lo[(size_t)TBMAX * LH];
__device__ __align__(16) __half g_h2_hi[(size_t)TBMAX * LH], g_h2_lo[(size_t)TBMAX * LH];
__device__ __align__(16) __half g_nh_hi[(size_t)TBMAX * LH], g_nh_lo[(size_t)TBMAX * LH];
__device__ __align__(16) __half g_wt1_hi[LH * DI], g_wt1_lo[LH * DI];
__device__ __align__(16) __half g_wt2_hi[LH * LH], g_wt2_lo[LH * LH];
__device__ __align__(16) __half g_wih_hi[4 * LH * LH], g_wih_lo[4 * LH * LH];
__device__ __align__(16) __half g_wa1_hi[LH * LH], g_wa1_lo[LH * LH];
__device__ __align__(16) __half g_wa2_hi[NAP * LH], g_wa2_lo[NAP * LH];
__device__ __align__(16) __half g_wc1_hi[LH * LH], g_wc1_lo[LH * LH];

__device__ __forceinline__ float sigm(float x) { return 1.0f / (1.0f + expf(-x)); }

// ----------------------------------------------------------------------------
// split: fp32 -> (hi fp16, lo fp16) so hi+lo ~= fp32
// ----------------------------------------------------------------------------
__global__ __launch_bounds__(256)
void split_kernel(const float* __restrict__ X, __half* __restrict__ H,
                  __half* __restrict__ L, int n4)
{
    int i = blockIdx.x * 256 + threadIdx.x;
    if (i < n4) {
        float4 v = ((const float4*)X)[i];
        __half2 a = __floats2half2_rn(v.x, v.y);
        __half2 b = __floats2half2_rn(v.z, v.w);
        float2 af = __half22float2(a), bf = __half22float2(b);
        __half2 al = __floats2half2_rn(v.x - af.x, v.y - af.y);
        __half2 bl = __floats2half2_rn(v.z - bf.x, v.w - bf.y);
        ((__half2*)H)[2 * i] = a;  ((__half2*)H)[2 * i + 1] = b;
        ((__half2*)L)[2 * i] = al; ((__half2*)L)[2 * i + 1] = bl;
    }
}

// zero-fill padded weight rows so they can't contain NaN garbage
__global__ void zero_half_kernel(__half* __restrict__ p, int n)
{
    int i = blockIdx.x * 256 + threadIdx.x;
    if (i < n) p[i] = __float2half(0.0f);
}

// ----------------------------------------------------------------------------
// HMMA fp32-via-fp16-split GEMM:
//   C[M,N] = (Ahi+Alo)[M,K] @ (Bhi+Blo)[N,K]^T + b1 (+b2), optional tanh.
// Tile 128x128, BK=32, cp.async double-buffered, ldmatrix + mma.sync m16n8k16.
// A and B tiles are both K-major in SMEM -> NON-trans ldmatrix for both.
// ----------------------------------------------------------------------------
#define ARR_BYTES 10240u   // 128 * 40 * 2
#define BUF_BYTES 40960u   // 4 arrays
#define G_SMEM 81920       // double buffer

__global__ __launch_bounds__(256, 2)
void gemm16_kernel(const __half* __restrict__ Ahi, const __half* __restrict__ Alo,
                   const __half* __restrict__ Bhi, const __half* __restrict__ Blo,
                   const float* __restrict__ b1, const float* __restrict__ b2,
                   float* __restrict__ C, __half* __restrict__ Chi, __half* __restrict__ Clo,
                   int M, int N, int K, int act)
{
    extern __shared__ __align__(16) char smem[];
    const uint32_t sb = smem_u32(smem);
    const int tid = threadIdx.x;
    const int lane = tid & 31, wid = tid >> 5;
    const int m0 = blockIdx.y * 128, n0 = blockIdx.x * 128;
    const int wm = (wid >> 2) * 64, wn = (wid & 3) * 32;

    float acc[4][4][4];
#pragma unroll
    for (int a = 0; a < 4; a++)
#pragma unroll
        for (int b = 0; b < 4; b++)
#pragma unroll
            for (int c = 0; c < 4; c++) acc[a][b][c] = 0.0f;

    const int NCH = K >> 5;

    // chunk loader: 2048 16B pieces; arr = piece>>9 (Ahi,Alo,Bhi,Blo)
    auto issue_chunk = [&](int c) {
        const uint32_t bufb = (uint32_t)(c & 1) * BUF_BYTES;
        const int k0 = c * 32;
#pragma unroll
        for (int i = 0; i < 8; i++) {
            int p = tid + i * 256;
            int arr = p >> 9;
            int q = p & 511;
            int r = q >> 2;
            int ch = (q & 3) * 8;   // half offset within row
            int grow = (arr < 2 ? m0 : n0) + r;
            const __half* src =
                (arr == 0 ? Ahi : arr == 1 ? Alo : arr == 2 ? Bhi : Blo)
                + (size_t)grow * K + k0 + ch;
            uint32_t dst = sb + bufb + (uint32_t)arr * ARR_BYTES
                         + (uint32_t)r * 80u + (uint32_t)ch * 2u;
            cp16(dst, src);
        }
        CP_COMMIT();
    };

    issue_chunk(0);

    for (int c = 0; c < NCH; c++) {
        if (c + 1 < NCH) { issue_chunk(c + 1); CP_WAIT1(); }
        else             { CP_WAIT0(); }
        __syncthreads();

        const uint32_t abase = sb + (uint32_t)(c & 1) * BUF_BYTES;
#pragma unroll
        for (int ks = 0; ks < 2; ks++) {
            const int kb = ks * 16;  // half offset
            const uint32_t kcol = (uint32_t)(kb + (lane >> 4) * 8) * 2u;

            // B fragments: K-major tile -> non-trans ldmatrix.
            // matrices: 0 = rows n..n+7 @ k-lo, 1 = rows n+8..n+15 @ k-lo,
            //           2 = rows n..n+7 @ k-hi, 3 = rows n+8..n+15 @ k-hi
            uint32_t bh[4][2], bl[4][2];
#pragma unroll
            for (int ng = 0; ng < 2; ng++) {
                uint32_t row = (uint32_t)(wn + ng * 16 + ((lane >> 3) & 1) * 8 + (lane & 7));
                uint32_t addr = abase + 2u * ARR_BYTES + row * 80u + kcol;
                uint32_t r4[4];
                ldsm_x4(r4, addr);
                bh[ng * 2 + 0][0] = r4[0]; bh[ng * 2 + 0][1] = r4[2];
                bh[ng * 2 + 1][0] = r4[1]; bh[ng * 2 + 1][1] = r4[3];
                ldsm_x4(r4, addr + ARR_BYTES);
                bl[ng * 2 + 0][0] = r4[0]; bl[ng * 2 + 0][1] = r4[2];
                bl[ng * 2 + 1][0] = r4[1]; bl[ng * 2 + 1][1] = r4[3];
            }
#pragma unroll
            for (int mi = 0; mi < 4; mi++) {
                uint32_t arow = (uint32_t)(wm + mi * 16 + (lane & 15));
                uint32_t aaddr = abase + arow * 80u + kcol;
                uint32_t ah[4], al[4];
                ldsm_x4(ah, aaddr);
                ldsm_x4(al, aaddr + ARR_BYTES);
#pragma unroll
                for (int ni = 0; ni < 4; ni++) {
                    mma16816(acc[mi][ni], ah, bh[ni][0], bh[ni][1]);
                    mma16816(acc[mi][ni], ah, bl[ni][0], bl[ni][1]);
                    mma16816(acc[mi][ni], al, bh[ni][0], bh[ni][1]);
                }
            }
        }
        __syncthreads();
    }

    // epilogue: bias (+b2), optional tanh, fp32 store + optional fp16 hi/lo
#pragma unroll
    for (int ni = 0; ni < 4; ni++) {
        int col = n0 + wn + ni * 8 + (lane & 3) * 2;
        if (col >= N) continue;   // N is even; col, col+1 both in-range
        float bb0 = b1[col], bb1 = b1[col + 1];
        if (b2) { bb0 += b2[col]; bb1 += b2[col + 1]; }
#pragma unroll
        for (int mi = 0; mi < 4; mi++) {
            int r0 = m0 + wm + mi * 16 + (lane >> 2);
#pragma unroll
            for (int h = 0; h < 2; h++) {
                int rr = r0 + h * 8;
                float v0 = acc[mi][ni][h * 2 + 0] + bb0;
                float v1 = acc[mi][ni][h * 2 + 1] + bb1;
                if (act) { v0 = tanhf(v0); v1 = tanhf(v1); }
                size_t base = (size_t)rr * N + col;
                *(float2*)&C[base] = make_float2(v0, v1);
                if (Chi) {
                    __half2 hh = __floats2half2_rn(v0, v1);
                    float2 hf = __half22float2(hh);
                    __half2 ll = __floats2half2_rn(v0 - hf.x, v1 - hf.y);
                    *(__half2*)&Chi[base] = hh;
                    *(__half2*)&Clo[base] = ll;
                }
            }
        }
    }
}

// ----------------------------------------------------------------------------
// Fused LSTM step (SIMT fp32) + fp16 hi/lo output of nh.
// ----------------------------------------------------------------------------
__global__ __launch_bounds__(256)
void lstm_step_kernel(const float* __restrict__ Whh,
                      const float* __restrict__ xg_t,
                      const int*   __restrict__ done_t,
                      const float* __restrict__ h_in,
                      float* __restrict__ h_out,
                      float* __restrict__ c_buf,
                      const float* __restrict__ h2_t,
                      float* __restrict__ nh_t,
                      __half* __restrict__ nhhi_t,
                      __half* __restrict__ nhlo_t)
{
    __shared__ float Hs[16][36];
    __shared__ float Ws[16][132];
    __shared__ float gsm[32][132];
    __shared__ float msk[32];

    const int tid = threadIdx.x;
    const int lbase = blockIdx.x * 32;
    const int r0 = blockIdx.y * 32;

    if (tid < 32) msk[tid] = 1.0f - (float)done_t[r0 + tid];
    __syncthreads();

    const int tr = (tid / 32) * 4;
    const int tc = (tid % 32) * 4;
    float acc[4][4];
#pragma unroll
    for (int i = 0; i < 4; i++)
#pragma unroll
        for (int j = 0; j < 4; j++) acc[i][j] = 0.0f;

    for (int kt = 0; kt < 32; kt++) {
        const int k0 = kt * 16;
        if (tid < 128) {
            int row = tid >> 2;
            int f = tid & 3;
            float4 v = *(const float4*)&h_in[(size_t)(r0 + row) * LH + k0 + f * 4];
            float m = msk[row];
            Hs[f * 4 + 0][row] = v.x * m;
            Hs[f * 4 + 1][row] = v.y * m;
            Hs[f * 4 + 2][row] = v.z * m;
            Hs[f * 4 + 3][row] = v.w * m;
        }
#pragma unroll
        for (int l = 0; l < 2; l++) {
            int id = tid + l * 256;
            int row = id >> 2;
            int f = id & 3;
            int ng = (row >> 5) * 512 + lbase + (row & 31);
            float4 v = *(const float4*)&Whh[(size_t)ng * LH + k0 + f * 4];
            Ws[f * 4 + 0][row] = v.x;
            Ws[f * 4 + 1][row] = v.y;
            Ws[f * 4 + 2][row] = v.z;
            Ws[f * 4 + 3][row] = v.w;
        }
        __syncthreads();
#pragma unroll
        for (int k = 0; k < 16; k++) {
            float4 a4 = *(const float4*)&Hs[k][tr];
            float4 b4 = *(const float4*)&Ws[k][tc];
            float ar[4] = {a4.x, a4.y, a4.z, a4.w};
            float br[4] = {b4.x, b4.y, b4.z, b4.w};
#pragma unroll
            for (int i = 0; i < 4; i++)
#pragma unroll
                for (int j = 0; j < 4; j++) acc[i][j] = fmaf(ar[i], br[j], acc[i][j]);
        }
        __syncthreads();
    }

#pragma unroll
    for (int i = 0; i < 4; i++) {
#pragma unroll
        for (int j = 0; j < 4; j++) {
            int jj = tc + j;
            int ng = (jj >> 5) * 512 + lbase + (jj & 31);
            gsm[tr + i][jj] = acc[i][j] + xg_t[(size_t)(r0 + tr + i) * (4 * LH) + ng];
        }
    }
    __syncthreads();

#pragma unroll
    for (int q = 0; q < 4; q++) {
        int cell = tid + q * 256;
        int r = cell >> 5;
        int li = cell & 31;
        float iv = gsm[r][li];
        float fv = gsm[r][32 + li];
        float gv = gsm[r][64 + li];
        float ov = gsm[r][96 + li];
        size_t gi = (size_t)(r0 + r) * LH + lbase + li;
        float cp = c_buf[gi] * msk[r];
        float cn = sigm(fv) * cp + sigm(iv) * tanhf(gv);
        float hn = sigm(ov) * tanhf(cn);
        c_buf[gi] = cn;
        h_out[gi] = hn;
        float nhv = hn + h2_t[gi];
        nh_t[gi] = nhv;
        __half hh = __float2half_rn(nhv);
        nhhi_t[gi] = hh;
        nhlo_t[gi] = __float2half_rn(nhv - __half2float(hh));
    }
}

// ----------------------------------------------------------------------------
__global__ void init_state_kernel(const float* __restrict__ h0,
                                  const float* __restrict__ c0,
                                  float* __restrict__ h, float* __restrict__ c)
{
    int idx = blockIdx.x * blockDim.x + threadIdx.x;
    if (idx < BB * LH) { h[idx] = h0[idx]; c[idx] = c0[idx]; }
}

// ----------------------------------------------------------------------------
__global__ __launch_bounds__(256)
void softmax_kernel(const float* __restrict__ logits,
                    const int* __restrict__ action,
                    float* __restrict__ out, int TBn)
{
    __shared__ float red[256];
    __shared__ float red2[256];
    const int row = blockIdx.x;
    const int tid = threadIdx.x;
    const float* lr = logits + (size_t)row * NA;

    float m = -3.402823e38f;
    for (int j = tid; j < NA; j += 256) m = fmaxf(m, lr[j]);
    red[tid] = m;
    __syncthreads();
    for (int s = 128; s > 0; s >>= 1) {
        if (tid < s) red[tid] = fmaxf(red[tid], red[tid + s]);
        __syncthreads();
    }
    m = red[0];
    __syncthreads();

    float s = 0.f, t = 0.f;
    for (int j = tid; j < NA; j += 256) {
        float l = lr[j];
        float e = expf(l - m);
        s += e;
        t += e * l;
    }
    red[tid] = s;
    red2[tid] = t;
    __syncthreads();
    for (int st = 128; st > 0; st >>= 1) {
        if (tid < st) { red[tid] += red[tid + st]; red2[tid] += red2[tid + st]; }
        __syncthreads();
    }
    if (tid == 0) {
        float ssum = red[0], tsum = red2[0];
        float lse = m + logf(ssum);
        float la = lr[action[row]];
        out[row] = la - lse;
        out[TBn + row] = lse - tsum / ssum;
    }
}

// ----------------------------------------------------------------------------
__global__ __launch_bounds__(256)
void critic_kernel(const float* __restrict__ ch, const float* __restrict__ Wc2,
                   const float* __restrict__ bc2, float* __restrict__ vout)
{
    __shared__ float wsh[LH];
    const int tid = threadIdx.x;
    for (int j = tid; j < LH; j += 256) wsh[j] = Wc2[j];
    __syncthreads();
    const int warp = tid >> 5, lane = tid & 31;
    const int row = blockIdx.x * 8 + warp;
    const float* r = ch + (size_t)row * LH;
    float s = 0.f;
    for (int k = lane; k < LH; k += 32) s += r[k] * wsh[k];
#pragma unroll
    for (int off = 16; off > 0; off >>= 1) s += __shfl_down_sync(0xFFFFFFFFu, s, off);
    if (lane == 0) vout[row] = s + bc2[0];
}

// ----------------------------------------------------------------------------
// host launcher
// ----------------------------------------------------------------------------
extern "C" void kernel_launch(void* const* d_in, const int* in_sizes, int n_in,
                              void* d_out, int out_size)
{
    const float* x    = (const float*)d_in[0];
    const int*   done = (const int*)d_in[1];
    const int*   act  = (const int*)d_in[2];
    const float* W_t1 = (const float*)d_in[4];
    const float* b_t1 = (const float*)d_in[5];
    const float* W_t2 = (const float*)d_in[6];
    const float* b_t2 = (const float*)d_in[7];
    const float* Wih  = (const float*)d_in[8];
    const float* Whh  = (const float*)d_in[9];
    const float* bih  = (const float*)d_in[10];
    const float* bhh  = (const float*)d_in[11];
    const float* Wa1  = (const float*)d_in[12];
    const float* ba1  = (const float*)d_in[13];
    const float* Wa2  = (const float*)d_in[14];
    const float* ba2  = (const float*)d_in[15];
    const float* Wc1  = (const float*)d_in[16];
    const float* bc1  = (const float*)d_in[17];
    const float* Wc2  = (const float*)d_in[18];
    const float* bc2  = (const float*)d_in[19];
    const float* h0   = (const float*)d_in[20];
    const float* c0   = (const float*)d_in[21];

    const int TBn = in_sizes[0] / DI;   // 65536
    const int T = TBn / BB;             // 256
    float* out = (float*)d_out;

    float *buf1, *h2, *xg, *nh, *logits, *hbuf, *cbuf;
    cudaGetSymbolAddress((void**)&buf1,   g_buf1);
    cudaGetSymbolAddress((void**)&h2,     g_h2);
    cudaGetSymbolAddress((void**)&xg,     g_xg);
    cudaGetSymbolAddress((void**)&nh,     g_nh);
    cudaGetSymbolAddress((void**)&logits, g_logits);
    cudaGetSymbolAddress((void**)&hbuf,   g_hbuf);
    cudaGetSymbolAddress((void**)&cbuf,   g_cbuf);

    __half *xhi, *xlo, *b1hi, *b1lo, *h2hi, *h2lo, *nhhi, *nhlo;
    __half *wt1h, *wt1l, *wt2h, *wt2l, *wihh, *wihl, *wa1h, *wa1l, *wa2h, *wa2l, *wc1h, *wc1l;
    cudaGetSymbolAddress((void**)&xhi,  g_x_hi);  cudaGetSymbolAddress((void**)&xlo,  g_x_lo);
    cudaGetSymbolAddress((void**)&b1hi, g_b1_hi); cudaGetSymbolAddress((void**)&b1lo, g_b1_lo);
    cudaGetSymbolAddress((void**)&h2hi, g_h2_hi); cudaGetSymbolAddress((void**)&h2lo, g_h2_lo);
    cudaGetSymbolAddress((void**)&nhhi, g_nh_hi); cudaGetSymbolAddress((void**)&nhlo, g_nh_lo);
    cudaGetSymbolAddress((void**)&wt1h, g_wt1_hi); cudaGetSymbolAddress((void**)&wt1l, g_wt1_lo);
    cudaGetSymbolAddress((void**)&wt2h, g_wt2_hi); cudaGetSymbolAddress((void**)&wt2l, g_wt2_lo);
    cudaGetSymbolAddress((void**)&wihh, g_wih_hi); cudaGetSymbolAddress((void**)&wihl, g_wih_lo);
    cudaGetSymbolAddress((void**)&wa1h, g_wa1_hi); cudaGetSymbolAddress((void**)&wa1l, g_wa1_lo);
    cudaGetSymbolAddress((void**)&wa2h, g_wa2_hi); cudaGetSymbolAddress((void**)&wa2l, g_wa2_lo);
    cudaGetSymbolAddress((void**)&wc1h, g_wc1_hi); cudaGetSymbolAddress((void**)&wc1l, g_wc1_lo);

    cudaFuncSetAttribute(gemm16_kernel, cudaFuncAttributeMaxDynamicSharedMemorySize, G_SMEM);

    const dim3 blk(256);
    auto SPLIT = [&](const float* src, __half* hi, __half* lo, int n) {
        int n4 = n / 4;
        split_kernel<<<(n4 + 255) / 256, blk>>>(src, hi, lo, n4);
    };

    // operand splits
    SPLIT(x,    xhi,  xlo,  TBn * DI);
    SPLIT(W_t1, wt1h, wt1l, LH * DI);
    SPLIT(W_t2, wt2h, wt2l, LH * LH);
    SPLIT(Wih,  wihh, wihl, 4 * LH * LH);
    SPLIT(Wa1,  wa1h, wa1l, LH * LH);
    SPLIT(Wa2,  wa2h, wa2l, NA * LH);
    SPLIT(Wc1,  wc1h, wc1l, LH * LH);
    // zero the padded Wa2 rows (1000..1023) so no NaN garbage enters mma
    zero_half_kernel<<<((NAP - NA) * LH + 255) / 256, blk>>>(wa2h + (size_t)NA * LH, (NAP - NA) * LH);
    zero_half_kernel<<<((NAP - NA) * LH + 255) / 256, blk>>>(wa2l + (size_t)NA * LH, (NAP - NA) * LH);

    const int MY = TBn / 128;

    // trunk
    gemm16_kernel<<<dim3(4, MY), blk, G_SMEM>>>(
        xhi, xlo, wt1h, wt1l, b_t1, nullptr, buf1, b1hi, b1lo, TBn, LH, DI, 1);
    gemm16_kernel<<<dim3(4, MY), blk, G_SMEM>>>(
        b1hi, b1lo, wt2h, wt2l, b_t2, nullptr, h2, h2hi, h2lo, TBn, LH, LH, 1);
    // batched x-gates
    gemm16_kernel<<<dim3(16, MY), blk, G_SMEM>>>(
        h2hi, h2lo, wihh, wihl, bih, bhh, xg, nullptr, nullptr, TBn, 4 * LH, LH, 0);

    // lstm scan
    init_state_kernel<<<(BB * LH + 255) / 256, blk>>>(h0, c0, hbuf, cbuf);
    for (int t = 0; t < T; t++) {
        lstm_step_kernel<<<dim3(16, 8), blk>>>(
            Whh,
            xg + (size_t)t * BB * 4 * LH,
            done + (size_t)t * BB,
            hbuf + (size_t)(t & 1) * BB * LH,
            hbuf + (size_t)((t + 1) & 1) * BB * LH,
            cbuf,
            h2 + (size_t)t * BB * LH,
            nh + (size_t)t * BB * LH,
            nhhi + (size_t)t * BB * LH,
            nhlo + (size_t)t * BB * LH);
    }

    // actor head
    gemm16_kernel<<<dim3(4, MY), blk, G_SMEM>>>(
        nhhi, nhlo, wa1h, wa1l, ba1, nullptr, buf1, b1hi, b1lo, TBn, LH, LH, 1);
    gemm16_kernel<<<dim3(8, MY), blk, G_SMEM>>>(
        b1hi, b1lo, wa2h, wa2l, ba2, nullptr, logits, nullptr, nullptr, TBn, NA, LH, 0);
    softmax_kernel<<<TBn, blk>>>(logits, act, out, TBn);

    // critic head
    gemm16_kernel<<<dim3(4, MY), blk, G_SMEM>>>(
        nhhi, nhlo, wc1h, wc1l, bc1, nullptr, buf1, nullptr, nullptr, TBn, LH, LH, 1);
    critic_kernel<<<TBn / 8, blk>>>(buf1, Wc2, bc2, out + (size_t)2 * TBn);
}

// round 5
// speedup vs baseline: 2.0861x; 1.4898x over previous
#include <cuda_runtime.h>
#include <cuda_fp16.h>
#include <math.h>
#include <stdint.h>

// ----------------------------------------------------------------------------
// Problem constants
// ----------------------------------------------------------------------------
#define LH 512      // hidden size
#define DI 512      // input size
#define NA 1000     // num actions
#define NAP 1024    // padded num actions
#define NG 2048     // 4*LH gate count
#define BB 256      // batch
#define TBMAX 65536 // T*B

// ----------------------------------------------------------------------------
// PTX helpers (base-target-safe: mma.sync / ldmatrix / cp.async only)
// ----------------------------------------------------------------------------
__device__ __forceinline__ uint32_t smem_u32(const void* p) {
    uint32_t a;
    asm("{ .reg .u64 t; cvta.to.shared.u64 t, %1; cvt.u32.u64 %0, t; }" : "=r"(a) : "l"(p));
    return a;
}
__device__ __forceinline__ void ldsm_x4(uint32_t (&r)[4], uint32_t addr) {
    asm volatile("ldmatrix.sync.aligned.m8n8.x4.shared.b16 {%0,%1,%2,%3}, [%4];"
                 : "=r"(r[0]), "=r"(r[1]), "=r"(r[2]), "=r"(r[3]) : "r"(addr));
}
__device__ __forceinline__ void mma16816(float (&d)[4], const uint32_t (&a)[4],
                                         uint32_t b0, uint32_t b1) {
    asm volatile(
        "mma.sync.aligned.m16n8k16.row.col.f32.f16.f16.f32 "
        "{%0,%1,%2,%3},{%4,%5,%6,%7},{%8,%9},{%0,%1,%2,%3};"
        : "+f"(d[0]), "+f"(d[1]), "+f"(d[2]), "+f"(d[3])
        : "r"(a[0]), "r"(a[1]), "r"(a[2]), "r"(a[3]), "r"(b0), "r"(b1));
}
__device__ __forceinline__ void cp16(uint32_t dst, const void* src) {
    asm volatile("cp.async.cg.shared.global [%0], [%1], 16;" :: "r"(dst), "l"(src) : "memory");
}
#define CP_COMMIT() asm volatile("cp.async.commit_group;" ::: "memory")
#define CP_WAIT1()  asm volatile("cp.async.wait_group 1;" ::: "memory")
#define CP_WAIT0()  asm volatile("cp.async.wait_group 0;" ::: "memory")

// gate permutation: pcol p -> original gate row. block=p>>7, gate=(p&127)>>5,
// l = (p>>7)*32 + (p&31); orig = gate*512 + l.
__host__ __device__ __forceinline__ int perm_orig(int p) {
    return (((p & 127) >> 5) << 9) + ((p >> 7) << 5) + (p & 31);
}

// ----------------------------------------------------------------------------
// Scratch (static device allocations)
// ----------------------------------------------------------------------------
__device__ float g_buf1[(size_t)TBMAX * LH];
__device__ float g_h2  [(size_t)TBMAX * LH];
__device__ float g_xg  [(size_t)TBMAX * NG];   // permuted gate order
__device__ float g_logits[(size_t)TBMAX * NA];
__device__ float g_cbuf[BB * LH];
__device__ float g_biasp[NG];                  // permuted bih+bhh

// fp16 hi/lo operand arrays (16B-aligned for cp.async)
__device__ __align__(16) __half g_x_hi [(size_t)TBMAX * DI], g_x_lo [(size_t)TBMAX * DI];
__device__ __align__(16) __half g_b1_hi[(size_t)TBMAX * LH], g_b1_lo[(size_t)TBMAX * LH];
__device__ __align__(16) __half g_h2_hi[(size_t)TBMAX * LH], g_h2_lo[(size_t)TBMAX * LH];
__device__ __align__(16) __half g_nh_hi[(size_t)TBMAX * LH], g_nh_lo[(size_t)TBMAX * LH];
__device__ __align__(16) __half g_hm_hi[2 * BB * LH], g_hm_lo[2 * BB * LH]; // masked h ping-pong
__device__ __align__(16) __half g_wt1_hi[LH * DI], g_wt1_lo[LH * DI];
__device__ __align__(16) __half g_wt2_hi[LH * LH], g_wt2_lo[LH * LH];
__device__ __align__(16) __half g_wihp_hi[NG * LH], g_wihp_lo[NG * LH];   // permuted
__device__ __align__(16) __half g_whhp_hi[NG * LH], g_whhp_lo[NG * LH];   // permuted
__device__ __align__(16) __half g_wa1_hi[LH * LH], g_wa1_lo[LH * LH];
__device__ __align__(16) __half g_wa2_hi[NAP * LH], g_wa2_lo[NAP * LH];
__device__ __align__(16) __half g_wc1_hi[LH * LH], g_wc1_lo[LH * LH];

__device__ __forceinline__ float sigm(float x) { return 1.0f / (1.0f + expf(-x)); }

__device__ __forceinline__ void split_store4(float4 v, __half* H, __half* L, size_t idx) {
    __half2 a = __floats2half2_rn(v.x, v.y);
    __half2 b = __floats2half2_rn(v.z, v.w);
    float2 af = __half22float2(a), bf = __half22float2(b);
    __half2 al = __floats2half2_rn(v.x - af.x, v.y - af.y);
    __half2 bl = __floats2half2_rn(v.z - bf.x, v.w - bf.y);
    *(__half2*)&H[idx] = a;  *(__half2*)&H[idx + 2] = b;
    *(__half2*)&L[idx] = al; *(__half2*)&L[idx + 2] = bl;
}

// ----------------------------------------------------------------------------
// x split (big, standalone)
// ----------------------------------------------------------------------------
__global__ __launch_bounds__(256)
void splitx_kernel(const float* __restrict__ X, __half* __restrict__ H,
                   __half* __restrict__ L, int n4)
{
    int i = blockIdx.x * 256 + threadIdx.x;
    if (i < n4) split_store4(((const float4*)X)[i], H, L, (size_t)i * 4);
}

// ----------------------------------------------------------------------------
// fused weight prep: splits + permutation + padding + bias perm.
// blockIdx.y selects section.
// ----------------------------------------------------------------------------
__global__ __launch_bounds__(256)
void prep_kernel(const float* __restrict__ W_t1, const float* __restrict__ W_t2,
                 const float* __restrict__ Wa1, const float* __restrict__ Wc1,
                 const float* __restrict__ Wa2,
                 const float* __restrict__ Wih, const float* __restrict__ Whh,
                 const float* __restrict__ bih, const float* __restrict__ bhh)
{
    const int i = blockIdx.x * 256 + threadIdx.x;
    const int sec = blockIdx.y;
    switch (sec) {
    case 0: if (i < LH * DI / 4) split_store4(((const float4*)W_t1)[i], g_wt1_hi, g_wt1_lo, (size_t)i * 4); break;
    case 1: if (i < LH * LH / 4) split_store4(((const float4*)W_t2)[i], g_wt2_hi, g_wt2_lo, (size_t)i * 4); break;
    case 2: if (i < LH * LH / 4) split_store4(((const float4*)Wa1)[i], g_wa1_hi, g_wa1_lo, (size_t)i * 4); break;
    case 3: if (i < LH * LH / 4) split_store4(((const float4*)Wc1)[i], g_wc1_hi, g_wc1_lo, (size_t)i * 4); break;
    case 4:
        if (i < NAP * LH / 4) {
            if (i < NA * LH / 4) split_store4(((const float4*)Wa2)[i], g_wa2_hi, g_wa2_lo, (size_t)i * 4);
            else {
                __half2 z = __floats2half2_rn(0.f, 0.f);
                *(__half2*)&g_wa2_hi[(size_t)i * 4] = z; *(__half2*)&g_wa2_hi[(size_t)i * 4 + 2] = z;
                *(__half2*)&g_wa2_lo[(size_t)i * 4] = z; *(__half2*)&g_wa2_lo[(size_t)i * 4 + 2] = z;
            }
        }
        break;
    case 5:
        if (i < NG * LH / 4) {
            int row = i >> 7;             // 512/4 = 128 float4 per row
            int c4 = i & 127;
            float4 v = ((const float4*)(Wih + (size_t)perm_orig(row) * LH))[c4];
            split_store4(v, g_wihp_hi, g_wihp_lo, (size_t)i * 4);
        }
        break;
    case 6:
        if (i < NG * LH / 4) {
            int row = i >> 7;
            int c4 = i & 127;
            float4 v = ((const float4*)(Whh + (size_t)perm_orig(row) * LH))[c4];
            split_store4(v, g_whhp_hi, g_whhp_lo, (size_t)i * 4);
        }
        break;
    case 7:
        if (i < NG) { int o = perm_orig(i); g_biasp[i] = bih[o] + bhh[o]; }
        break;
    }
}

// ----------------------------------------------------------------------------
// init: masked h0/c0; h0 split to fp16 hi/lo
// ----------------------------------------------------------------------------
__global__ __launch_bounds__(256)
void init_state_kernel(const float* __restrict__ h0, const float* __restrict__ c0,
                       const int* __restrict__ done0,
                       __half* __restrict__ hhi, __half* __restrict__ hlo,
                       float* __restrict__ c)
{
    int idx = blockIdx.x * 256 + threadIdx.x;
    if (idx < BB * LH) {
        float m = 1.0f - (float)done0[idx >> 9];
        float hv = h0[idx] * m;
        __half hh = __float2half_rn(hv);
        hhi[idx] = hh;
        hlo[idx] = __float2half_rn(hv - __half2float(hh));
        c[idx] = c0[idx] * m;
    }
}

// ----------------------------------------------------------------------------
// HMMA fp32-via-fp16-split GEMM (validated round 4):
//   C = (Ah+Al)@(Bh+Bl)^T + b1, optional tanh; optional fp16 hi/lo re-split.
// ----------------------------------------------------------------------------
#define ARR_BYTES 10240u
#define BUF_BYTES 40960u
#define G_SMEM 81920

__global__ __launch_bounds__(256, 2)
void gemm16_kernel(const __half* __restrict__ Ahi, const __half* __restrict__ Alo,
                   const __half* __restrict__ Bhi, const __half* __restrict__ Blo,
                   const float* __restrict__ b1,
                   float* __restrict__ C, __half* __restrict__ Chi, __half* __restrict__ Clo,
                   int M, int N, int K, int act)
{
    extern __shared__ __align__(16) char smem[];
    const uint32_t sb = smem_u32(smem);
    const int tid = threadIdx.x;
    const int lane = tid & 31, wid = tid >> 5;
    const int m0 = blockIdx.y * 128, n0 = blockIdx.x * 128;
    const int wm = (wid >> 2) * 64, wn = (wid & 3) * 32;

    float acc[4][4][4];
#pragma unroll
    for (int a = 0; a < 4; a++)
#pragma unroll
        for (int b = 0; b < 4; b++)
#pragma unroll
            for (int c = 0; c < 4; c++) acc[a][b][c] = 0.0f;

    const int NCH = K >> 5;

    auto issue_chunk = [&](int c) {
        const uint32_t bufb = (uint32_t)(c & 1) * BUF_BYTES;
        const int k0 = c * 32;
#pragma unroll
        for (int i = 0; i < 8; i++) {
            int p = tid + i * 256;
            int arr = p >> 9;
            int q = p & 511;
            int r = q >> 2;
            int ch = (q & 3) * 8;
            int grow = (arr < 2 ? m0 : n0) + r;
            const __half* src =
                (arr == 0 ? Ahi : arr == 1 ? Alo : arr == 2 ? Bhi : Blo)
                + (size_t)grow * K + k0 + ch;
            uint32_t dst = sb + bufb + (uint32_t)arr * ARR_BYTES
                         + (uint32_t)r * 80u + (uint32_t)ch * 2u;
            cp16(dst, src);
        }
        CP_COMMIT();
    };

    issue_chunk(0);

    for (int c = 0; c < NCH; c++) {
        if (c + 1 < NCH) { issue_chunk(c + 1); CP_WAIT1(); }
        else             { CP_WAIT0(); }
        __syncthreads();

        const uint32_t abase = sb + (uint32_t)(c & 1) * BUF_BYTES;
#pragma unroll
        for (int ks = 0; ks < 2; ks++) {
            const uint32_t kcol = (uint32_t)(ks * 16 + (lane >> 4) * 8) * 2u;
            uint32_t bh[4][2], bl[4][2];
#pragma unroll
            for (int ng = 0; ng < 2; ng++) {
                uint32_t row = (uint32_t)(wn + ng * 16 + ((lane >> 3) & 1) * 8 + (lane & 7));
                uint32_t addr = abase + 2u * ARR_BYTES + row * 80u + kcol;
                uint32_t r4[4];
                ldsm_x4(r4, addr);
                bh[ng * 2 + 0][0] = r4[0]; bh[ng * 2 + 0][1] = r4[2];
                bh[ng * 2 + 1][0] = r4[1]; bh[ng * 2 + 1][1] = r4[3];
                ldsm_x4(r4, addr + ARR_BYTES);
                bl[ng * 2 + 0][0] = r4[0]; bl[ng * 2 + 0][1] = r4[2];
                bl[ng * 2 + 1][0] = r4[1]; bl[ng * 2 + 1][1] = r4[3];
            }
#pragma unroll
            for (int mi = 0; mi < 4; mi++) {
                uint32_t aaddr = abase + (uint32_t)(wm + mi * 16 + (lane & 15)) * 80u + kcol;
                uint32_t ah[4], al[4];
                ldsm_x4(ah, aaddr);
                ldsm_x4(al, aaddr + ARR_BYTES);
#pragma unroll
                for (int ni = 0; ni < 4; ni++) {
                    mma16816(acc[mi][ni], ah, bh[ni][0], bh[ni][1]);
                    mma16816(acc[mi][ni], ah, bl[ni][0], bl[ni][1]);
                    mma16816(acc[mi][ni], al, bh[ni][0], bh[ni][1]);
                }
            }
        }
        __syncthreads();
    }

#pragma unroll
    for (int ni = 0; ni < 4; ni++) {
        int col = n0 + wn + ni * 8 + (lane & 3) * 2;
        if (col >= N) continue;
        float bb0 = b1[col], bb1 = b1[col + 1];
#pragma unroll
        for (int mi = 0; mi < 4; mi++) {
            int r0 = m0 + wm + mi * 16 + (lane >> 2);
#pragma unroll
            for (int h = 0; h < 2; h++) {
                int rr = r0 + h * 8;
                float v0 = acc[mi][ni][h * 2 + 0] + bb0;
                float v1 = acc[mi][ni][h * 2 + 1] + bb1;
                if (act) { v0 = tanhf(v0); v1 = tanhf(v1); }
                size_t base = (size_t)rr * N + col;
                *(float2*)&C[base] = make_float2(v0, v1);
                if (Chi) {
                    __half2 hh = __floats2half2_rn(v0, v1);
                    float2 hf = __half22float2(hh);
                    __half2 ll = __floats2half2_rn(v0 - hf.x, v1 - hf.y);
                    *(__half2*)&Chi[base] = hh;
                    *(__half2*)&Clo[base] = ll;
                }
            }
        }
    }
}

// ----------------------------------------------------------------------------
// Tensorized fused LSTM step.
// grid (16 n-blocks of 128 permuted gate cols, 8 m-blocks of 32 rows), 256 thr.
// gates = hm @ Whhp^T (fp16-split HMMA) + xg_perm; cell update fused.
// Outputs: c (pre-masked for t+1), h hi/lo (pre-masked), nh hi/lo (+h2 residual).
// ----------------------------------------------------------------------------
#define S_AH(b)  ((uint32_t)(b) * 2560u)
#define S_AL(b)  (5120u + (uint32_t)(b) * 2560u)
#define S_BH(b)  (10240u + (uint32_t)(b) * 10240u)
#define S_BL(b)  (30720u + (uint32_t)(b) * 10240u)
#define S_GSM    51200u
#define LSTM_SMEM 68608

__global__ __launch_bounds__(256, 1)
void lstm_mma_step(const __half* __restrict__ Wh, const __half* __restrict__ Wl,
                   const float* __restrict__ xg_t,
                   const int*   __restrict__ done_next,   // null on last step
                   const __half* __restrict__ hhi_in, const __half* __restrict__ hlo_in,
                   __half* __restrict__ hhi_out, __half* __restrict__ hlo_out,
                   float* __restrict__ c_buf,
                   const float* __restrict__ h2_t,
                   __half* __restrict__ nhhi_t, __half* __restrict__ nhlo_t)
{
    extern __shared__ __align__(16) char smem[];
    const uint32_t sb = smem_u32(smem);
    float* gsm = (float*)(smem + S_GSM);

    const int tid = threadIdx.x;
    const int lane = tid & 31, wid = tid >> 5;
    const int n0 = blockIdx.x * 128;      // permuted gate col base
    const int lbase = blockIdx.x * 32;    // l-range base
    const int r0 = blockIdx.y * 32;       // batch row base
    const int wm16 = (wid & 1) * 16, wn32 = (wid >> 1) * 32;

    float acc[4][4];
#pragma unroll
    for (int a = 0; a < 4; a++)
#pragma unroll
        for (int b = 0; b < 4; b++) acc[a][b] = 0.0f;

    auto load_chunk = [&](int c) {
        const int b = c & 1;
        const int k0 = c * 32;
#pragma unroll
        for (int i = 0; i < 5; i++) {
            int p = tid + i * 256;
            if (p < 256) {
                int hl = p >> 7, q = p & 127, row = q >> 2, c4 = q & 3;
                const __half* src = (hl ? hlo_in : hhi_in) + (size_t)(r0 + row) * LH + k0 + c4 * 8;
                uint32_t dst = sb + (hl ? S_AL(b) : S_AH(b)) + (uint32_t)row * 80u + (uint32_t)c4 * 16u;
                cp16(dst, src);
            } else {
                int pb = p - 256;
                int hl = pb >> 9, q = pb & 511, row = q >> 2, c4 = q & 3;
                const __half* src = (hl ? Wl : Wh) + (size_t)(n0 + row) * LH + k0 + c4 * 8;
                uint32_t dst = sb + (hl ? S_BL(b) : S_BH(b)) + (uint32_t)row * 80u + (uint32_t)c4 * 16u;
                cp16(dst, src);
            }
        }
        CP_COMMIT();
    };

    load_chunk(0);
    for (int c = 0; c < 16; c++) {
        if (c + 1 < 16) { load_chunk(c + 1); CP_WAIT1(); }
        else            { CP_WAIT0(); }
        __syncthreads();
        const int b = c & 1;
#pragma unroll
        for (int ks = 0; ks < 2; ks++) {
            const uint32_t kcol = (uint32_t)(ks * 16 + (lane >> 4) * 8) * 2u;
            uint32_t bh[4][2], bl[4][2];
#pragma unroll
            for (int ng = 0; ng < 2; ng++) {
                uint32_t row = (uint32_t)(wn32 + ng * 16 + ((lane >> 3) & 1) * 8 + (lane & 7));
                uint32_t addr = sb + S_BH(b) + row * 80u + kcol;
                uint32_t r4[4];
                ldsm_x4(r4, addr);
                bh[ng * 2 + 0][0] = r4[0]; bh[ng * 2 + 0][1] = r4[2];
                bh[ng * 2 + 1][0] = r4[1]; bh[ng * 2 + 1][1] = r4[3];
                ldsm_x4(r4, addr + 20480u);
                bl[ng * 2 + 0][0] = r4[0]; bl[ng * 2 + 0][1] = r4[2];
                bl[ng * 2 + 1][0] = r4[1]; bl[ng * 2 + 1][1] = r4[3];
            }
            uint32_t aaddr = sb + S_AH(b) + (uint32_t)(wm16 + (lane & 15)) * 80u + kcol;
            uint32_t ah[4], al[4];
            ldsm_x4(ah, aaddr);
            ldsm_x4(al, aaddr + 5120u);
#pragma unroll
            for (int ni = 0; ni < 4; ni++) {
                mma16816(acc[ni], ah, bh[ni][0], bh[ni][1]);
                mma16816(acc[ni], ah, bl[ni][0], bl[ni][1]);
                mma16816(acc[ni], al, bh[ni][0], bh[ni][1]);
            }
        }
        __syncthreads();
    }

    // stage gates (+ permuted xg) into SMEM
#pragma unroll
    for (int ni = 0; ni < 4; ni++) {
        int col = wn32 + ni * 8 + (lane & 3) * 2;
        int row0 = wm16 + (lane >> 2);
        const float* xr0 = xg_t + (size_t)(r0 + row0) * NG + n0 + col;
        gsm[row0 * 132 + col]     = acc[ni][0] + xr0[0];
        gsm[row0 * 132 + col + 1] = acc[ni][1] + xr0[1];
        const float* xr1 = xr0 + 8 * NG;
        gsm[(row0 + 8) * 132 + col]     = acc[ni][2] + xr1[0];
        gsm[(row0 + 8) * 132 + col + 1] = acc[ni][3] + xr1[1];
    }
    __syncthreads();

    // cell update: 32 rows x 32 l, 4 cells per thread
#pragma unroll
    for (int q = 0; q < 4; q++) {
        int cell = tid + q * 256;
        int r = cell >> 5;
        int li = cell & 31;
        float iv = gsm[r * 132 + li];
        float fv = gsm[r * 132 + 32 + li];
        float gv = gsm[r * 132 + 64 + li];
        float ov = gsm[r * 132 + 96 + li];
        size_t gi = (size_t)(r0 + r) * LH + lbase + li;
        float cp = c_buf[gi];                       // already masked
        float cn = sigm(fv) * cp + sigm(iv) * tanhf(gv);
        float hn = sigm(ov) * tanhf(cn);
        float mn = done_next ? (1.0f - (float)done_next[r0 + r]) : 1.0f;
        c_buf[gi] = cn * mn;
        float hm = hn * mn;
        __half hmh = __float2half_rn(hm);
        hhi_out[gi] = hmh;
        hlo_out[gi] = __float2half_rn(hm - __half2float(hmh));
        float nhv = hn + h2_t[gi];
        __half nhh = __float2half_rn(nhv);
        nhhi_t[gi] = nhh;
        nhlo_t[gi] = __float2half_rn(nhv - __half2float(nhh));
    }
}

// ----------------------------------------------------------------------------
__global__ __launch_bounds__(256)
void softmax_kernel(const float* __restrict__ logits,
                    const int* __restrict__ action,
                    float* __restrict__ out, int TBn)
{
    __shared__ float red[256];
    __shared__ float red2[256];
    const int row = blockIdx.x;
    const int tid = threadIdx.x;
    const float* lr = logits + (size_t)row * NA;

    float m = -3.402823e38f;
    for (int j = tid; j < NA; j += 256) m = fmaxf(m, lr[j]);
    red[tid] = m;
    __syncthreads();
    for (int s = 128; s > 0; s >>= 1) {
        if (tid < s) red[tid] = fmaxf(red[tid], red[tid + s]);
        __syncthreads();
    }
    m = red[0];
    __syncthreads();

    float s = 0.f, t = 0.f;
    for (int j = tid; j < NA; j += 256) {
        float l = lr[j];
        float e = expf(l - m);
        s += e;
        t += e * l;
    }
    red[tid] = s;
    red2[tid] = t;
    __syncthreads();
    for (int st = 128; st > 0; st >>= 1) {
        if (tid < st) { red[tid] += red[tid + st]; red2[tid] += red2[tid + st]; }
        __syncthreads();
    }
    if (tid == 0) {
        float ssum = red[0], tsum = red2[0];
        float lse = m + logf(ssum);
        float la = lr[action[row]];
        out[row] = la - lse;
        out[TBn + row] = lse - tsum / ssum;
    }
}

// ----------------------------------------------------------------------------
__global__ __launch_bounds__(256)
void critic_kernel(const float* __restrict__ ch, const float* __restrict__ Wc2,
                   const float* __restrict__ bc2, float* __restrict__ vout)
{
    __shared__ float wsh[LH];
    const int tid = threadIdx.x;
    for (int j = tid; j < LH; j += 256) wsh[j] = Wc2[j];
    __syncthreads();
    const int warp = tid >> 5, lane = tid & 31;
    const int row = blockIdx.x * 8 + warp;
    const float* r = ch + (size_t)row * LH;
    float s = 0.f;
    for (int k = lane; k < LH; k += 32) s += r[k] * wsh[k];
#pragma unroll
    for (int off = 16; off > 0; off >>= 1) s += __shfl_down_sync(0xFFFFFFFFu, s, off);
    if (lane == 0) vout[row] = s + bc2[0];
}

// ----------------------------------------------------------------------------
// host launcher
// ----------------------------------------------------------------------------
extern "C" void kernel_launch(void* const* d_in, const int* in_sizes, int n_in,
                              void* d_out, int out_size)
{
    const float* x    = (const float*)d_in[0];
    const int*   done = (const int*)d_in[1];
    const int*   act  = (const int*)d_in[2];
    const float* W_t1 = (const float*)d_in[4];
    const float* b_t1 = (const float*)d_in[5];
    const float* W_t2 = (const float*)d_in[6];
    const float* b_t2 = (const float*)d_in[7];
    const float* Wih  = (const float*)d_in[8];
    const float* Whh  = (const float*)d_in[9];
    const float* bih  = (const float*)d_in[10];
    const float* bhh  = (const float*)d_in[11];
    const float* Wa1  = (const float*)d_in[12];
    const float* ba1  = (const float*)d_in[13];
    const float* Wa2  = (const float*)d_in[14];
    const float* ba2  = (const float*)d_in[15];
    const float* Wc1  = (const float*)d_in[16];
    const float* bc1  = (const float*)d_in[17];
    const float* Wc2  = (const float*)d_in[18];
    const float* bc2  = (const float*)d_in[19];
    const float* h0   = (const float*)d_in[20];
    const float* c0   = (const float*)d_in[21];

    const int TBn = in_sizes[0] / DI;   // 65536
    const int T = TBn / BB;             // 256
    float* out = (float*)d_out;

    float *buf1, *h2, *xg, *logits, *cbuf, *biasp;
    cudaGetSymbolAddress((void**)&buf1,   g_buf1);
    cudaGetSymbolAddress((void**)&h2,     g_h2);
    cudaGetSymbolAddress((void**)&xg,     g_xg);
    cudaGetSymbolAddress((void**)&logits, g_logits);
    cudaGetSymbolAddress((void**)&cbuf,   g_cbuf);
    cudaGetSymbolAddress((void**)&biasp,  g_biasp);

    __half *xhi, *xlo, *b1hi, *b1lo, *h2hi, *h2lo, *nhhi, *nhlo, *hmhi, *hmlo;
    __half *wt1h, *wt1l, *wt2h, *wt2l, *wihh, *wihl, *whhh, *whhl;
    __half *wa1h, *wa1l, *wa2h, *wa2l, *wc1h, *wc1l;
    cudaGetSymbolAddress((void**)&xhi,  g_x_hi);   cudaGetSymbolAddress((void**)&xlo,  g_x_lo);
    cudaGetSymbolAddress((void**)&b1hi, g_b1_hi);  cudaGetSymbolAddress((void**)&b1lo, g_b1_lo);
    cudaGetSymbolAddress((void**)&h2hi, g_h2_hi);  cudaGetSymbolAddress((void**)&h2lo, g_h2_lo);
    cudaGetSymbolAddress((void**)&nhhi, g_nh_hi);  cudaGetSymbolAddress((void**)&nhlo, g_nh_lo);
    cudaGetSymbolAddress((void**)&hmhi, g_hm_hi);  cudaGetSymbolAddress((void**)&hmlo, g_hm_lo);
    cudaGetSymbolAddress((void**)&wt1h, g_wt1_hi); cudaGetSymbolAddress((void**)&wt1l, g_wt1_lo);
    cudaGetSymbolAddress((void**)&wt2h, g_wt2_hi); cudaGetSymbolAddress((void**)&wt2l, g_wt2_lo);
    cudaGetSymbolAddress((void**)&wihh, g_wihp_hi); cudaGetSymbolAddress((void**)&wihl, g_wihp_lo);
    cudaGetSymbolAddress((void**)&whhh, g_whhp_hi); cudaGetSymbolAddress((void**)&whhl, g_whhp_lo);
    cudaGetSymbolAddress((void**)&wa1h, g_wa1_hi); cudaGetSymbolAddress((void**)&wa1l, g_wa1_lo);
    cudaGetSymbolAddress((void**)&wa2h, g_wa2_hi); cudaGetSymbolAddress((void**)&wa2l, g_wa2_lo);
    cudaGetSymbolAddress((void**)&wc1h, g_wc1_hi); cudaGetSymbolAddress((void**)&wc1l, g_wc1_lo);

    cudaFuncSetAttribute(gemm16_kernel, cudaFuncAttributeMaxDynamicSharedMemorySize, G_SMEM);
    cudaFuncSetAttribute(lstm_mma_step, cudaFuncAttributeMaxDynamicSharedMemorySize, LSTM_SMEM);

    const dim3 blk(256);

    // launch 0: x split
    splitx_kernel<<<TBn * DI / 4 / 256, blk>>>(x, xhi, xlo, TBn * DI / 4);
    // launch 1: all weight prep (8 sections, max 262144 float4 -> 1024 blocks)
    prep_kernel<<<dim3(1024, 8), blk>>>(W_t1, W_t2, Wa1, Wc1, Wa2, Wih, Whh, bih, bhh);
    // launch 2: init state (masked by done[0])
    init_state_kernel<<<(BB * LH + 255) / 256, blk>>>(h0, c0, done, hmhi, hmlo, cbuf);

    const int MY = TBn / 128;
    // launches 3,4: trunk
    gemm16_kernel<<<dim3(4, MY), blk, G_SMEM>>>(
        xhi, xlo, wt1h, wt1l, b_t1, buf1, b1hi, b1lo, TBn, LH, DI, 1);
    gemm16_kernel<<<dim3(4, MY), blk, G_SMEM>>>(
        b1hi, b1lo, wt2h, wt2l, b_t2, h2, h2hi, h2lo, TBn, LH, LH, 1);
    // launch 5: batched x-gates in PERMUTED order (ncu -s5 lands here)
    gemm16_kernel<<<dim3(16, MY), blk, G_SMEM>>>(
        h2hi, h2lo, wihh, wihl, biasp, xg, nullptr, nullptr, TBn, NG, LH, 0);

    // lstm scan (tensorized)
    for (int t = 0; t < T; t++) {
        lstm_mma_step<<<dim3(16, 8), blk, LSTM_SMEM>>>(
            whhh, whhl,
            xg + (size_t)t * BB * NG,
            (t + 1 < T) ? (done + (size_t)(t + 1) * BB) : nullptr,
            hmhi + (size_t)(t & 1) * BB * LH,
            hmlo + (size_t)(t & 1) * BB * LH,
            hmhi + (size_t)((t + 1) & 1) * BB * LH,
            hmlo + (size_t)((t + 1) & 1) * BB * LH,
            cbuf,
            h2 + (size_t)t * BB * LH,
            nhhi + (size_t)t * BB * LH,
            nhlo + (size_t)t * BB * LH);
    }

    // actor head
    gemm16_kernel<<<dim3(4, MY), blk, G_SMEM>>>(
        nhhi, nhlo, wa1h, wa1l, ba1, buf1, b1hi, b1lo, TBn, LH, LH, 1);
    gemm16_kernel<<<dim3(8, MY), blk, G_SMEM>>>(
        b1hi, b1lo, wa2h, wa2l, ba2, logits, nullptr, nullptr, TBn, NA, LH, 0);
    softmax_kernel<<<TBn, blk>>>(logits, act, out, TBn);

    // critic head
    gemm16_kernel<<<dim3(4, MY), blk, G_SMEM>>>(
        nhhi, nhlo, wc1h, wc1l, bc1, buf1, nullptr, nullptr, TBn, LH, LH, 1);
    critic_kernel<<<TBn / 8, blk>>>(buf1, Wc2, bc2, out + (size_t)2 * TBn);
}

// round 6
// speedup vs baseline: 2.0901x; 1.0019x over previous
#include <cuda_runtime.h>
#include <cuda_fp16.h>
#include <math.h>
#include <stdint.h>

// ----------------------------------------------------------------------------
// Problem constants
// ----------------------------------------------------------------------------
#define LH 512      // hidden size
#define DI 512      // input size
#define NA 1000     // num actions
#define NAP 1024    // padded num actions
#define NG 2048     // 4*LH gate count
#define BB 256      // batch
#define TBMAX 65536 // T*B
#define TT 256      // time steps

// ----------------------------------------------------------------------------
// PTX helpers (base-target-safe: mma.sync / ldmatrix / cp.async only)
// ----------------------------------------------------------------------------
__device__ __forceinline__ uint32_t smem_u32(const void* p) {
    uint32_t a;
    asm("{ .reg .u64 t; cvta.to.shared.u64 t, %1; cvt.u32.u64 %0, t; }" : "=r"(a) : "l"(p));
    return a;
}
__device__ __forceinline__ void ldsm_x4(uint32_t (&r)[4], uint32_t addr) {
    asm volatile("ldmatrix.sync.aligned.m8n8.x4.shared.b16 {%0,%1,%2,%3}, [%4];"
                 : "=r"(r[0]), "=r"(r[1]), "=r"(r[2]), "=r"(r[3]) : "r"(addr));
}
__device__ __forceinline__ void mma16816(float (&d)[4], const uint32_t (&a)[4],
                                         uint32_t b0, uint32_t b1) {
    asm volatile(
        "mma.sync.aligned.m16n8k16.row.col.f32.f16.f16.f32 "
        "{%0,%1,%2,%3},{%4,%5,%6,%7},{%8,%9},{%0,%1,%2,%3};"
        : "+f"(d[0]), "+f"(d[1]), "+f"(d[2]), "+f"(d[3])
        : "r"(a[0]), "r"(a[1]), "r"(a[2]), "r"(a[3]), "r"(b0), "r"(b1));
}
__device__ __forceinline__ void cp16(uint32_t dst, const void* src) {
    asm volatile("cp.async.cg.shared.global [%0], [%1], 16;" :: "r"(dst), "l"(src) : "memory");
}
#define CP_COMMIT() asm volatile("cp.async.commit_group;" ::: "memory")
#define CP_WAIT1()  asm volatile("cp.async.wait_group 1;" ::: "memory")
#define CP_WAIT0()  asm volatile("cp.async.wait_group 0;" ::: "memory")

// gate permutation: pcol p -> original gate row. block=p>>7, gate=(p&127)>>5,
// l = (p>>7)*32 + (p&31); orig = gate*512 + l.
__host__ __device__ __forceinline__ int perm_orig(int p) {
    return (((p & 127) >> 5) << 9) + ((p >> 7) << 5) + (p & 31);
}

// ----------------------------------------------------------------------------
// Scratch (static device allocations)
// ----------------------------------------------------------------------------
__device__ float g_buf1[(size_t)TBMAX * LH];
__device__ float g_h2  [(size_t)TBMAX * LH];
__device__ float g_xg  [(size_t)TBMAX * NG];   // permuted gate order
__device__ float g_logits[(size_t)TBMAX * NA];
__device__ float g_cbuf[BB * LH];
__device__ float g_biasp[NG];                  // permuted bih+bhh
__device__ unsigned int g_bar[8];              // row-group barriers

// fp16 hi/lo operand arrays (16B-aligned for cp.async)
__device__ __align__(16) __half g_x_hi [(size_t)TBMAX * DI], g_x_lo [(size_t)TBMAX * DI];
__device__ __align__(16) __half g_b1_hi[(size_t)TBMAX * LH], g_b1_lo[(size_t)TBMAX * LH];
__device__ __align__(16) __half g_h2_hi[(size_t)TBMAX * LH], g_h2_lo[(size_t)TBMAX * LH];
__device__ __align__(16) __half g_nh_hi[(size_t)TBMAX * LH], g_nh_lo[(size_t)TBMAX * LH];
__device__ __align__(16) __half g_hm_hi[2 * BB * LH], g_hm_lo[2 * BB * LH]; // masked h ping-pong
__device__ __align__(16) __half g_wt1_hi[LH * DI], g_wt1_lo[LH * DI];
__device__ __align__(16) __half g_wt2_hi[LH * LH], g_wt2_lo[LH * LH];
__device__ __align__(16) __half g_wihp_hi[NG * LH], g_wihp_lo[NG * LH];   // permuted
__device__ __align__(16) __half g_whhp_hi[NG * LH], g_whhp_lo[NG * LH];   // permuted
__device__ __align__(16) __half g_wa1_hi[LH * LH], g_wa1_lo[LH * LH];
__device__ __align__(16) __half g_wa2_hi[NAP * LH], g_wa2_lo[NAP * LH];
__device__ __align__(16) __half g_wc1_hi[LH * LH], g_wc1_lo[LH * LH];

__device__ __forceinline__ float sigm(float x) { return 1.0f / (1.0f + expf(-x)); }

__device__ __forceinline__ void split_store4(float4 v, __half* H, __half* L, size_t idx) {
    __half2 a = __floats2half2_rn(v.x, v.y);
    __half2 b = __floats2half2_rn(v.z, v.w);
    float2 af = __half22float2(a), bf = __half22float2(b);
    __half2 al = __floats2half2_rn(v.x - af.x, v.y - af.y);
    __half2 bl = __floats2half2_rn(v.z - bf.x, v.w - bf.y);
    *(__half2*)&H[idx] = a;  *(__half2*)&H[idx + 2] = b;
    *(__half2*)&L[idx] = al; *(__half2*)&L[idx + 2] = bl;
}

// ----------------------------------------------------------------------------
// x split (big, standalone)
// ----------------------------------------------------------------------------
__global__ __launch_bounds__(256)
void splitx_kernel(const float* __restrict__ X, __half* __restrict__ H,
                   __half* __restrict__ L, int n4)
{
    int i = blockIdx.x * 256 + threadIdx.x;
    if (i < n4) split_store4(((const float4*)X)[i], H, L, (size_t)i * 4);
}

// ----------------------------------------------------------------------------
// fused weight prep: splits + permutation + padding + bias perm.
// ----------------------------------------------------------------------------
__global__ __launch_bounds__(256)
void prep_kernel(const float* __restrict__ W_t1, const float* __restrict__ W_t2,
                 const float* __restrict__ Wa1, const float* __restrict__ Wc1,
                 const float* __restrict__ Wa2,
                 const float* __restrict__ Wih, const float* __restrict__ Whh,
                 const float* __restrict__ bih, const float* __restrict__ bhh)
{
    const int i = blockIdx.x * 256 + threadIdx.x;
    const int sec = blockIdx.y;
    switch (sec) {
    case 0: if (i < LH * DI / 4) split_store4(((const float4*)W_t1)[i], g_wt1_hi, g_wt1_lo, (size_t)i * 4); break;
    case 1: if (i < LH * LH / 4) split_store4(((const float4*)W_t2)[i], g_wt2_hi, g_wt2_lo, (size_t)i * 4); break;
    case 2: if (i < LH * LH / 4) split_store4(((const float4*)Wa1)[i], g_wa1_hi, g_wa1_lo, (size_t)i * 4); break;
    case 3: if (i < LH * LH / 4) split_store4(((const float4*)Wc1)[i], g_wc1_hi, g_wc1_lo, (size_t)i * 4); break;
    case 4:
        if (i < NAP * LH / 4) {
            if (i < NA * LH / 4) split_store4(((const float4*)Wa2)[i], g_wa2_hi, g_wa2_lo, (size_t)i * 4);
            else {
                __half2 z = __floats2half2_rn(0.f, 0.f);
                *(__half2*)&g_wa2_hi[(size_t)i * 4] = z; *(__half2*)&g_wa2_hi[(size_t)i * 4 + 2] = z;
                *(__half2*)&g_wa2_lo[(size_t)i * 4] = z; *(__half2*)&g_wa2_lo[(size_t)i * 4 + 2] = z;
            }
        }
        break;
    case 5:
        if (i < NG * LH / 4) {
            int row = i >> 7;
            int c4 = i & 127;
            float4 v = ((const float4*)(Wih + (size_t)perm_orig(row) * LH))[c4];
            split_store4(v, g_wihp_hi, g_wihp_lo, (size_t)i * 4);
        }
        break;
    case 6:
        if (i < NG * LH / 4) {
            int row = i >> 7;
            int c4 = i & 127;
            float4 v = ((const float4*)(Whh + (size_t)perm_orig(row) * LH))[c4];
            split_store4(v, g_whhp_hi, g_whhp_lo, (size_t)i * 4);
        }
        break;
    case 7:
        if (i < NG) { int o = perm_orig(i); g_biasp[i] = bih[o] + bhh[o]; }
        break;
    }
}

// ----------------------------------------------------------------------------
// init: masked h0/c0; h0 split to fp16 hi/lo; zero scan barriers
// ----------------------------------------------------------------------------
__global__ __launch_bounds__(256)
void init_state_kernel(const float* __restrict__ h0, const float* __restrict__ c0,
                       const int* __restrict__ done0,
                       __half* __restrict__ hhi, __half* __restrict__ hlo,
                       float* __restrict__ c)
{
    int idx = blockIdx.x * 256 + threadIdx.x;
    if (blockIdx.x == 0 && threadIdx.x < 8) g_bar[threadIdx.x] = 0u;
    if (idx < BB * LH) {
        float m = 1.0f - (float)done0[idx >> 9];
        float hv = h0[idx] * m;
        __half hh = __float2half_rn(hv);
        hhi[idx] = hh;
        hlo[idx] = __float2half_rn(hv - __half2float(hh));
        c[idx] = c0[idx] * m;
    }
}

// ----------------------------------------------------------------------------
// HMMA fp32-via-fp16-split GEMM (validated round 4) — unchanged.
// ----------------------------------------------------------------------------
#define ARR_BYTES 10240u
#define BUF_BYTES 40960u
#define G_SMEM 81920

__global__ __launch_bounds__(256, 2)
void gemm16_kernel(const __half* __restrict__ Ahi, const __half* __restrict__ Alo,
                   const __half* __restrict__ Bhi, const __half* __restrict__ Blo,
                   const float* __restrict__ b1,
                   float* __restrict__ C, __half* __restrict__ Chi, __half* __restrict__ Clo,
                   int M, int N, int K, int act)
{
    extern __shared__ __align__(16) char smem[];
    const uint32_t sb = smem_u32(smem);
    const int tid = threadIdx.x;
    const int lane = tid & 31, wid = tid >> 5;
    const int m0 = blockIdx.y * 128, n0 = blockIdx.x * 128;
    const int wm = (wid >> 2) * 64, wn = (wid & 3) * 32;

    float acc[4][4][4];
#pragma unroll
    for (int a = 0; a < 4; a++)
#pragma unroll
        for (int b = 0; b < 4; b++)
#pragma unroll
            for (int c = 0; c < 4; c++) acc[a][b][c] = 0.0f;

    const int NCH = K >> 5;

    auto issue_chunk = [&](int c) {
        const uint32_t bufb = (uint32_t)(c & 1) * BUF_BYTES;
        const int k0 = c * 32;
#pragma unroll
        for (int i = 0; i < 8; i++) {
            int p = tid + i * 256;
            int arr = p >> 9;
            int q = p & 511;
            int r = q >> 2;
            int ch = (q & 3) * 8;
            int grow = (arr < 2 ? m0 : n0) + r;
            const __half* src =
                (arr == 0 ? Ahi : arr == 1 ? Alo : arr == 2 ? Bhi : Blo)
                + (size_t)grow * K + k0 + ch;
            uint32_t dst = sb + bufb + (uint32_t)arr * ARR_BYTES
                         + (uint32_t)r * 80u + (uint32_t)ch * 2u;
            cp16(dst, src);
        }
        CP_COMMIT();
    };

    issue_chunk(0);

    for (int c = 0; c < NCH; c++) {
        if (c + 1 < NCH) { issue_chunk(c + 1); CP_WAIT1(); }
        else             { CP_WAIT0(); }
        __syncthreads();

        const uint32_t abase = sb + (uint32_t)(c & 1) * BUF_BYTES;
#pragma unroll
        for (int ks = 0; ks < 2; ks++) {
            const uint32_t kcol = (uint32_t)(ks * 16 + (lane >> 4) * 8) * 2u;
            uint32_t bh[4][2], bl[4][2];
#pragma unroll
            for (int ng = 0; ng < 2; ng++) {
                uint32_t row = (uint32_t)(wn + ng * 16 + ((lane >> 3) & 1) * 8 + (lane & 7));
                uint32_t addr = abase + 2u * ARR_BYTES + row * 80u + kcol;
                uint32_t r4[4];
                ldsm_x4(r4, addr);
                bh[ng * 2 + 0][0] = r4[0]; bh[ng * 2 + 0][1] = r4[2];
                bh[ng * 2 + 1][0] = r4[1]; bh[ng * 2 + 1][1] = r4[3];
                ldsm_x4(r4, addr + ARR_BYTES);
                bl[ng * 2 + 0][0] = r4[0]; bl[ng * 2 + 0][1] = r4[2];
                bl[ng * 2 + 1][0] = r4[1]; bl[ng * 2 + 1][1] = r4[3];
            }
#pragma unroll
            for (int mi = 0; mi < 4; mi++) {
                uint32_t aaddr = abase + (uint32_t)(wm + mi * 16 + (lane & 15)) * 80u + kcol;
                uint32_t ah[4], al[4];
                ldsm_x4(ah, aaddr);
                ldsm_x4(al, aaddr + ARR_BYTES);
#pragma unroll
                for (int ni = 0; ni < 4; ni++) {
                    mma16816(acc[mi][ni], ah, bh[ni][0], bh[ni][1]);
                    mma16816(acc[mi][ni], ah, bl[ni][0], bl[ni][1]);
                    mma16816(acc[mi][ni], al, bh[ni][0], bh[ni][1]);
                }
            }
        }
        __syncthreads();
    }

#pragma unroll
    for (int ni = 0; ni < 4; ni++) {
        int col = n0 + wn + ni * 8 + (lane & 3) * 2;
        if (col >= N) continue;
        float bb0 = b1[col], bb1 = b1[col + 1];
#pragma unroll
        for (int mi = 0; mi < 4; mi++) {
            int r0 = m0 + wm + mi * 16 + (lane >> 2);
#pragma unroll
            for (int h = 0; h < 2; h++) {
                int rr = r0 + h * 8;
                float v0 = acc[mi][ni][h * 2 + 0] + bb0;
                float v1 = acc[mi][ni][h * 2 + 1] + bb1;
                if (act) { v0 = tanhf(v0); v1 = tanhf(v1); }
                size_t base = (size_t)rr * N + col;
                *(float2*)&C[base] = make_float2(v0, v1);
                if (Chi) {
                    __half2 hh = __floats2half2_rn(v0, v1);
                    float2 hf = __half22float2(hh);
                    __half2 ll = __floats2half2_rn(v0 - hf.x, v1 - hf.y);
                    *(__half2*)&Chi[base] = hh;
                    *(__half2*)&Clo[base] = ll;
                }
            }
        }
    }
}

// ----------------------------------------------------------------------------
// PERSISTENT tensorized LSTM scan. grid (16,8) = 128 CTAs, all resident.
// Each CTA: 32 batch rows x 128 permuted gate cols, loops t = 0..T-1.
// Cross-step sync: per-row-group (blockIdx.y) counter barrier over 16 CTAs.
// ----------------------------------------------------------------------------
#define S_AH(b)  ((uint32_t)(b) * 2560u)
#define S_AL(b)  (5120u + (uint32_t)(b) * 2560u)
#define S_BH(b)  (10240u + (uint32_t)(b) * 10240u)
#define S_BL(b)  (30720u + (uint32_t)(b) * 10240u)
#define S_GSM    51200u
#define LSTM_SMEM 68608

__global__ __launch_bounds__(256, 1)
void lstm_persist(const __half* __restrict__ Wh, const __half* __restrict__ Wl,
                  const float* __restrict__ xg,
                  const int*   __restrict__ done,
                  __half* __restrict__ hmhi, __half* __restrict__ hmlo,
                  float* __restrict__ c_buf,
                  const float* __restrict__ h2,
                  __half* __restrict__ nhhi, __half* __restrict__ nhlo,
                  int T)
{
    extern __shared__ __align__(16) char smem[];
    const uint32_t sb = smem_u32(smem);
    float* gsm = (float*)(smem + S_GSM);

    const int tid = threadIdx.x;
    const int lane = tid & 31, wid = tid >> 5;
    const int n0 = blockIdx.x * 128;
    const int lbase = blockIdx.x * 32;
    const int r0 = blockIdx.y * 32;
    const int rb = blockIdx.y;
    const int wm16 = (wid & 1) * 16, wn32 = (wid >> 1) * 32;

    for (int t = 0; t < T; t++) {
        // wait for previous step's h writes from all 16 CTAs of this row group
        if (t > 0) {
            if (tid == 0) {
                unsigned int need = (unsigned int)(16 * t);
                while (atomicAdd(&g_bar[rb], 0u) < need) { __nanosleep(100); }
            }
            __syncthreads();
            __threadfence();
        }

        const __half* hhi_in = hmhi + (size_t)(t & 1) * BB * LH;
        const __half* hlo_in = hmlo + (size_t)(t & 1) * BB * LH;
        const float* xg_t = xg + (size_t)t * BB * NG;
        const float* h2_t = h2 + (size_t)t * BB * LH;

        float acc[4][4];
#pragma unroll
        for (int a = 0; a < 4; a++)
#pragma unroll
            for (int b = 0; b < 4; b++) acc[a][b] = 0.0f;

        auto load_chunk = [&](int c) {
            const int b = c & 1;
            const int k0 = c * 32;
#pragma unroll
            for (int i = 0; i < 5; i++) {
                int p = tid + i * 256;
                if (p < 256) {
                    int hl = p >> 7, q = p & 127, row = q >> 2, c4 = q & 3;
                    const __half* src = (hl ? hlo_in : hhi_in) + (size_t)(r0 + row) * LH + k0 + c4 * 8;
                    uint32_t dst = sb + (hl ? S_AL(b) : S_AH(b)) + (uint32_t)row * 80u + (uint32_t)c4 * 16u;
                    cp16(dst, src);
                } else {
                    int pb = p - 256;
                    int hl = pb >> 9, q = pb & 511, row = q >> 2, c4 = q & 3;
                    const __half* src = (hl ? Wl : Wh) + (size_t)(n0 + row) * LH + k0 + c4 * 8;
                    uint32_t dst = sb + (hl ? S_BL(b) : S_BH(b)) + (uint32_t)row * 80u + (uint32_t)c4 * 16u;
                    cp16(dst, src);
                }
            }
            CP_COMMIT();
        };

        load_chunk(0);
        for (int c = 0; c < 16; c++) {
            if (c + 1 < 16) { load_chunk(c + 1); CP_WAIT1(); }
            else            { CP_WAIT0(); }
            __syncthreads();
            const int b = c & 1;
#pragma unroll
            for (int ks = 0; ks < 2; ks++) {
                const uint32_t kcol = (uint32_t)(ks * 16 + (lane >> 4) * 8) * 2u;
                uint32_t bh[4][2], bl[4][2];
#pragma unroll
                for (int ng = 0; ng < 2; ng++) {
                    uint32_t row = (uint32_t)(wn32 + ng * 16 + ((lane >> 3) & 1) * 8 + (lane & 7));
                    uint32_t addr = sb + S_BH(b) + row * 80u + kcol;
                    uint32_t r4[4];
                    ldsm_x4(r4, addr);
                    bh[ng * 2 + 0][0] = r4[0]; bh[ng * 2 + 0][1] = r4[2];
                    bh[ng * 2 + 1][0] = r4[1]; bh[ng * 2 + 1][1] = r4[3];
                    ldsm_x4(r4, addr + 20480u);
                    bl[ng * 2 + 0][0] = r4[0]; bl[ng * 2 + 0][1] = r4[2];
                    bl[ng * 2 + 1][0] = r4[1]; bl[ng * 2 + 1][1] = r4[3];
                }
                uint32_t aaddr = sb + S_AH(b) + (uint32_t)(wm16 + (lane & 15)) * 80u + kcol;
                uint32_t ah[4], al[4];
                ldsm_x4(ah, aaddr);
                ldsm_x4(al, aaddr + 5120u);
#pragma unroll
                for (int ni = 0; ni < 4; ni++) {
                    mma16816(acc[ni], ah, bh[ni][0], bh[ni][1]);
                    mma16816(acc[ni], ah, bl[ni][0], bl[ni][1]);
                    mma16816(acc[ni], al, bh[ni][0], bh[ni][1]);
                }
            }
            __syncthreads();
        }

        // stage gates (+ permuted xg) into SMEM
#pragma unroll
        for (int ni = 0; ni < 4; ni++) {
            int col = wn32 + ni * 8 + (lane & 3) * 2;
            int row0 = wm16 + (lane >> 2);
            const float* xr0 = xg_t + (size_t)(r0 + row0) * NG + n0 + col;
            gsm[row0 * 132 + col]     = acc[ni][0] + xr0[0];
            gsm[row0 * 132 + col + 1] = acc[ni][1] + xr0[1];
            const float* xr1 = xr0 + 8 * NG;
            gsm[(row0 + 8) * 132 + col]     = acc[ni][2] + xr1[0];
            gsm[(row0 + 8) * 132 + col + 1] = acc[ni][3] + xr1[1];
        }
        __syncthreads();

        __half* hhi_out = hmhi + (size_t)((t + 1) & 1) * BB * LH;
        __half* hlo_out = hmlo + (size_t)((t + 1) & 1) * BB * LH;
        __half* nhhi_t = nhhi + (size_t)t * BB * LH;
        __half* nhlo_t = nhlo + (size_t)t * BB * LH;
        const int* done_next = (t + 1 < T) ? (done + (size_t)(t + 1) * BB) : nullptr;

        // cell update: 32 rows x 32 l, 4 cells per thread
#pragma unroll
        for (int q = 0; q < 4; q++) {
            int cell = tid + q * 256;
            int r = cell >> 5;
            int li = cell & 31;
            float iv = gsm[r * 132 + li];
            float fv = gsm[r * 132 + 32 + li];
            float gv = gsm[r * 132 + 64 + li];
            float ov = gsm[r * 132 + 96 + li];
            size_t gi = (size_t)(r0 + r) * LH + lbase + li;
            float cp = c_buf[gi];                       // already masked
            float cn = sigm(fv) * cp + sigm(iv) * tanhf(gv);
            float hn = sigm(ov) * tanhf(cn);
            float mn = done_next ? (1.0f - (float)done_next[r0 + r]) : 1.0f;
            c_buf[gi] = cn * mn;
            float hm = hn * mn;
            __half hmh = __float2half_rn(hm);
            hhi_out[gi] = hmh;
            hlo_out[gi] = __float2half_rn(hm - __half2float(hmh));
            float nhv = hn + h2_t[gi];
            __half nhh = __float2half_rn(nhv);
            nhhi_t[gi] = nhh;
            nhlo_t[gi] = __float2half_rn(nhv - __half2float(nhh));
        }

        // publish this step's h to the row group
        __threadfence();
        __syncthreads();
        if (tid == 0) atomicAdd(&g_bar[rb], 1u);
    }
}

// ----------------------------------------------------------------------------
__global__ __launch_bounds__(256)
void softmax_kernel(const float* __restrict__ logits,
                    const int* __restrict__ action,
                    float* __restrict__ out, int TBn)
{
    __shared__ float red[256];
    __shared__ float red2[256];
    const int row = blockIdx.x;
    const int tid = threadIdx.x;
    const float* lr = logits + (size_t)row * NA;

    float m = -3.402823e38f;
    for (int j = tid; j < NA; j += 256) m = fmaxf(m, lr[j]);
    red[tid] = m;
    __syncthreads();
    for (int s = 128; s > 0; s >>= 1) {
        if (tid < s) red[tid] = fmaxf(red[tid], red[tid + s]);
        __syncthreads();
    }
    m = red[0];
    __syncthreads();

    float s = 0.f, t = 0.f;
    for (int j = tid; j < NA; j += 256) {
        float l = lr[j];
        float e = expf(l - m);
        s += e;
        t += e * l;
    }
    red[tid] = s;
    red2[tid] = t;
    __syncthreads();
    for (int st = 128; st > 0; st >>= 1) {
        if (tid < st) { red[tid] += red[tid + st]; red2[tid] += red2[tid + st]; }
        __syncthreads();
    }
    if (tid == 0) {
        float ssum = red[0], tsum = red2[0];
        float lse = m + logf(ssum);
        float la = lr[action[row]];
        out[row] = la - lse;
        out[TBn + row] = lse - tsum / ssum;
    }
}

// ----------------------------------------------------------------------------
__global__ __launch_bounds__(256)
void critic_kernel(const float* __restrict__ ch, const float* __restrict__ Wc2,
                   const float* __restrict__ bc2, float* __restrict__ vout)
{
    __shared__ float wsh[LH];
    const int tid = threadIdx.x;
    for (int j = tid; j < LH; j += 256) wsh[j] = Wc2[j];
    __syncthreads();
    const int warp = tid >> 5, lane = tid & 31;
    const int row = blockIdx.x * 8 + warp;
    const float* r = ch + (size_t)row * LH;
    float s = 0.f;
    for (int k = lane; k < LH; k += 32) s += r[k] * wsh[k];
#pragma unroll
    for (int off = 16; off > 0; off >>= 1) s += __shfl_down_sync(0xFFFFFFFFu, s, off);
    if (lane == 0) vout[row] = s + bc2[0];
}

// ----------------------------------------------------------------------------
// host launcher
// ----------------------------------------------------------------------------
extern "C" void kernel_launch(void* const* d_in, const int* in_sizes, int n_in,
                              void* d_out, int out_size)
{
    const float* x    = (const float*)d_in[0];
    const int*   done = (const int*)d_in[1];
    const int*   act  = (const int*)d_in[2];
    const float* W_t1 = (const float*)d_in[4];
    const float* b_t1 = (const float*)d_in[5];
    const float* W_t2 = (const float*)d_in[6];
    const float* b_t2 = (const float*)d_in[7];
    const float* Wih  = (const float*)d_in[8];
    const float* Whh  = (const float*)d_in[9];
    const float* bih  = (const float*)d_in[10];
    const float* bhh  = (const float*)d_in[11];
    const float* Wa1  = (const float*)d_in[12];
    const float* ba1  = (const float*)d_in[13];
    const float* Wa2  = (const float*)d_in[14];
    const float* ba2  = (const float*)d_in[15];
    const float* Wc1  = (const float*)d_in[16];
    const float* bc1  = (const float*)d_in[17];
    const float* Wc2  = (const float*)d_in[18];
    const float* bc2  = (const float*)d_in[19];
    const float* h0   = (const float*)d_in[20];
    const float* c0   = (const float*)d_in[21];

    const int TBn = in_sizes[0] / DI;   // 65536
    const int T = TBn / BB;             // 256
    float* out = (float*)d_out;

    float *buf1, *h2, *xg, *logits, *cbuf, *biasp;
    cudaGetSymbolAddress((void**)&buf1,   g_buf1);
    cudaGetSymbolAddress((void**)&h2,     g_h2);
    cudaGetSymbolAddress((void**)&xg,     g_xg);
    cudaGetSymbolAddress((void**)&logits, g_logits);
    cudaGetSymbolAddress((void**)&cbuf,   g_cbuf);
    cudaGetSymbolAddress((void**)&biasp,  g_biasp);

    __half *xhi, *xlo, *b1hi, *b1lo, *h2hi, *h2lo, *nhhi, *nhlo, *hmhi, *hmlo;
    __half *wt1h, *wt1l, *wt2h, *wt2l, *wihh, *wihl, *whhh, *whhl;
    __half *wa1h, *wa1l, *wa2h, *wa2l, *wc1h, *wc1l;
    cudaGetSymbolAddress((void**)&xhi,  g_x_hi);   cudaGetSymbolAddress((void**)&xlo,  g_x_lo);
    cudaGetSymbolAddress((void**)&b1hi, g_b1_hi);  cudaGetSymbolAddress((void**)&b1lo, g_b1_lo);
    cudaGetSymbolAddress((void**)&h2hi, g_h2_hi);  cudaGetSymbolAddress((void**)&h2lo, g_h2_lo);
    cudaGetSymbolAddress((void**)&nhhi, g_nh_hi);  cudaGetSymbolAddress((void**)&nhlo, g_nh_lo);
    cudaGetSymbolAddress((void**)&hmhi, g_hm_hi);  cudaGetSymbolAddress((void**)&hmlo, g_hm_lo);
    cudaGetSymbolAddress((void**)&wt1h, g_wt1_hi); cudaGetSymbolAddress((void**)&wt1l, g_wt1_lo);
    cudaGetSymbolAddress((void**)&wt2h, g_wt2_hi); cudaGetSymbolAddress((void**)&wt2l, g_wt2_lo);
    cudaGetSymbolAddress((void**)&wihh, g_wihp_hi); cudaGetSymbolAddress((void**)&wihl, g_wihp_lo);
    cudaGetSymbolAddress((void**)&whhh, g_whhp_hi); cudaGetSymbolAddress((void**)&whhl, g_whhp_lo);
    cudaGetSymbolAddress((void**)&wa1h, g_wa1_hi); cudaGetSymbolAddress((void**)&wa1l, g_wa1_lo);
    cudaGetSymbolAddress((void**)&wa2h, g_wa2_hi); cudaGetSymbolAddress((void**)&wa2l, g_wa2_lo);
    cudaGetSymbolAddress((void**)&wc1h, g_wc1_hi); cudaGetSymbolAddress((void**)&wc1l, g_wc1_lo);

    cudaFuncSetAttribute(gemm16_kernel, cudaFuncAttributeMaxDynamicSharedMemorySize, G_SMEM);
    cudaFuncSetAttribute(lstm_persist, cudaFuncAttributeMaxDynamicSharedMemorySize, LSTM_SMEM);

    const dim3 blk(256);

    splitx_kernel<<<TBn * DI / 4 / 256, blk>>>(x, xhi, xlo, TBn * DI / 4);
    prep_kernel<<<dim3(1024, 8), blk>>>(W_t1, W_t2, Wa1, Wc1, Wa2, Wih, Whh, bih, bhh);
    init_state_kernel<<<(BB * LH + 255) / 256, blk>>>(h0, c0, done, hmhi, hmlo, cbuf);

    const int MY = TBn / 128;
    gemm16_kernel<<<dim3(4, MY), blk, G_SMEM>>>(
        xhi, xlo, wt1h, wt1l, b_t1, buf1, b1hi, b1lo, TBn, LH, DI, 1);
    gemm16_kernel<<<dim3(4, MY), blk, G_SMEM>>>(
        b1hi, b1lo, wt2h, wt2l, b_t2, h2, h2hi, h2lo, TBn, LH, LH, 1);
    gemm16_kernel<<<dim3(16, MY), blk, G_SMEM>>>(
        h2hi, h2lo, wihh, wihl, biasp, xg, nullptr, nullptr, TBn, NG, LH, 0);

    // persistent lstm scan: ONE launch, internal t-loop + row-group barriers
    lstm_persist<<<dim3(16, 8), blk, LSTM_SMEM>>>(
        whhh, whhl, xg, done, hmhi, hmlo, cbuf, h2, nhhi, nhlo, T);

    // actor head
    gemm16_kernel<<<dim3(4, MY), blk, G_SMEM>>>(
        nhhi, nhlo, wa1h, wa1l, ba1, buf1, b1hi, b1lo, TBn, LH, LH, 1);
    gemm16_kernel<<<dim3(8, MY), blk, G_SMEM>>>(
        b1hi, b1lo, wa2h, wa2l, ba2, logits, nullptr, nullptr, TBn, NA, LH, 0);
    softmax_kernel<<<TBn, blk>>>(logits, act, out, TBn);

    // critic head
    gemm16_kernel<<<dim3(4, MY), blk, G_SMEM>>>(
        nhhi, nhlo, wc1h, wc1l, bc1, buf1, nullptr, nullptr, TBn, LH, LH, 1);
    critic_kernel<<<TBn / 8, blk>>>(buf1, Wc2, bc2, out + (size_t)2 * TBn);
}

// round 7
// speedup vs baseline: 2.2957x; 1.0984x over previous
#include <cuda_runtime.h>
#include <cuda_fp16.h>
#include <math.h>
#include <stdint.h>

// ----------------------------------------------------------------------------
// Problem constants
// ----------------------------------------------------------------------------
#define LH 512      // hidden size
#define DI 512      // input size
#define NA 1000     // num actions
#define NAP 1024    // padded num actions
#define NG 2048     // 4*LH gate count
#define BB 256      // batch
#define TBMAX 65536 // T*B

// ----------------------------------------------------------------------------
// PTX helpers (base-target-safe: mma.sync / ldmatrix / cp.async only)
// ----------------------------------------------------------------------------
__device__ __forceinline__ uint32_t smem_u32(const void* p) {
    uint32_t a;
    asm("{ .reg .u64 t; cvta.to.shared.u64 t, %1; cvt.u32.u64 %0, t; }" : "=r"(a) : "l"(p));
    return a;
}
__device__ __forceinline__ void ldsm_x4(uint32_t (&r)[4], uint32_t addr) {
    asm volatile("ldmatrix.sync.aligned.m8n8.x4.shared.b16 {%0,%1,%2,%3}, [%4];"
                 : "=r"(r[0]), "=r"(r[1]), "=r"(r[2]), "=r"(r[3]) : "r"(addr));
}
__device__ __forceinline__ void mma16816(float (&d)[4], const uint32_t (&a)[4],
                                         uint32_t b0, uint32_t b1) {
    asm volatile(
        "mma.sync.aligned.m16n8k16.row.col.f32.f16.f16.f32 "
        "{%0,%1,%2,%3},{%4,%5,%6,%7},{%8,%9},{%0,%1,%2,%3};"
        : "+f"(d[0]), "+f"(d[1]), "+f"(d[2]), "+f"(d[3])
        : "r"(a[0]), "r"(a[1]), "r"(a[2]), "r"(a[3]), "r"(b0), "r"(b1));
}
__device__ __forceinline__ void cp16(uint32_t dst, const void* src) {
    asm volatile("cp.async.cg.shared.global [%0], [%1], 16;" :: "r"(dst), "l"(src) : "memory");
}
#define CP_COMMIT() asm volatile("cp.async.commit_group;" ::: "memory")
#define CP_WAIT1()  asm volatile("cp.async.wait_group 1;" ::: "memory")
#define CP_WAIT0()  asm volatile("cp.async.wait_group 0;" ::: "memory")

// gate permutation: pcol p -> original gate row.
__host__ __device__ __forceinline__ int perm_orig(int p) {
    return (((p & 127) >> 5) << 9) + ((p >> 7) << 5) + (p & 31);
}

// ----------------------------------------------------------------------------
// Scratch (static device allocations)
// ----------------------------------------------------------------------------
__device__ float g_buf1[(size_t)TBMAX * LH];
__device__ float g_h2  [(size_t)TBMAX * LH];
__device__ float g_xg  [(size_t)TBMAX * NG];
__device__ float g_cbuf[BB * LH];
__device__ float g_biasp[NG];
__device__ unsigned int g_bar[8];
__device__ __align__(16) float4 g_part[(size_t)TBMAX * 8];      // softmax partials (m,s,t)
__device__ __align__(16) __half g_l16[(size_t)TBMAX * NAP];      // fp16 logits for gather

// fp16 hi/lo operand arrays
__device__ __align__(16) __half g_x_hi [(size_t)TBMAX * DI], g_x_lo [(size_t)TBMAX * DI];
__device__ __align__(16) __half g_b1_hi[(size_t)TBMAX * LH], g_b1_lo[(size_t)TBMAX * LH];
__device__ __align__(16) __half g_h2_hi[(size_t)TBMAX * LH], g_h2_lo[(size_t)TBMAX * LH];
__device__ __align__(16) __half g_nh_hi[(size_t)TBMAX * LH], g_nh_lo[(size_t)TBMAX * LH];
__device__ __align__(16) __half g_hm_hi[2 * BB * LH], g_hm_lo[2 * BB * LH];
__device__ __align__(16) __half g_wt1_hi[LH * DI], g_wt1_lo[LH * DI];
__device__ __align__(16) __half g_wt2_hi[LH * LH], g_wt2_lo[LH * LH];
__device__ __align__(16) __half g_wihp_hi[NG * LH], g_wihp_lo[NG * LH];
__device__ __align__(16) __half g_whhp_hi[NG * LH], g_whhp_lo[NG * LH];
__device__ __align__(16) __half g_wa1_hi[LH * LH];
__device__ __align__(16) __half g_wa2_hi[NAP * LH];
__device__ __align__(16) __half g_wc1_hi[LH * LH];

__device__ __forceinline__ float sigm(float x) { return 1.0f / (1.0f + expf(-x)); }

__device__ __forceinline__ void split_store4(float4 v, __half* H, __half* L, size_t idx) {
    __half2 a = __floats2half2_rn(v.x, v.y);
    __half2 b = __floats2half2_rn(v.z, v.w);
    float2 af = __half22float2(a), bf = __half22float2(b);
    __half2 al = __floats2half2_rn(v.x - af.x, v.y - af.y);
    __half2 bl = __floats2half2_rn(v.z - bf.x, v.w - bf.y);
    *(__half2*)&H[idx] = a;  *(__half2*)&H[idx + 2] = b;
    *(__half2*)&L[idx] = al; *(__half2*)&L[idx + 2] = bl;
}
__device__ __forceinline__ void hi_store4(float4 v, __half* H, size_t idx) {
    *(__half2*)&H[idx] = __floats2half2_rn(v.x, v.y);
    *(__half2*)&H[idx + 2] = __floats2half2_rn(v.z, v.w);
}

// ----------------------------------------------------------------------------
__global__ __launch_bounds__(256)
void splitx_kernel(const float* __restrict__ X, __half* __restrict__ H,
                   __half* __restrict__ L, int n4)
{
    int i = blockIdx.x * 256 + threadIdx.x;
    if (i < n4) split_store4(((const float4*)X)[i], H, L, (size_t)i * 4);
}

// ----------------------------------------------------------------------------
// fused weight prep (head weights hi-only now)
// ----------------------------------------------------------------------------
__global__ __launch_bounds__(256)
void prep_kernel(const float* __restrict__ W_t1, const float* __restrict__ W_t2,
                 const float* __restrict__ Wa1, const float* __restrict__ Wc1,
                 const float* __restrict__ Wa2,
                 const float* __restrict__ Wih, const float* __restrict__ Whh,
                 const float* __restrict__ bih, const float* __restrict__ bhh)
{
    const int i = blockIdx.x * 256 + threadIdx.x;
    const int sec = blockIdx.y;
    switch (sec) {
    case 0: if (i < LH * DI / 4) split_store4(((const float4*)W_t1)[i], g_wt1_hi, g_wt1_lo, (size_t)i * 4); break;
    case 1: if (i < LH * LH / 4) split_store4(((const float4*)W_t2)[i], g_wt2_hi, g_wt2_lo, (size_t)i * 4); break;
    case 2: if (i < LH * LH / 4) hi_store4(((const float4*)Wa1)[i], g_wa1_hi, (size_t)i * 4); break;
    case 3: if (i < LH * LH / 4) hi_store4(((const float4*)Wc1)[i], g_wc1_hi, (size_t)i * 4); break;
    case 4:
        if (i < NAP * LH / 4) {
            if (i < NA * LH / 4) hi_store4(((const float4*)Wa2)[i], g_wa2_hi, (size_t)i * 4);
            else {
                __half2 z = __floats2half2_rn(0.f, 0.f);
                *(__half2*)&g_wa2_hi[(size_t)i * 4] = z; *(__half2*)&g_wa2_hi[(size_t)i * 4 + 2] = z;
            }
        }
        break;
    case 5:
        if (i < NG * LH / 4) {
            int row = i >> 7, c4 = i & 127;
            float4 v = ((const float4*)(Wih + (size_t)perm_orig(row) * LH))[c4];
            split_store4(v, g_wihp_hi, g_wihp_lo, (size_t)i * 4);
        }
        break;
    case 6:
        if (i < NG * LH / 4) {
            int row = i >> 7, c4 = i & 127;
            float4 v = ((const float4*)(Whh + (size_t)perm_orig(row) * LH))[c4];
            split_store4(v, g_whhp_hi, g_whhp_lo, (size_t)i * 4);
        }
        break;
    case 7:
        if (i < NG) { int o = perm_orig(i); g_biasp[i] = bih[o] + bhh[o]; }
        break;
    }
}

// ----------------------------------------------------------------------------
__global__ __launch_bounds__(256)
void init_state_kernel(const float* __restrict__ h0, const float* __restrict__ c0,
                       const int* __restrict__ done0,
                       __half* __restrict__ hhi, __half* __restrict__ hlo,
                       float* __restrict__ c)
{
    int idx = blockIdx.x * 256 + threadIdx.x;
    if (blockIdx.x == 0 && threadIdx.x < 8) g_bar[threadIdx.x] = 0u;
    if (idx < BB * LH) {
        float m = 1.0f - (float)done0[idx >> 9];
        float hv = h0[idx] * m;
        __half hh = __float2half_rn(hv);
        hhi[idx] = hh;
        hlo[idx] = __float2half_rn(hv - __half2float(hh));
        c[idx] = c0[idx] * m;
    }
}

// ----------------------------------------------------------------------------
// HMMA fp16-split GEMM.
// MODE 0: linear -> C (+Chi/Clo if nonnull)
// MODE 1: tanh   -> C if nonnull (+Chi/Clo if nonnull)
// MODE 2: softmax-partial: fp16 logits (stride NAP) + per-tile (m,s,t) partials
// FULLB: true = 3-product (B split), false = 2-product (Bhi only)
// ----------------------------------------------------------------------------
#define ARR_BYTES 10240u
#define BUF_BYTES 40960u
#define G_SMEM 81920

template<int MODE, bool FULLB>
__global__ __launch_bounds__(256, 2)
void gemm16_kernel(const __half* __restrict__ Ahi, const __half* __restrict__ Alo,
                   const __half* __restrict__ Bhi, const __half* __restrict__ Blo,
                   const float* __restrict__ b1,
                   float* __restrict__ C, __half* __restrict__ Chi, __half* __restrict__ Clo,
                   __half* __restrict__ C16, float4* __restrict__ part,
                   int M, int N, int K)
{
    extern __shared__ __align__(16) char smem[];
    const uint32_t sb = smem_u32(smem);
    const int tid = threadIdx.x;
    const int lane = tid & 31, wid = tid >> 5;
    const int m0 = blockIdx.y * 128, n0 = blockIdx.x * 128;
    const int wm = (wid >> 2) * 64, wn = (wid & 3) * 32;

    float acc[4][4][4];
#pragma unroll
    for (int a = 0; a < 4; a++)
#pragma unroll
        for (int b = 0; b < 4; b++)
#pragma unroll
            for (int c = 0; c < 4; c++) acc[a][b][c] = 0.0f;

    const int NCH = K >> 5;

    auto issue_chunk = [&](int c) {
        const uint32_t bufb = (uint32_t)(c & 1) * BUF_BYTES;
        const int k0 = c * 32;
#pragma unroll
        for (int i = 0; i < 8; i++) {
            int p = tid + i * 256;
            int arr = p >> 9;
            if (!FULLB && arr == 3) continue;
            int q = p & 511;
            int r = q >> 2;
            int ch = (q & 3) * 8;
            int grow = (arr < 2 ? m0 : n0) + r;
            const __half* src =
                (arr == 0 ? Ahi : arr == 1 ? Alo : arr == 2 ? Bhi : Blo)
                + (size_t)grow * K + k0 + ch;
            uint32_t dst = sb + bufb + (uint32_t)arr * ARR_BYTES
                         + (uint32_t)r * 80u + (uint32_t)ch * 2u;
            cp16(dst, src);
        }
        CP_COMMIT();
    };

    issue_chunk(0);

    for (int c = 0; c < NCH; c++) {
        if (c + 1 < NCH) { issue_chunk(c + 1); CP_WAIT1(); }
        else             { CP_WAIT0(); }
        __syncthreads();

        const uint32_t abase = sb + (uint32_t)(c & 1) * BUF_BYTES;
#pragma unroll
        for (int ks = 0; ks < 2; ks++) {
            const uint32_t kcol = (uint32_t)(ks * 16 + (lane >> 4) * 8) * 2u;
            uint32_t bh[4][2], bl[4][2];
#pragma unroll
            for (int ng = 0; ng < 2; ng++) {
                uint32_t row = (uint32_t)(wn + ng * 16 + ((lane >> 3) & 1) * 8 + (lane & 7));
                uint32_t addr = abase + 2u * ARR_BYTES + row * 80u + kcol;
                uint32_t r4[4];
                ldsm_x4(r4, addr);
                bh[ng * 2 + 0][0] = r4[0]; bh[ng * 2 + 0][1] = r4[2];
                bh[ng * 2 + 1][0] = r4[1]; bh[ng * 2 + 1][1] = r4[3];
                if (FULLB) {
                    ldsm_x4(r4, addr + ARR_BYTES);
                    bl[ng * 2 + 0][0] = r4[0]; bl[ng * 2 + 0][1] = r4[2];
                    bl[ng * 2 + 1][0] = r4[1]; bl[ng * 2 + 1][1] = r4[3];
                }
            }
#pragma unroll
            for (int mi = 0; mi < 4; mi++) {
                uint32_t aaddr = abase + (uint32_t)(wm + mi * 16 + (lane & 15)) * 80u + kcol;
                uint32_t ah[4], al[4];
                ldsm_x4(ah, aaddr);
                ldsm_x4(al, aaddr + ARR_BYTES);
#pragma unroll
                for (int ni = 0; ni < 4; ni++) {
                    mma16816(acc[mi][ni], ah, bh[ni][0], bh[ni][1]);
                    if (FULLB) mma16816(acc[mi][ni], ah, bl[ni][0], bl[ni][1]);
                    mma16816(acc[mi][ni], al, bh[ni][0], bh[ni][1]);
                }
            }
        }
        __syncthreads();
    }

    if (MODE == 2) {
        // stage (acc + bias) to smem; per-row partial (max, sum e, sum e*l); fp16 store
        __syncthreads();
        float* st = (float*)smem;                     // 128 x 132
        float3* pr = (float3*)(smem + 128 * 132 * 4); // 256 partials
#pragma unroll
        for (int ni = 0; ni < 4; ni++) {
            int col = n0 + wn + ni * 8 + (lane & 3) * 2;
            int jc = wn + ni * 8 + (lane & 3) * 2;
            if (col >= N) continue;
            float bb0 = b1[col], bb1 = b1[col + 1];
#pragma unroll
            for (int mi = 0; mi < 4; mi++) {
                int rloc = wm + mi * 16 + (lane >> 2);
#pragma unroll
                for (int h = 0; h < 2; h++) {
                    st[(rloc + h * 8) * 132 + jc]     = acc[mi][ni][h * 2 + 0] + bb0;
                    st[(rloc + h * 8) * 132 + jc + 1] = acc[mi][ni][h * 2 + 1] + bb1;
                }
            }
        }
        __syncthreads();
        {
            int rloc = tid >> 1;
            int half = tid & 1;
            float m = -3.402823e38f, s = 0.f, t = 0.f;
#pragma unroll 4
            for (int j = 0; j < 64; j++) {
                int jc = half * 64 + j;
                if (n0 + jc < N) m = fmaxf(m, st[rloc * 132 + jc]);
            }
#pragma unroll 4
            for (int j = 0; j < 64; j++) {
                int jc = half * 64 + j;
                if (n0 + jc < N) {
                    float l = st[rloc * 132 + jc];
                    float e = expf(l - m);
                    s += e; t += e * l;
                }
            }
            pr[tid] = make_float3(m, s, t);
        }
        __syncthreads();
        if (tid < 128) {
            float3 a = pr[tid * 2], b = pr[tid * 2 + 1];
            float m = fmaxf(a.x, b.x);
            float ea = expf(a.x - m), eb = expf(b.x - m);
            part[(size_t)(m0 + tid) * 8 + blockIdx.x] =
                make_float4(m, a.y * ea + b.y * eb, a.z * ea + b.z * eb, 0.f);
        }
        // fp16 logits (stride NAP) for action gather
        for (int i = tid; i < 128 * 64; i += 256) {
            int rloc = i >> 6;
            int j2 = (i & 63) * 2;
            int col = n0 + j2;
            if (col < N) {
                __half2 hv = __floats2half2_rn(st[rloc * 132 + j2],
                                               (col + 1 < N) ? st[rloc * 132 + j2 + 1] : 0.f);
                *(__half2*)&C16[(size_t)(m0 + rloc) * NAP + col] = hv;
            }
        }
        return;
    }

    // MODE 0/1 epilogue
#pragma unroll
    for (int ni = 0; ni < 4; ni++) {
        int col = n0 + wn + ni * 8 + (lane & 3) * 2;
        if (col >= N) continue;
        float bb0 = b1[col], bb1 = b1[col + 1];
#pragma unroll
        for (int mi = 0; mi < 4; mi++) {
            int r0 = m0 + wm + mi * 16 + (lane >> 2);
#pragma unroll
            for (int h = 0; h < 2; h++) {
                int rr = r0 + h * 8;
                float v0 = acc[mi][ni][h * 2 + 0] + bb0;
                float v1 = acc[mi][ni][h * 2 + 1] + bb1;
                if (MODE == 1) { v0 = tanhf(v0); v1 = tanhf(v1); }
                size_t base = (size_t)rr * N + col;
                if (C) *(float2*)&C[base] = make_float2(v0, v1);
                if (Chi) {
                    __half2 hh = __floats2half2_rn(v0, v1);
                    float2 hf = __half22float2(hh);
                    __half2 ll = __floats2half2_rn(v0 - hf.x, v1 - hf.y);
                    *(__half2*)&Chi[base] = hh;
                    *(__half2*)&Clo[base] = ll;
                }
            }
        }
    }
}

// ----------------------------------------------------------------------------
// PERSISTENT tensorized LSTM scan (3-product kept: errors compound here).
// ----------------------------------------------------------------------------
#define S_AH(b)  ((uint32_t)(b) * 2560u)
#define S_AL(b)  (5120u + (uint32_t)(b) * 2560u)
#define S_BH(b)  (10240u + (uint32_t)(b) * 10240u)
#define S_BL(b)  (30720u + (uint32_t)(b) * 10240u)
#define S_GSM    51200u
#define LSTM_SMEM 68608

__global__ __launch_bounds__(256, 1)
void lstm_persist(const __half* __restrict__ Wh, const __half* __restrict__ Wl,
                  const float* __restrict__ xg,
                  const int*   __restrict__ done,
                  __half* __restrict__ hmhi, __half* __restrict__ hmlo,
                  float* __restrict__ c_buf,
                  const float* __restrict__ h2,
                  __half* __restrict__ nhhi, __half* __restrict__ nhlo,
                  int T)
{
    extern __shared__ __align__(16) char smem[];
    const uint32_t sb = smem_u32(smem);
    float* gsm = (float*)(smem + S_GSM);

    const int tid = threadIdx.x;
    const int lane = tid & 31, wid = tid >> 5;
    const int n0 = blockIdx.x * 128;
    const int lbase = blockIdx.x * 32;
    const int r0 = blockIdx.y * 32;
    const int rb = blockIdx.y;
    const int wm16 = (wid & 1) * 16, wn32 = (wid >> 1) * 32;

    for (int t = 0; t < T; t++) {
        if (t > 0) {
            if (tid == 0) {
                unsigned int need = (unsigned int)(16 * t);
                while (atomicAdd(&g_bar[rb], 0u) < need) { __nanosleep(100); }
            }
            __syncthreads();
            __threadfence();
        }

        const __half* hhi_in = hmhi + (size_t)(t & 1) * BB * LH;
        const __half* hlo_in = hmlo + (size_t)(t & 1) * BB * LH;
        const float* xg_t = xg + (size_t)t * BB * NG;
        const float* h2_t = h2 + (size_t)t * BB * LH;

        float acc[4][4];
#pragma unroll
        for (int a = 0; a < 4; a++)
#pragma unroll
            for (int b = 0; b < 4; b++) acc[a][b] = 0.0f;

        auto load_chunk = [&](int c) {
            const int b = c & 1;
            const int k0 = c * 32;
#pragma unroll
            for (int i = 0; i < 5; i++) {
                int p = tid + i * 256;
                if (p < 256) {
                    int hl = p >> 7, q = p & 127, row = q >> 2, c4 = q & 3;
                    const __half* src = (hl ? hlo_in : hhi_in) + (size_t)(r0 + row) * LH + k0 + c4 * 8;
                    uint32_t dst = sb + (hl ? S_AL(b) : S_AH(b)) + (uint32_t)row * 80u + (uint32_t)c4 * 16u;
                    cp16(dst, src);
                } else {
                    int pb = p - 256;
                    int hl = pb >> 9, q = pb & 511, row = q >> 2, c4 = q & 3;
                    const __half* src = (hl ? Wl : Wh) + (size_t)(n0 + row) * LH + k0 + c4 * 8;
                    uint32_t dst = sb + (hl ? S_BL(b) : S_BH(b)) + (uint32_t)row * 80u + (uint32_t)c4 * 16u;
                    cp16(dst, src);
                }
            }
            CP_COMMIT();
        };

        load_chunk(0);
        for (int c = 0; c < 16; c++) {
            if (c + 1 < 16) { load_chunk(c + 1); CP_WAIT1(); }
            else            { CP_WAIT0(); }
            __syncthreads();
            const int b = c & 1;
#pragma unroll
            for (int ks = 0; ks < 2; ks++) {
                const uint32_t kcol = (uint32_t)(ks * 16 + (lane >> 4) * 8) * 2u;
                uint32_t bh[4][2], bl[4][2];
#pragma unroll
                for (int ng = 0; ng < 2; ng++) {
                    uint32_t row = (uint32_t)(wn32 + ng * 16 + ((lane >> 3) & 1) * 8 + (lane & 7));
                    uint32_t addr = sb + S_BH(b) + row * 80u + kcol;
                    uint32_t r4[4];
                    ldsm_x4(r4, addr);
                    bh[ng * 2 + 0][0] = r4[0]; bh[ng * 2 + 0][1] = r4[2];
                    bh[ng * 2 + 1][0] = r4[1]; bh[ng * 2 + 1][1] = r4[3];
                    ldsm_x4(r4, addr + 20480u);
                    bl[ng * 2 + 0][0] = r4[0]; bl[ng * 2 + 0][1] = r4[2];
                    bl[ng * 2 + 1][0] = r4[1]; bl[ng * 2 + 1][1] = r4[3];
                }
                uint32_t aaddr = sb + S_AH(b) + (uint32_t)(wm16 + (lane & 15)) * 80u + kcol;
                uint32_t ah[4], al[4];
                ldsm_x4(ah, aaddr);
                ldsm_x4(al, aaddr + 5120u);
#pragma unroll
                for (int ni = 0; ni < 4; ni++) {
                    mma16816(acc[ni], ah, bh[ni][0], bh[ni][1]);
                    mma16816(acc[ni], ah, bl[ni][0], bl[ni][1]);
                    mma16816(acc[ni], al, bh[ni][0], bh[ni][1]);
                }
            }
            __syncthreads();
        }

#pragma unroll
        for (int ni = 0; ni < 4; ni++) {
            int col = wn32 + ni * 8 + (lane & 3) * 2;
            int row0 = wm16 + (lane >> 2);
            const float* xr0 = xg_t + (size_t)(r0 + row0) * NG + n0 + col;
            gsm[row0 * 132 + col]     = acc[ni][0] + xr0[0];
            gsm[row0 * 132 + col + 1] = acc[ni][1] + xr0[1];
            const float* xr1 = xr0 + 8 * NG;
            gsm[(row0 + 8) * 132 + col]     = acc[ni][2] + xr1[0];
            gsm[(row0 + 8) * 132 + col + 1] = acc[ni][3] + xr1[1];
        }
        __syncthreads();

        __half* hhi_out = hmhi + (size_t)((t + 1) & 1) * BB * LH;
        __half* hlo_out = hmlo + (size_t)((t + 1) & 1) * BB * LH;
        __half* nhhi_t = nhhi + (size_t)t * BB * LH;
        __half* nhlo_t = nhlo + (size_t)t * BB * LH;
        const int* done_next = (t + 1 < T) ? (done + (size_t)(t + 1) * BB) : nullptr;

        // critical path: compute cell, publish h/c; nh deferred past barrier-arrive
        float hn_s[4];
#pragma unroll
        for (int q = 0; q < 4; q++) {
            int cell = tid + q * 256;
            int r = cell >> 5;
            int li = cell & 31;
            float iv = gsm[r * 132 + li];
            float fv = gsm[r * 132 + 32 + li];
            float gv = gsm[r * 132 + 64 + li];
            float ov = gsm[r * 132 + 96 + li];
            size_t gi = (size_t)(r0 + r) * LH + lbase + li;
            float cp = c_buf[gi];
            float cn = sigm(fv) * cp + sigm(iv) * tanhf(gv);
            float hn = sigm(ov) * tanhf(cn);
            hn_s[q] = hn;
            float mn = done_next ? (1.0f - (float)done_next[r0 + r]) : 1.0f;
            c_buf[gi] = cn * mn;
            float hm = hn * mn;
            __half hmh = __float2half_rn(hm);
            hhi_out[gi] = hmh;
            hlo_out[gi] = __float2half_rn(hm - __half2float(hmh));
        }
        __threadfence();
        __syncthreads();
        if (tid == 0) atomicAdd(&g_bar[rb], 1u);

        // deferred: nh = hn + h2 (not consumed by the scan)
#pragma unroll
        for (int q = 0; q < 4; q++) {
            int cell = tid + q * 256;
            int r = cell >> 5;
            int li = cell & 31;
            size_t gi = (size_t)(r0 + r) * LH + lbase + li;
            float nhv = hn_s[q] + h2_t[gi];
            __half nhh = __float2half_rn(nhv);
            nhhi_t[gi] = nhh;
            nhlo_t[gi] = __float2half_rn(nhv - __half2float(nhh));
        }
    }
}

// ----------------------------------------------------------------------------
// combine softmax partials: lp, ent per row
// ----------------------------------------------------------------------------
__global__ __launch_bounds__(256)
void softmax2_kernel(const float4* __restrict__ part, const __half* __restrict__ l16,
                     const int* __restrict__ action, float* __restrict__ out, int TBn)
{
    int row = blockIdx.x * 256 + threadIdx.x;
    if (row >= TBn) return;
    float4 p[8];
#pragma unroll
    for (int i = 0; i < 8; i++) p[i] = part[(size_t)row * 8 + i];
    float M = p[0].x;
#pragma unroll
    for (int i = 1; i < 8; i++) M = fmaxf(M, p[i].x);
    float S = 0.f, Tm = 0.f;
#pragma unroll
    for (int i = 0; i < 8; i++) {
        float e = expf(p[i].x - M);
        S += p[i].y * e;
        Tm += p[i].z * e;
    }
    float lse = M + logf(S);
    float la = __half2float(l16[(size_t)row * NAP + action[row]]);
    out[row] = la - lse;
    out[TBn + row] = lse - Tm / S;
}

// ----------------------------------------------------------------------------
__global__ __launch_bounds__(256)
void critic_kernel(const float* __restrict__ ch, const float* __restrict__ Wc2,
                   const float* __restrict__ bc2, float* __restrict__ vout)
{
    __shared__ float wsh[LH];
    const int tid = threadIdx.x;
    for (int j = tid; j < LH; j += 256) wsh[j] = Wc2[j];
    __syncthreads();
    const int warp = tid >> 5, lane = tid & 31;
    const int row = blockIdx.x * 8 + warp;
    const float* r = ch + (size_t)row * LH;
    float s = 0.f;
    for (int k = lane; k < LH; k += 32) s += r[k] * wsh[k];
#pragma unroll
    for (int off = 16; off > 0; off >>= 1) s += __shfl_down_sync(0xFFFFFFFFu, s, off);
    if (lane == 0) vout[row] = s + bc2[0];
}

// ----------------------------------------------------------------------------
// host launcher
// ----------------------------------------------------------------------------
extern "C" void kernel_launch(void* const* d_in, const int* in_sizes, int n_in,
                              void* d_out, int out_size)
{
    const float* x    = (const float*)d_in[0];
    const int*   done = (const int*)d_in[1];
    const int*   act  = (const int*)d_in[2];
    const float* W_t1 = (const float*)d_in[4];
    const float* b_t1 = (const float*)d_in[5];
    const float* W_t2 = (const float*)d_in[6];
    const float* b_t2 = (const float*)d_in[7];
    const float* Wih  = (const float*)d_in[8];
    const float* Whh  = (const float*)d_in[9];
    const float* bih  = (const float*)d_in[10];
    const float* bhh  = (const float*)d_in[11];
    const float* Wa1  = (const float*)d_in[12];
    const float* ba1  = (const float*)d_in[13];
    const float* Wa2  = (const float*)d_in[14];
    const float* ba2  = (const float*)d_in[15];
    const float* Wc1  = (const float*)d_in[16];
    const float* bc1  = (const float*)d_in[17];
    const float* Wc2  = (const float*)d_in[18];
    const float* bc2  = (const float*)d_in[19];
    const float* h0   = (const float*)d_in[20];
    const float* c0   = (const float*)d_in[21];

    const int TBn = in_sizes[0] / DI;   // 65536
    const int T = TBn / BB;             // 256
    float* out = (float*)d_out;

    float *buf1, *h2, *xg, *cbuf, *biasp;
    float4* part;
    __half* l16;
    cudaGetSymbolAddress((void**)&buf1,  g_buf1);
    cudaGetSymbolAddress((void**)&h2,    g_h2);
    cudaGetSymbolAddress((void**)&xg,    g_xg);
    cudaGetSymbolAddress((void**)&cbuf,  g_cbuf);
    cudaGetSymbolAddress((void**)&biasp, g_biasp);
    cudaGetSymbolAddress((void**)&part,  g_part);
    cudaGetSymbolAddress((void**)&l16,   g_l16);

    __half *xhi, *xlo, *b1hi, *b1lo, *h2hi, *h2lo, *nhhi, *nhlo, *hmhi, *hmlo;
    __half *wt1h, *wt1l, *wt2h, *wt2l, *wihh, *wihl, *whhh, *whhl;
    __half *wa1h, *wa2h, *wc1h;
    cudaGetSymbolAddress((void**)&xhi,  g_x_hi);   cudaGetSymbolAddress((void**)&xlo,  g_x_lo);
    cudaGetSymbolAddress((void**)&b1hi, g_b1_hi);  cudaGetSymbolAddress((void**)&b1lo, g_b1_lo);
    cudaGetSymbolAddress((void**)&h2hi, g_h2_hi);  cudaGetSymbolAddress((void**)&h2lo, g_h2_lo);
    cudaGetSymbolAddress((void**)&nhhi, g_nh_hi);  cudaGetSymbolAddress((void**)&nhlo, g_nh_lo);
    cudaGetSymbolAddress((void**)&hmhi, g_hm_hi);  cudaGetSymbolAddress((void**)&hmlo, g_hm_lo);
    cudaGetSymbolAddress((void**)&wt1h, g_wt1_hi); cudaGetSymbolAddress((void**)&wt1l, g_wt1_lo);
    cudaGetSymbolAddress((void**)&wt2h, g_wt2_hi); cudaGetSymbolAddress((void**)&wt2l, g_wt2_lo);
    cudaGetSymbolAddress((void**)&wihh, g_wihp_hi); cudaGetSymbolAddress((void**)&wihl, g_wihp_lo);
    cudaGetSymbolAddress((void**)&whhh, g_whhp_hi); cudaGetSymbolAddress((void**)&whhl, g_whhp_lo);
    cudaGetSymbolAddress((void**)&wa1h, g_wa1_hi);
    cudaGetSymbolAddress((void**)&wa2h, g_wa2_hi);
    cudaGetSymbolAddress((void**)&wc1h, g_wc1_hi);

    cudaFuncSetAttribute(gemm16_kernel<0, true>,  cudaFuncAttributeMaxDynamicSharedMemorySize, G_SMEM);
    cudaFuncSetAttribute(gemm16_kernel<1, true>,  cudaFuncAttributeMaxDynamicSharedMemorySize, G_SMEM);
    cudaFuncSetAttribute(gemm16_kernel<1, false>, cudaFuncAttributeMaxDynamicSharedMemorySize, G_SMEM);
    cudaFuncSetAttribute(gemm16_kernel<2, false>, cudaFuncAttributeMaxDynamicSharedMemorySize, G_SMEM);
    cudaFuncSetAttribute(lstm_persist, cudaFuncAttributeMaxDynamicSharedMemorySize, LSTM_SMEM);

    const dim3 blk(256);

    splitx_kernel<<<TBn * DI / 4 / 256, blk>>>(x, xhi, xlo, TBn * DI / 4);
    prep_kernel<<<dim3(1024, 8), blk>>>(W_t1, W_t2, Wa1, Wc1, Wa2, Wih, Whh, bih, bhh);
    init_state_kernel<<<(BB * LH + 255) / 256, blk>>>(h0, c0, done, hmhi, hmlo, cbuf);

    const int MY = TBn / 128;
    // trunk (3-product; feeds recurrence)
    gemm16_kernel<1, true><<<dim3(4, MY), blk, G_SMEM>>>(
        xhi, xlo, wt1h, wt1l, b_t1, nullptr, b1hi, b1lo, nullptr, nullptr, TBn, LH, DI);
    gemm16_kernel<1, true><<<dim3(4, MY), blk, G_SMEM>>>(
        b1hi, b1lo, wt2h, wt2l, b_t2, h2, h2hi, h2lo, nullptr, nullptr, TBn, LH, LH);
    gemm16_kernel<0, true><<<dim3(16, MY), blk, G_SMEM>>>(
        h2hi, h2lo, wihh, wihl, biasp, xg, nullptr, nullptr, nullptr, nullptr, TBn, NG, LH);

    // persistent lstm scan
    lstm_persist<<<dim3(16, 8), blk, LSTM_SMEM>>>(
        whhh, whhl, xg, done, hmhi, hmlo, cbuf, h2, nhhi, nhlo, T);

    // actor head (2-product) + fused softmax partials
    gemm16_kernel<1, false><<<dim3(4, MY), blk, G_SMEM>>>(
        nhhi, nhlo, wa1h, nullptr, ba1, nullptr, b1hi, b1lo, nullptr, nullptr, TBn, LH, LH);
    gemm16_kernel<2, false><<<dim3(8, MY), blk, G_SMEM>>>(
        b1hi, b1lo, wa2h, nullptr, ba2, nullptr, nullptr, nullptr, l16, part, TBn, NA, LH);
    softmax2_kernel<<<(TBn + 255) / 256, blk>>>(part, l16, act, out, TBn);

    // critic head (2-product)
    gemm16_kernel<1, false><<<dim3(4, MY), blk, G_SMEM>>>(
        nhhi, nhlo, wc1h, nullptr, bc1, buf1, nullptr, nullptr, nullptr, nullptr, TBn, LH, LH);
    critic_kernel<<<TBn / 8, blk>>>(buf1, Wc2, bc2, out + (size_t)2 * TBn);
}

// round 11
// speedup vs baseline: 3.1698x; 1.3808x over previous
#include <cuda_runtime.h>
#include <cuda_fp16.h>
#include <math.h>
#include <stdint.h>

// ----------------------------------------------------------------------------
// Problem constants
// ----------------------------------------------------------------------------
#define LH 512
#define DI 512
#define NA 1000
#define NAP 1024
#define NG 2048
#define BB 256
#define TBMAX 65536

// ----------------------------------------------------------------------------
// PTX helpers (base-target-safe)
// ----------------------------------------------------------------------------
__device__ __forceinline__ uint32_t smem_u32(const void* p) {
    uint32_t a;
    asm("{ .reg .u64 t; cvta.to.shared.u64 t, %1; cvt.u32.u64 %0, t; }" : "=r"(a) : "l"(p));
    return a;
}
__device__ __forceinline__ void ldsm_x4(uint32_t (&r)[4], uint32_t addr) {
    asm volatile("ldmatrix.sync.aligned.m8n8.x4.shared.b16 {%0,%1,%2,%3}, [%4];"
                 : "=r"(r[0]), "=r"(r[1]), "=r"(r[2]), "=r"(r[3]) : "r"(addr));
}
__device__ __forceinline__ void mma16816(float (&d)[4], const uint32_t (&a)[4],
                                         uint32_t b0, uint32_t b1) {
    asm volatile(
        "mma.sync.aligned.m16n8k16.row.col.f32.f16.f16.f32 "
        "{%0,%1,%2,%3},{%4,%5,%6,%7},{%8,%9},{%0,%1,%2,%3};"
        : "+f"(d[0]), "+f"(d[1]), "+f"(d[2]), "+f"(d[3])
        : "r"(a[0]), "r"(a[1]), "r"(a[2]), "r"(a[3]), "r"(b0), "r"(b1));
}
__device__ __forceinline__ void cp16(uint32_t dst, const void* src) {
    asm volatile("cp.async.cg.shared.global [%0], [%1], 16;" :: "r"(dst), "l"(src) : "memory");
}
#define CP_COMMIT() asm volatile("cp.async.commit_group;" ::: "memory")
#define CP_WAIT1()  asm volatile("cp.async.wait_group 1;" ::: "memory")
#define CP_WAIT0()  asm volatile("cp.async.wait_group 0;" ::: "memory")

__host__ __device__ __forceinline__ int perm_orig(int p) {
    return (((p & 127) >> 5) << 9) + ((p >> 7) << 5) + (p & 31);
}

// ----------------------------------------------------------------------------
// Scratch
// ----------------------------------------------------------------------------
__device__ __align__(16) float4 g_partc[(size_t)TBMAX * 4];     // critic partials (FIX: float4, was float)
__device__ float g_h2  [(size_t)TBMAX * LH];
__device__ float g_xg  [(size_t)TBMAX * NG];
__device__ float g_cbuf[BB * LH];
__device__ float g_biasp[NG];
__device__ unsigned int g_bar[8];
__device__ __align__(16) float4 g_part[(size_t)TBMAX * 8];      // softmax partials
__device__ __align__(16) __half g_l16[(size_t)TBMAX * NAP];     // fp16 logits

__device__ __align__(16) __half g_x_hi [(size_t)TBMAX * DI], g_x_lo [(size_t)TBMAX * DI];
__device__ __align__(16) __half g_b1_hi[(size_t)TBMAX * LH], g_b1_lo[(size_t)TBMAX * LH];
__device__ __align__(16) __half g_h2_hi[(size_t)TBMAX * LH], g_h2_lo[(size_t)TBMAX * LH];
__device__ __align__(16) __half g_nh_hi[(size_t)TBMAX * LH], g_nh_lo[(size_t)TBMAX * LH];
__device__ __align__(16) __half g_hm_hi[2 * BB * LH], g_hm_lo[2 * BB * LH];
__device__ __align__(16) __half g_wt1_hi[LH * DI];
__device__ __align__(16) __half g_wt2_hi[LH * LH];
__device__ __align__(16) __half g_wihp_hi[NG * LH];
__device__ __align__(16) __half g_whhp_hi[NG * LH];
__device__ __align__(16) __half g_wa1_hi[LH * LH];
__device__ __align__(16) __half g_wa2_hi[NAP * LH];
__device__ __align__(16) __half g_wc1_hi[LH * LH];

__device__ __forceinline__ float sigm(float x) { return 1.0f / (1.0f + expf(-x)); }

__device__ __forceinline__ void split_store4(float4 v, __half* H, __half* L, size_t idx) {
    __half2 a = __floats2half2_rn(v.x, v.y);
    __half2 b = __floats2half2_rn(v.z, v.w);
    float2 af = __half22float2(a), bf = __half22float2(b);
    __half2 al = __floats2half2_rn(v.x - af.x, v.y - af.y);
    __half2 bl = __floats2half2_rn(v.z - bf.x, v.w - bf.y);
    *(__half2*)&H[idx] = a;  *(__half2*)&H[idx + 2] = b;
    *(__half2*)&L[idx] = al; *(__half2*)&L[idx + 2] = bl;
}
__device__ __forceinline__ void hi_store4(float4 v, __half* H, size_t idx) {
    *(__half2*)&H[idx] = __floats2half2_rn(v.x, v.y);
    *(__half2*)&H[idx + 2] = __floats2half2_rn(v.z, v.w);
}

// ----------------------------------------------------------------------------
__global__ __launch_bounds__(256)
void splitx_kernel(const float* __restrict__ X, __half* __restrict__ H,
                   __half* __restrict__ L, int n4)
{
    int i = blockIdx.x * 256 + threadIdx.x;
    if (i < n4) split_store4(((const float4*)X)[i], H, L, (size_t)i * 4);
}

// ----------------------------------------------------------------------------
// weight prep: all weights hi-only (2-product GEMMs); permutation for Wih/Whh
// ----------------------------------------------------------------------------
__global__ __launch_bounds__(256)
void prep_kernel(const float* __restrict__ W_t1, const float* __restrict__ W_t2,
                 const float* __restrict__ Wa1, const float* __restrict__ Wc1,
                 const float* __restrict__ Wa2,
                 const float* __restrict__ Wih, const float* __restrict__ Whh,
                 const float* __restrict__ bih, const float* __restrict__ bhh)
{
    const int i = blockIdx.x * 256 + threadIdx.x;
    const int sec = blockIdx.y;
    switch (sec) {
    case 0: if (i < LH * DI / 4) hi_store4(((const float4*)W_t1)[i], g_wt1_hi, (size_t)i * 4); break;
    case 1: if (i < LH * LH / 4) hi_store4(((const float4*)W_t2)[i], g_wt2_hi, (size_t)i * 4); break;
    case 2: if (i < LH * LH / 4) hi_store4(((const float4*)Wa1)[i], g_wa1_hi, (size_t)i * 4); break;
    case 3: if (i < LH * LH / 4) hi_store4(((const float4*)Wc1)[i], g_wc1_hi, (size_t)i * 4); break;
    case 4:
        if (i < NAP * LH / 4) {
            if (i < NA * LH / 4) hi_store4(((const float4*)Wa2)[i], g_wa2_hi, (size_t)i * 4);
            else {
                __half2 z = __floats2half2_rn(0.f, 0.f);
                *(__half2*)&g_wa2_hi[(size_t)i * 4] = z; *(__half2*)&g_wa2_hi[(size_t)i * 4 + 2] = z;
            }
        }
        break;
    case 5:
        if (i < NG * LH / 4) {
            int row = i >> 7, c4 = i & 127;
            hi_store4(((const float4*)(Wih + (size_t)perm_orig(row) * LH))[c4], g_wihp_hi, (size_t)i * 4);
        }
        break;
    case 6:
        if (i < NG * LH / 4) {
            int row = i >> 7, c4 = i & 127;
            hi_store4(((const float4*)(Whh + (size_t)perm_orig(row) * LH))[c4], g_whhp_hi, (size_t)i * 4);
        }
        break;
    case 7:
        if (i < NG) { int o = perm_orig(i); g_biasp[i] = bih[o] + bhh[o]; }
        break;
    }
}

// ----------------------------------------------------------------------------
__global__ __launch_bounds__(256)
void init_state_kernel(const float* __restrict__ h0, const float* __restrict__ c0,
                       const int* __restrict__ done0,
                       __half* __restrict__ hhi, __half* __restrict__ hlo,
                       float* __restrict__ c)
{
    int idx = blockIdx.x * 256 + threadIdx.x;
    if (blockIdx.x == 0 && threadIdx.x < 8) g_bar[threadIdx.x] = 0u;
    if (idx < BB * LH) {
        float m = 1.0f - (float)done0[idx >> 9];
        float hv = h0[idx] * m;
        __half hh = __float2half_rn(hv);
        hhi[idx] = hh;
        hlo[idx] = __float2half_rn(hv - __half2float(hh));
        c[idx] = c0[idx] * m;
    }
}

// ----------------------------------------------------------------------------
// HMMA 2-product GEMM: C = (Ahi+Alo)@Bhi^T + b1
// MODE 0: linear -> C (+Chi/Clo)      MODE 1: tanh -> C/Chi/Clo
// MODE 2: fused softmax partials      MODE 3: fused critic dot partials (w2)
// SMEM per buffer: [Ahi][Alo][Bhi] = 3 x 10240; double buffered.
// ----------------------------------------------------------------------------
#define ARR_BYTES 10240u
#define BUF_BYTES 30720u
#define G_SMEM 70656

template<int MODE>
__global__ __launch_bounds__(256, 2)
void gemm16_kernel(const __half* __restrict__ Ahi, const __half* __restrict__ Alo,
                   const __half* __restrict__ Bhi,
                   const float* __restrict__ b1,
                   float* __restrict__ C, __half* __restrict__ Chi, __half* __restrict__ Clo,
                   __half* __restrict__ C16, float4* __restrict__ part,
                   const float* __restrict__ w2,
                   int M, int N, int K)
{
    extern __shared__ __align__(16) char smem[];
    const uint32_t sb = smem_u32(smem);
    const int tid = threadIdx.x;
    const int lane = tid & 31, wid = tid >> 5;
    const int m0 = blockIdx.y * 128, n0 = blockIdx.x * 128;
    const int wm = (wid >> 2) * 64, wn = (wid & 3) * 32;

    float acc[4][4][4];
#pragma unroll
    for (int a = 0; a < 4; a++)
#pragma unroll
        for (int b = 0; b < 4; b++)
#pragma unroll
            for (int c = 0; c < 4; c++) acc[a][b][c] = 0.0f;

    const int NCH = K >> 5;

    auto issue_chunk = [&](int c) {
        const uint32_t bufb = (uint32_t)(c & 1) * BUF_BYTES;
        const int k0 = c * 32;
#pragma unroll
        for (int i = 0; i < 6; i++) {
            int p = tid + i * 256;
            int arr = p >> 9;
            int q = p & 511;
            int r = q >> 2;
            int ch = (q & 3) * 8;
            int grow = (arr < 2 ? m0 : n0) + r;
            const __half* src = (arr == 0 ? Ahi : arr == 1 ? Alo : Bhi)
                              + (size_t)grow * K + k0 + ch;
            uint32_t dst = sb + bufb + (uint32_t)arr * ARR_BYTES
                         + (uint32_t)r * 80u + (uint32_t)ch * 2u;
            cp16(dst, src);
        }
        CP_COMMIT();
    };

    issue_chunk(0);

    for (int c = 0; c < NCH; c++) {
        if (c + 1 < NCH) { issue_chunk(c + 1); CP_WAIT1(); }
        else             { CP_WAIT0(); }
        __syncthreads();

        const uint32_t abase = sb + (uint32_t)(c & 1) * BUF_BYTES;
#pragma unroll
        for (int ks = 0; ks < 2; ks++) {
            const uint32_t kcol = (uint32_t)(ks * 16 + (lane >> 4) * 8) * 2u;
            uint32_t bh[4][2];
#pragma unroll
            for (int ng = 0; ng < 2; ng++) {
                uint32_t row = (uint32_t)(wn + ng * 16 + ((lane >> 3) & 1) * 8 + (lane & 7));
                uint32_t addr = abase + 2u * ARR_BYTES + row * 80u + kcol;
                uint32_t r4[4];
                ldsm_x4(r4, addr);
                bh[ng * 2 + 0][0] = r4[0]; bh[ng * 2 + 0][1] = r4[2];
                bh[ng * 2 + 1][0] = r4[1]; bh[ng * 2 + 1][1] = r4[3];
            }
#pragma unroll
            for (int mi = 0; mi < 4; mi++) {
                uint32_t aaddr = abase + (uint32_t)(wm + mi * 16 + (lane & 15)) * 80u + kcol;
                uint32_t ah[4], al[4];
                ldsm_x4(ah, aaddr);
                ldsm_x4(al, aaddr + ARR_BYTES);
#pragma unroll
                for (int ni = 0; ni < 4; ni++) {
                    mma16816(acc[mi][ni], ah, bh[ni][0], bh[ni][1]);
                    mma16816(acc[mi][ni], al, bh[ni][0], bh[ni][1]);
                }
            }
        }
        __syncthreads();
    }

    if (MODE == 2) {
        float* st = (float*)smem;                     // 128 x 132 fp32
        float3* pr = (float3*)(smem + 128 * 132 * 4); // 256 partials
#pragma unroll
        for (int ni = 0; ni < 4; ni++) {
            int col = n0 + wn + ni * 8 + (lane & 3) * 2;
            int jc = wn + ni * 8 + (lane & 3) * 2;
            if (col >= N) continue;
            float bb0 = b1[col], bb1 = b1[col + 1];
#pragma unroll
            for (int mi = 0; mi < 4; mi++) {
                int rloc = wm + mi * 16 + (lane >> 2);
#pragma unroll
                for (int h = 0; h < 2; h++) {
                    st[(rloc + h * 8) * 132 + jc]     = acc[mi][ni][h * 2 + 0] + bb0;
                    st[(rloc + h * 8) * 132 + jc + 1] = acc[mi][ni][h * 2 + 1] + bb1;
                }
            }
        }
        __syncthreads();
        {
            int rloc = tid >> 1;
            int half = tid & 1;
            float m = -3.402823e38f, s = 0.f, t = 0.f;
#pragma unroll 4
            for (int j = 0; j < 64; j++) {
                int jc = half * 64 + j;
                if (n0 + jc < N) m = fmaxf(m, st[rloc * 132 + jc]);
            }
#pragma unroll 4
            for (int j = 0; j < 64; j++) {
                int jc = half * 64 + j;
                if (n0 + jc < N) {
                    float l = st[rloc * 132 + jc];
                    float e = expf(l - m);
                    s += e; t += e * l;
                }
            }
            pr[tid] = make_float3(m, s, t);
        }
        __syncthreads();
        if (tid < 128) {
            float3 a = pr[tid * 2], b = pr[tid * 2 + 1];
            float m = fmaxf(a.x, b.x);
            float ea = expf(a.x - m), eb = expf(b.x - m);
            part[(size_t)(m0 + tid) * 8 + blockIdx.x] =
                make_float4(m, a.y * ea + b.y * eb, a.z * ea + b.z * eb, 0.f);
        }
        for (int i = tid; i < 128 * 64; i += 256) {
            int rloc = i >> 6;
            int j2 = (i & 63) * 2;
            int col = n0 + j2;
            if (col < N) {
                __half2 hv = __floats2half2_rn(st[rloc * 132 + j2],
                                               (col + 1 < N) ? st[rloc * 132 + j2 + 1] : 0.f);
                *(__half2*)&C16[(size_t)(m0 + rloc) * NAP + col] = hv;
            }
        }
        return;
    }

    if (MODE == 3) {
        // fused critic: ps[row] = sum_cols tanh(acc+b)*w2[col]; quad shfl-reduce
        float* smp = (float*)smem;  // 128 x 4
        float ps[8];
#pragma unroll
        for (int i = 0; i < 8; i++) ps[i] = 0.f;
#pragma unroll
        for (int ni = 0; ni < 4; ni++) {
            int col = n0 + wn + ni * 8 + (lane & 3) * 2;
            float bb0 = b1[col], bb1 = b1[col + 1];
            float w0 = w2[col], w1 = w2[col + 1];
#pragma unroll
            for (int mi = 0; mi < 4; mi++) {
#pragma unroll
                for (int h = 0; h < 2; h++) {
                    float v0 = tanhf(acc[mi][ni][h * 2 + 0] + bb0);
                    float v1 = tanhf(acc[mi][ni][h * 2 + 1] + bb1);
                    ps[mi * 2 + h] += v0 * w0 + v1 * w1;
                }
            }
        }
#pragma unroll
        for (int i = 0; i < 8; i++) {
            ps[i] += __shfl_xor_sync(0xffffffffu, ps[i], 1);
            ps[i] += __shfl_xor_sync(0xffffffffu, ps[i], 2);
        }
        if ((lane & 3) == 0) {
#pragma unroll
            for (int mi = 0; mi < 4; mi++)
#pragma unroll
                for (int h = 0; h < 2; h++) {
                    int rloc = wm + mi * 16 + (lane >> 2) + h * 8;
                    smp[rloc * 4 + (wid & 3)] = ps[mi * 2 + h];
                }
        }
        __syncthreads();
        if (tid < 128)
            part[(size_t)(m0 + tid) * 4 + blockIdx.x] =
                make_float4(smp[tid * 4], smp[tid * 4 + 1], smp[tid * 4 + 2], smp[tid * 4 + 3]);
        return;
    }

    // MODE 0/1 epilogue
#pragma unroll
    for (int ni = 0; ni < 4; ni++) {
        int col = n0 + wn + ni * 8 + (lane & 3) * 2;
        if (col >= N) continue;
        float bb0 = b1[col], bb1 = b1[col + 1];
#pragma unroll
        for (int mi = 0; mi < 4; mi++) {
            int r0 = m0 + wm + mi * 16 + (lane >> 2);
#pragma unroll
            for (int h = 0; h < 2; h++) {
                int rr = r0 + h * 8;
                float v0 = acc[mi][ni][h * 2 + 0] + bb0;
                float v1 = acc[mi][ni][h * 2 + 1] + bb1;
                if (MODE == 1) { v0 = tanhf(v0); v1 = tanhf(v1); }
                size_t base = (size_t)rr * N + col;
                if (C) *(float2*)&C[base] = make_float2(v0, v1);
                if (Chi) {
                    __half2 hh = __floats2half2_rn(v0, v1);
                    float2 hf = __half22float2(hh);
                    __half2 ll = __floats2half2_rn(v0 - hf.x, v1 - hf.y);
                    *(__half2*)&Chi[base] = hh;
                    *(__half2*)&Clo[base] = ll;
                }
            }
        }
    }
}

// ----------------------------------------------------------------------------
// PERSISTENT tensorized LSTM scan, 2-product (hi*Whi + lo*Whi).
// ----------------------------------------------------------------------------
#define S_AH(b)  ((uint32_t)(b) * 2560u)
#define S_AL(b)  (5120u + (uint32_t)(b) * 2560u)
#define S_BH(b)  (10240u + (uint32_t)(b) * 10240u)
#define S_GSM    30720u
#define LSTM_SMEM 47616

__global__ __launch_bounds__(256, 1)
void lstm_persist(const __half* __restrict__ Wh,
                  const float* __restrict__ xg,
                  const int*   __restrict__ done,
                  __half* __restrict__ hmhi, __half* __restrict__ hmlo,
                  float* __restrict__ c_buf,
                  const float* __restrict__ h2,
                  __half* __restrict__ nhhi, __half* __restrict__ nhlo,
                  int T)
{
    extern __shared__ __align__(16) char smem[];
    const uint32_t sb = smem_u32(smem);
    float* gsm = (float*)(smem + S_GSM);

    const int tid = threadIdx.x;
    const int lane = tid & 31, wid = tid >> 5;
    const int n0 = blockIdx.x * 128;
    const int lbase = blockIdx.x * 32;
    const int r0 = blockIdx.y * 32;
    const int rb = blockIdx.y;
    const int wm16 = (wid & 1) * 16, wn32 = (wid >> 1) * 32;

    for (int t = 0; t < T; t++) {
        if (t > 0) {
            if (tid == 0) {
                unsigned int need = (unsigned int)(16 * t);
                while (atomicAdd(&g_bar[rb], 0u) < need) { __nanosleep(100); }
            }
            __syncthreads();
            __threadfence();
        }

        const __half* hhi_in = hmhi + (size_t)(t & 1) * BB * LH;
        const __half* hlo_in = hmlo + (size_t)(t & 1) * BB * LH;
        const float* xg_t = xg + (size_t)t * BB * NG;
        const float* h2_t = h2 + (size_t)t * BB * LH;

        float acc[4][4];
#pragma unroll
        for (int a = 0; a < 4; a++)
#pragma unroll
            for (int b = 0; b < 4; b++) acc[a][b] = 0.0f;

        auto load_chunk = [&](int c) {
            const int b = c & 1;
            const int k0 = c * 32;
#pragma unroll
            for (int i = 0; i < 3; i++) {
                int p = tid + i * 256;
                if (p < 256) {
                    int hl = p >> 7, q = p & 127, row = q >> 2, c4 = q & 3;
                    const __half* src = (hl ? hlo_in : hhi_in) + (size_t)(r0 + row) * LH + k0 + c4 * 8;
                    uint32_t dst = sb + (hl ? S_AL(b) : S_AH(b)) + (uint32_t)row * 80u + (uint32_t)c4 * 16u;
                    cp16(dst, src);
                } else {
                    int q = p - 256;            // 0..511
                    int row = q >> 2, c4 = q & 3;
                    const __half* src = Wh + (size_t)(n0 + row) * LH + k0 + c4 * 8;
                    uint32_t dst = sb + S_BH(b) + (uint32_t)row * 80u + (uint32_t)c4 * 16u;
                    cp16(dst, src);
                }
            }
            CP_COMMIT();
        };

        load_chunk(0);
        for (int c = 0; c < 16; c++) {
            if (c + 1 < 16) { load_chunk(c + 1); CP_WAIT1(); }
            else            { CP_WAIT0(); }
            __syncthreads();
            const int b = c & 1;
#pragma unroll
            for (int ks = 0; ks < 2; ks++) {
                const uint32_t kcol = (uint32_t)(ks * 16 + (lane >> 4) * 8) * 2u;
                uint32_t bh[4][2];
#pragma unroll
                for (int ng = 0; ng < 2; ng++) {
                    uint32_t row = (uint32_t)(wn32 + ng * 16 + ((lane >> 3) & 1) * 8 + (lane & 7));
                    uint32_t addr = sb + S_BH(b) + row * 80u + kcol;
                    uint32_t r4[4];
                    ldsm_x4(r4, addr);
                    bh[ng * 2 + 0][0] = r4[0]; bh[ng * 2 + 0][1] = r4[2];
                    bh[ng * 2 + 1][0] = r4[1]; bh[ng * 2 + 1][1] = r4[3];
                }
                uint32_t aaddr = sb + S_AH(b) + (uint32_t)(wm16 + (lane & 15)) * 80u + kcol;
                uint32_t ah[4], al[4];
                ldsm_x4(ah, aaddr);
                ldsm_x4(al, aaddr + 5120u);
#pragma unroll
                for (int ni = 0; ni < 4; ni++) {
                    mma16816(acc[ni], ah, bh[ni][0], bh[ni][1]);
                    mma16816(acc[ni], al, bh[ni][0], bh[ni][1]);
                }
            }
            __syncthreads();
        }

#pragma unroll
        for (int ni = 0; ni < 4; ni++) {
            int col = wn32 + ni * 8 + (lane & 3) * 2;
            int row0 = wm16 + (lane >> 2);
            const float* xr0 = xg_t + (size_t)(r0 + row0) * NG + n0 + col;
            gsm[row0 * 132 + col]     = acc[ni][0] + xr0[0];
            gsm[row0 * 132 + col + 1] = acc[ni][1] + xr0[1];
            const float* xr1 = xr0 + 8 * NG;
            gsm[(row0 + 8) * 132 + col]     = acc[ni][2] + xr1[0];
            gsm[(row0 + 8) * 132 + col + 1] = acc[ni][3] + xr1[1];
        }
        __syncthreads();

        __half* hhi_out = hmhi + (size_t)((t + 1) & 1) * BB * LH;
        __half* hlo_out = hmlo + (size_t)((t + 1) & 1) * BB * LH;
        __half* nhhi_t = nhhi + (size_t)t * BB * LH;
        __half* nhlo_t = nhlo + (size_t)t * BB * LH;
        const int* done_next = (t + 1 < T) ? (done + (size_t)(t + 1) * BB) : nullptr;

        float hn_s[4];
#pragma unroll
        for (int q = 0; q < 4; q++) {
            int cell = tid + q * 256;
            int r = cell >> 5;
            int li = cell & 31;
            float iv = gsm[r * 132 + li];
            float fv = gsm[r * 132 + 32 + li];
            float gv = gsm[r * 132 + 64 + li];
            float ov = gsm[r * 132 + 96 + li];
            size_t gi = (size_t)(r0 + r) * LH + lbase + li;
            float cp = c_buf[gi];
            float cn = sigm(fv) * cp + sigm(iv) * tanhf(gv);
            float hn = sigm(ov) * tanhf(cn);
            hn_s[q] = hn;
            float mn = done_next ? (1.0f - (float)done_next[r0 + r]) : 1.0f;
            c_buf[gi] = cn * mn;
            float hm = hn * mn;
            __half hmh = __float2half_rn(hm);
            hhi_out[gi] = hmh;
            hlo_out[gi] = __float2half_rn(hm - __half2float(hmh));
        }
        __threadfence();
        __syncthreads();
        if (tid == 0) atomicAdd(&g_bar[rb], 1u);

#pragma unroll
        for (int q = 0; q < 4; q++) {
            int cell = tid + q * 256;
            int r = cell >> 5;
            int li = cell & 31;
            size_t gi = (size_t)(r0 + r) * LH + lbase + li;
            float nhv = hn_s[q] + h2_t[gi];
            __half nhh = __float2half_rn(nhv);
            nhhi_t[gi] = nhh;
            nhlo_t[gi] = __float2half_rn(nhv - __half2float(nhh));
        }
    }
}

// ----------------------------------------------------------------------------
// final combine: lp + ent (softmax partials) + v (critic partials)
// ----------------------------------------------------------------------------
__global__ __launch_bounds__(256)
void heads_final_kernel(const float4* __restrict__ part, const __half* __restrict__ l16,
                        const int* __restrict__ action,
                        const float4* __restrict__ partc, const float* __restrict__ bc2,
                        float* __restrict__ out, int TBn)
{
    int row = blockIdx.x * 256 + threadIdx.x;
    if (row >= TBn) return;
    float4 p[8];
#pragma unroll
    for (int i = 0; i < 8; i++) p[i] = part[(size_t)row * 8 + i];
    float M = p[0].x;
#pragma unroll
    for (int i = 1; i < 8; i++) M = fmaxf(M, p[i].x);
    float S = 0.f, Tm = 0.f;
#pragma unroll
    for (int i = 0; i < 8; i++) {
        float e = expf(p[i].x - M);
        S += p[i].y * e;
        Tm += p[i].z * e;
    }
    float lse = M + logf(S);
    float la = __half2float(l16[(size_t)row * NAP + action[row]]);
    out[row] = la - lse;
    out[TBn + row] = lse - Tm / S;

    float v = bc2[0];
#pragma unroll
    for (int i = 0; i < 4; i++) {
        float4 c = partc[(size_t)row * 4 + i];
        v += c.x + c.y + c.z + c.w;
    }
    out[2 * TBn + row] = v;
}

// ----------------------------------------------------------------------------
// host launcher
// ----------------------------------------------------------------------------
extern "C" void kernel_launch(void* const* d_in, const int* in_sizes, int n_in,
                              void* d_out, int out_size)
{
    const float* x    = (const float*)d_in[0];
    const int*   done = (const int*)d_in[1];
    const int*   act  = (const int*)d_in[2];
    const float* W_t1 = (const float*)d_in[4];
    const float* b_t1 = (const float*)d_in[5];
    const float* W_t2 = (const float*)d_in[6];
    const float* b_t2 = (const float*)d_in[7];
    const float* Wih  = (const float*)d_in[8];
    const float* Whh  = (const float*)d_in[9];
    const float* bih  = (const float*)d_in[10];
    const float* bhh  = (const float*)d_in[11];
    const float* Wa1  = (const float*)d_in[12];
    const float* ba1  = (const float*)d_in[13];
    const float* Wa2  = (const float*)d_in[14];
    const float* ba2  = (const float*)d_in[15];
    const float* Wc1  = (const float*)d_in[16];
    const float* bc1  = (const float*)d_in[17];
    const float* Wc2  = (const float*)d_in[18];
    const float* bc2  = (const float*)d_in[19];
    const float* h0   = (const float*)d_in[20];
    const float* c0   = (const float*)d_in[21];

    const int TBn = in_sizes[0] / DI;   // 65536
    const int T = TBn / BB;             // 256
    float* out = (float*)d_out;

    float *h2, *xg, *cbuf, *biasp;
    float4 *part, *partc;
    __half* l16;
    cudaGetSymbolAddress((void**)&h2,    g_h2);
    cudaGetSymbolAddress((void**)&xg,    g_xg);
    cudaGetSymbolAddress((void**)&cbuf,  g_cbuf);
    cudaGetSymbolAddress((void**)&biasp, g_biasp);
    cudaGetSymbolAddress((void**)&part,  g_part);
    cudaGetSymbolAddress((void**)&partc, g_partc);
    cudaGetSymbolAddress((void**)&l16,   g_l16);

    __half *xhi, *xlo, *b1hi, *b1lo, *h2hi, *h2lo, *nhhi, *nhlo, *hmhi, *hmlo;
    __half *wt1h, *wt2h, *wihh, *whhh, *wa1h, *wa2h, *wc1h;
    cudaGetSymbolAddress((void**)&xhi,  g_x_hi);   cudaGetSymbolAddress((void**)&xlo,  g_x_lo);
    cudaGetSymbolAddress((void**)&b1hi, g_b1_hi);  cudaGetSymbolAddress((void**)&b1lo, g_b1_lo);
    cudaGetSymbolAddress((void**)&h2hi, g_h2_hi);  cudaGetSymbolAddress((void**)&h2lo, g_h2_lo);
    cudaGetSymbolAddress((void**)&nhhi, g_nh_hi);  cudaGetSymbolAddress((void**)&nhlo, g_nh_lo);
    cudaGetSymbolAddress((void**)&hmhi, g_hm_hi);  cudaGetSymbolAddress((void**)&hmlo, g_hm_lo);
    cudaGetSymbolAddress((void**)&wt1h, g_wt1_hi);
    cudaGetSymbolAddress((void**)&wt2h, g_wt2_hi);
    cudaGetSymbolAddress((void**)&wihh, g_wihp_hi);
    cudaGetSymbolAddress((void**)&whhh, g_whhp_hi);
    cudaGetSymbolAddress((void**)&wa1h, g_wa1_hi);
    cudaGetSymbolAddress((void**)&wa2h, g_wa2_hi);
    cudaGetSymbolAddress((void**)&wc1h, g_wc1_hi);

    cudaFuncSetAttribute(gemm16_kernel<0>, cudaFuncAttributeMaxDynamicSharedMemorySize, G_SMEM);
    cudaFuncSetAttribute(gemm16_kernel<1>, cudaFuncAttributeMaxDynamicSharedMemorySize, G_SMEM);
    cudaFuncSetAttribute(gemm16_kernel<2>, cudaFuncAttributeMaxDynamicSharedMemorySize, G_SMEM);
    cudaFuncSetAttribute(gemm16_kernel<3>, cudaFuncAttributeMaxDynamicSharedMemorySize, G_SMEM);
    cudaFuncSetAttribute(lstm_persist, cudaFuncAttributeMaxDynamicSharedMemorySize, LSTM_SMEM);

    const dim3 blk(256);

    splitx_kernel<<<TBn * DI / 4 / 256, blk>>>(x, xhi, xlo, TBn * DI / 4);
    prep_kernel<<<dim3(1024, 8), blk>>>(W_t1, W_t2, Wa1, Wc1, Wa2, Wih, Whh, bih, bhh);
    init_state_kernel<<<(BB * LH + 255) / 256, blk>>>(h0, c0, done, hmhi, hmlo, cbuf);

    const int MY = TBn / 128;
    // trunk (2-product)
    gemm16_kernel<1><<<dim3(4, MY), blk, G_SMEM>>>(
        xhi, xlo, wt1h, b_t1, nullptr, b1hi, b1lo, nullptr, nullptr, nullptr, TBn, LH, DI);
    gemm16_kernel<1><<<dim3(4, MY), blk, G_SMEM>>>(
        b1hi, b1lo, wt2h, b_t2, h2, h2hi, h2lo, nullptr, nullptr, nullptr, TBn, LH, LH);
    gemm16_kernel<0><<<dim3(16, MY), blk, G_SMEM>>>(
        h2hi, h2lo, wihh, biasp, xg, nullptr, nullptr, nullptr, nullptr, nullptr, TBn, NG, LH);

    // persistent lstm scan (2-product)
    lstm_persist<<<dim3(16, 8), blk, LSTM_SMEM>>>(
        whhh, xg, done, hmhi, hmlo, cbuf, h2, nhhi, nhlo, T);

    // actor head + fused softmax partials
    gemm16_kernel<1><<<dim3(4, MY), blk, G_SMEM>>>(
        nhhi, nhlo, wa1h, ba1, nullptr, b1hi, b1lo, nullptr, nullptr, nullptr, TBn, LH, LH);
    gemm16_kernel<2><<<dim3(8, MY), blk, G_SMEM>>>(
        b1hi, b1lo, wa2h, ba2, nullptr, nullptr, nullptr, l16, part, nullptr, TBn, NA, LH);

    // critic head fully fused into GEMM epilogue
    gemm16_kernel<3><<<dim3(4, MY), blk, G_SMEM>>>(
        nhhi, nhlo, wc1h, bc1, nullptr, nullptr, nullptr, nullptr, partc, Wc2, TBn, LH, LH);

    // final combine: lp, ent, v
    heads_final_kernel<<<(TBn + 255) / 256, blk>>>(part, l16, act, partc, bc2, out, TBn);
}

// round 12
// speedup vs baseline: 3.3804x; 1.0664x over previous
#include <cuda_runtime.h>
#include <cuda_fp16.h>
#include <math.h>
#include <stdint.h>

// ----------------------------------------------------------------------------
// Problem constants
// ----------------------------------------------------------------------------
#define LH 512
#define DI 512
#define NA 1000
#define NAP 1024
#define NG 2048
#define BB 256
#define TBMAX 65536

// ----------------------------------------------------------------------------
// PTX helpers (base-target-safe)
// ----------------------------------------------------------------------------
__device__ __forceinline__ uint32_t smem_u32(const void* p) {
    uint32_t a;
    asm("{ .reg .u64 t; cvta.to.shared.u64 t, %1; cvt.u32.u64 %0, t; }" : "=r"(a) : "l"(p));
    return a;
}
__device__ __forceinline__ void ldsm_x4(uint32_t (&r)[4], uint32_t addr) {
    asm volatile("ldmatrix.sync.aligned.m8n8.x4.shared.b16 {%0,%1,%2,%3}, [%4];"
                 : "=r"(r[0]), "=r"(r[1]), "=r"(r[2]), "=r"(r[3]) : "r"(addr));
}
__device__ __forceinline__ void mma16816(float (&d)[4], const uint32_t (&a)[4],
                                         uint32_t b0, uint32_t b1) {
    asm volatile(
        "mma.sync.aligned.m16n8k16.row.col.f32.f16.f16.f32 "
        "{%0,%1,%2,%3},{%4,%5,%6,%7},{%8,%9},{%0,%1,%2,%3};"
        : "+f"(d[0]), "+f"(d[1]), "+f"(d[2]), "+f"(d[3])
        : "r"(a[0]), "r"(a[1]), "r"(a[2]), "r"(a[3]), "r"(b0), "r"(b1));
}
__device__ __forceinline__ void cp16(uint32_t dst, const void* src) {
    asm volatile("cp.async.cg.shared.global [%0], [%1], 16;" :: "r"(dst), "l"(src) : "memory");
}
#define CP_COMMIT() asm volatile("cp.async.commit_group;" ::: "memory")
#define CP_WAIT1()  asm volatile("cp.async.wait_group 1;" ::: "memory")
#define CP_WAIT0()  asm volatile("cp.async.wait_group 0;" ::: "memory")

__host__ __device__ __forceinline__ int perm_orig(int p) {
    return (((p & 127) >> 5) << 9) + ((p >> 7) << 5) + (p & 31);
}

// ----------------------------------------------------------------------------
// Scratch
// ----------------------------------------------------------------------------
__device__ __align__(16) float4 g_partc[(size_t)TBMAX * 4];     // critic partials
__device__ float g_h2  [(size_t)TBMAX * LH];
__device__ float g_xg  [(size_t)TBMAX * NG];
__device__ float g_cbuf[BB * LH];
__device__ float g_biasp[NG];
__device__ unsigned int g_bar[8];
__device__ __align__(16) float4 g_part[(size_t)TBMAX * 8];      // softmax partials
__device__ __align__(16) __half g_l16[(size_t)TBMAX * NAP];     // fp16 logits

__device__ __align__(16) __half g_x_hi [(size_t)TBMAX * DI], g_x_lo [(size_t)TBMAX * DI];
__device__ __align__(16) __half g_b1_hi[(size_t)TBMAX * LH], g_b1_lo[(size_t)TBMAX * LH];
__device__ __align__(16) __half g_h2_hi[(size_t)TBMAX * LH], g_h2_lo[(size_t)TBMAX * LH];
__device__ __align__(16) __half g_nh_hi[(size_t)TBMAX * LH], g_nh_lo[(size_t)TBMAX * LH];
__device__ __align__(16) __half g_hm_hi[2 * BB * LH], g_hm_lo[2 * BB * LH];
__device__ __align__(16) __half g_wt1_hi[LH * DI];
__device__ __align__(16) __half g_wt2_hi[LH * LH];
__device__ __align__(16) __half g_wihp_hi[NG * LH];
__device__ __align__(16) __half g_whhp_hi[NG * LH];
__device__ __align__(16) __half g_wa1_hi[LH * LH];
__device__ __align__(16) __half g_wa2_hi[NAP * LH];
__device__ __align__(16) __half g_wc1_hi[LH * LH];

__device__ __forceinline__ float sigm(float x) { return 1.0f / (1.0f + expf(-x)); }

__device__ __forceinline__ void split_store4(float4 v, __half* H, __half* L, size_t idx) {
    __half2 a = __floats2half2_rn(v.x, v.y);
    __half2 b = __floats2half2_rn(v.z, v.w);
    float2 af = __half22float2(a), bf = __half22float2(b);
    __half2 al = __floats2half2_rn(v.x - af.x, v.y - af.y);
    __half2 bl = __floats2half2_rn(v.z - bf.x, v.w - bf.y);
    *(__half2*)&H[idx] = a;  *(__half2*)&H[idx + 2] = b;
    *(__half2*)&L[idx] = al; *(__half2*)&L[idx + 2] = bl;
}
__device__ __forceinline__ void hi_store4(float4 v, __half* H, size_t idx) {
    *(__half2*)&H[idx] = __floats2half2_rn(v.x, v.y);
    *(__half2*)&H[idx + 2] = __floats2half2_rn(v.z, v.w);
}

// ----------------------------------------------------------------------------
__global__ __launch_bounds__(256)
void splitx_kernel(const float* __restrict__ X, __half* __restrict__ H,
                   __half* __restrict__ L, int n4)
{
    int i = blockIdx.x * 256 + threadIdx.x;
    if (i < n4) split_store4(((const float4*)X)[i], H, L, (size_t)i * 4);
}

// ----------------------------------------------------------------------------
// weight prep: all weights hi-only; permutation for Wih/Whh
// ----------------------------------------------------------------------------
__global__ __launch_bounds__(256)
void prep_kernel(const float* __restrict__ W_t1, const float* __restrict__ W_t2,
                 const float* __restrict__ Wa1, const float* __restrict__ Wc1,
                 const float* __restrict__ Wa2,
                 const float* __restrict__ Wih, const float* __restrict__ Whh,
                 const float* __restrict__ bih, const float* __restrict__ bhh)
{
    const int i = blockIdx.x * 256 + threadIdx.x;
    const int sec = blockIdx.y;
    switch (sec) {
    case 0: if (i < LH * DI / 4) hi_store4(((const float4*)W_t1)[i], g_wt1_hi, (size_t)i * 4); break;
    case 1: if (i < LH * LH / 4) hi_store4(((const float4*)W_t2)[i], g_wt2_hi, (size_t)i * 4); break;
    case 2: if (i < LH * LH / 4) hi_store4(((const float4*)Wa1)[i], g_wa1_hi, (size_t)i * 4); break;
    case 3: if (i < LH * LH / 4) hi_store4(((const float4*)Wc1)[i], g_wc1_hi, (size_t)i * 4); break;
    case 4:
        if (i < NAP * LH / 4) {
            if (i < NA * LH / 4) hi_store4(((const float4*)Wa2)[i], g_wa2_hi, (size_t)i * 4);
            else {
                __half2 z = __floats2half2_rn(0.f, 0.f);
                *(__half2*)&g_wa2_hi[(size_t)i * 4] = z; *(__half2*)&g_wa2_hi[(size_t)i * 4 + 2] = z;
            }
        }
        break;
    case 5:
        if (i < NG * LH / 4) {
            int row = i >> 7, c4 = i & 127;
            hi_store4(((const float4*)(Wih + (size_t)perm_orig(row) * LH))[c4], g_wihp_hi, (size_t)i * 4);
        }
        break;
    case 6:
        if (i < NG * LH / 4) {
            int row = i >> 7, c4 = i & 127;
            hi_store4(((const float4*)(Whh + (size_t)perm_orig(row) * LH))[c4], g_whhp_hi, (size_t)i * 4);
        }
        break;
    case 7:
        if (i < NG) { int o = perm_orig(i); g_biasp[i] = bih[o] + bhh[o]; }
        break;
    }
}

// ----------------------------------------------------------------------------
__global__ __launch_bounds__(256)
void init_state_kernel(const float* __restrict__ h0, const float* __restrict__ c0,
                       const int* __restrict__ done0,
                       __half* __restrict__ hhi, __half* __restrict__ hlo,
                       float* __restrict__ c)
{
    int idx = blockIdx.x * 256 + threadIdx.x;
    if (blockIdx.x == 0 && threadIdx.x < 8) g_bar[threadIdx.x] = 0u;
    if (idx < BB * LH) {
        float m = 1.0f - (float)done0[idx >> 9];
        float hv = h0[idx] * m;
        __half hh = __float2half_rn(hv);
        hhi[idx] = hh;
        hlo[idx] = __float2half_rn(hv - __half2float(hh));
        c[idx] = c0[idx] * m;
    }
}

// ----------------------------------------------------------------------------
// HMMA 2-product GEMM (unchanged from round 11)
// ----------------------------------------------------------------------------
#define ARR_BYTES 10240u
#define BUF_BYTES 30720u
#define G_SMEM 70656

template<int MODE>
__global__ __launch_bounds__(256, 2)
void gemm16_kernel(const __half* __restrict__ Ahi, const __half* __restrict__ Alo,
                   const __half* __restrict__ Bhi,
                   const float* __restrict__ b1,
                   float* __restrict__ C, __half* __restrict__ Chi, __half* __restrict__ Clo,
                   __half* __restrict__ C16, float4* __restrict__ part,
                   const float* __restrict__ w2,
                   int M, int N, int K)
{
    extern __shared__ __align__(16) char smem[];
    const uint32_t sb = smem_u32(smem);
    const int tid = threadIdx.x;
    const int lane = tid & 31, wid = tid >> 5;
    const int m0 = blockIdx.y * 128, n0 = blockIdx.x * 128;
    const int wm = (wid >> 2) * 64, wn = (wid & 3) * 32;

    float acc[4][4][4];
#pragma unroll
    for (int a = 0; a < 4; a++)
#pragma unroll
        for (int b = 0; b < 4; b++)
#pragma unroll
            for (int c = 0; c < 4; c++) acc[a][b][c] = 0.0f;

    const int NCH = K >> 5;

    auto issue_chunk = [&](int c) {
        const uint32_t bufb = (uint32_t)(c & 1) * BUF_BYTES;
        const int k0 = c * 32;
#pragma unroll
        for (int i = 0; i < 6; i++) {
            int p = tid + i * 256;
            int arr = p >> 9;
            int q = p & 511;
            int r = q >> 2;
            int ch = (q & 3) * 8;
            int grow = (arr < 2 ? m0 : n0) + r;
            const __half* src = (arr == 0 ? Ahi : arr == 1 ? Alo : Bhi)
                              + (size_t)grow * K + k0 + ch;
            uint32_t dst = sb + bufb + (uint32_t)arr * ARR_BYTES
                         + (uint32_t)r * 80u + (uint32_t)ch * 2u;
            cp16(dst, src);
        }
        CP_COMMIT();
    };

    issue_chunk(0);

    for (int c = 0; c < NCH; c++) {
        if (c + 1 < NCH) { issue_chunk(c + 1); CP_WAIT1(); }
        else             { CP_WAIT0(); }
        __syncthreads();

        const uint32_t abase = sb + (uint32_t)(c & 1) * BUF_BYTES;
#pragma unroll
        for (int ks = 0; ks < 2; ks++) {
            const uint32_t kcol = (uint32_t)(ks * 16 + (lane >> 4) * 8) * 2u;
            uint32_t bh[4][2];
#pragma unroll
            for (int ng = 0; ng < 2; ng++) {
                uint32_t row = (uint32_t)(wn + ng * 16 + ((lane >> 3) & 1) * 8 + (lane & 7));
                uint32_t addr = abase + 2u * ARR_BYTES + row * 80u + kcol;
                uint32_t r4[4];
                ldsm_x4(r4, addr);
                bh[ng * 2 + 0][0] = r4[0]; bh[ng * 2 + 0][1] = r4[2];
                bh[ng * 2 + 1][0] = r4[1]; bh[ng * 2 + 1][1] = r4[3];
            }
#pragma unroll
            for (int mi = 0; mi < 4; mi++) {
                uint32_t aaddr = abase + (uint32_t)(wm + mi * 16 + (lane & 15)) * 80u + kcol;
                uint32_t ah[4], al[4];
                ldsm_x4(ah, aaddr);
                ldsm_x4(al, aaddr + ARR_BYTES);
#pragma unroll
                for (int ni = 0; ni < 4; ni++) {
                    mma16816(acc[mi][ni], ah, bh[ni][0], bh[ni][1]);
                    mma16816(acc[mi][ni], al, bh[ni][0], bh[ni][1]);
                }
            }
        }
        __syncthreads();
    }

    if (MODE == 2) {
        float* st = (float*)smem;                     // 128 x 132 fp32
        float3* pr = (float3*)(smem + 128 * 132 * 4); // 256 partials
#pragma unroll
        for (int ni = 0; ni < 4; ni++) {
            int col = n0 + wn + ni * 8 + (lane & 3) * 2;
            int jc = wn + ni * 8 + (lane & 3) * 2;
            if (col >= N) continue;
            float bb0 = b1[col], bb1 = b1[col + 1];
#pragma unroll
            for (int mi = 0; mi < 4; mi++) {
                int rloc = wm + mi * 16 + (lane >> 2);
#pragma unroll
                for (int h = 0; h < 2; h++) {
                    st[(rloc + h * 8) * 132 + jc]     = acc[mi][ni][h * 2 + 0] + bb0;
                    st[(rloc + h * 8) * 132 + jc + 1] = acc[mi][ni][h * 2 + 1] + bb1;
                }
            }
        }
        __syncthreads();
        {
            int rloc = tid >> 1;
            int half = tid & 1;
            float m = -3.402823e38f, s = 0.f, t = 0.f;
#pragma unroll 4
            for (int j = 0; j < 64; j++) {
                int jc = half * 64 + j;
                if (n0 + jc < N) m = fmaxf(m, st[rloc * 132 + jc]);
            }
#pragma unroll 4
            for (int j = 0; j < 64; j++) {
                int jc = half * 64 + j;
                if (n0 + jc < N) {
                    float l = st[rloc * 132 + jc];
                    float e = expf(l - m);
                    s += e; t += e * l;
                }
            }
            pr[tid] = make_float3(m, s, t);
        }
        __syncthreads();
        if (tid < 128) {
            float3 a = pr[tid * 2], b = pr[tid * 2 + 1];
            float m = fmaxf(a.x, b.x);
            float ea = expf(a.x - m), eb = expf(b.x - m);
            part[(size_t)(m0 + tid) * 8 + blockIdx.x] =
                make_float4(m, a.y * ea + b.y * eb, a.z * ea + b.z * eb, 0.f);
        }
        for (int i = tid; i < 128 * 64; i += 256) {
            int rloc = i >> 6;
            int j2 = (i & 63) * 2;
            int col = n0 + j2;
            if (col < N) {
                __half2 hv = __floats2half2_rn(st[rloc * 132 + j2],
                                               (col + 1 < N) ? st[rloc * 132 + j2 + 1] : 0.f);
                *(__half2*)&C16[(size_t)(m0 + rloc) * NAP + col] = hv;
            }
        }
        return;
    }

    if (MODE == 3) {
        float* smp = (float*)smem;  // 128 x 4
        float ps[8];
#pragma unroll
        for (int i = 0; i < 8; i++) ps[i] = 0.f;
#pragma unroll
        for (int ni = 0; ni < 4; ni++) {
            int col = n0 + wn + ni * 8 + (lane & 3) * 2;
            float bb0 = b1[col], bb1 = b1[col + 1];
            float w0 = w2[col], w1 = w2[col + 1];
#pragma unroll
            for (int mi = 0; mi < 4; mi++) {
#pragma unroll
                for (int h = 0; h < 2; h++) {
                    float v0 = tanhf(acc[mi][ni][h * 2 + 0] + bb0);
                    float v1 = tanhf(acc[mi][ni][h * 2 + 1] + bb1);
                    ps[mi * 2 + h] += v0 * w0 + v1 * w1;
                }
            }
        }
#pragma unroll
        for (int i = 0; i < 8; i++) {
            ps[i] += __shfl_xor_sync(0xffffffffu, ps[i], 1);
            ps[i] += __shfl_xor_sync(0xffffffffu, ps[i], 2);
        }
        if ((lane & 3) == 0) {
#pragma unroll
            for (int mi = 0; mi < 4; mi++)
#pragma unroll
                for (int h = 0; h < 2; h++) {
                    int rloc = wm + mi * 16 + (lane >> 2) + h * 8;
                    smp[rloc * 4 + (wid & 3)] = ps[mi * 2 + h];
                }
        }
        __syncthreads();
        if (tid < 128)
            part[(size_t)(m0 + tid) * 4 + blockIdx.x] =
                make_float4(smp[tid * 4], smp[tid * 4 + 1], smp[tid * 4 + 2], smp[tid * 4 + 3]);
        return;
    }

    // MODE 0/1 epilogue
#pragma unroll
    for (int ni = 0; ni < 4; ni++) {
        int col = n0 + wn + ni * 8 + (lane & 3) * 2;
        if (col >= N) continue;
        float bb0 = b1[col], bb1 = b1[col + 1];
#pragma unroll
        for (int mi = 0; mi < 4; mi++) {
            int r0 = m0 + wm + mi * 16 + (lane >> 2);
#pragma unroll
            for (int h = 0; h < 2; h++) {
                int rr = r0 + h * 8;
                float v0 = acc[mi][ni][h * 2 + 0] + bb0;
                float v1 = acc[mi][ni][h * 2 + 1] + bb1;
                if (MODE == 1) { v0 = tanhf(v0); v1 = tanhf(v1); }
                size_t base = (size_t)rr * N + col;
                if (C) *(float2*)&C[base] = make_float2(v0, v1);
                if (Chi) {
                    __half2 hh = __floats2half2_rn(v0, v1);
                    float2 hf = __half22float2(hh);
                    __half2 ll = __floats2half2_rn(v0 - hf.x, v1 - hf.y);
                    *(__half2*)&Chi[base] = hh;
                    *(__half2*)&Clo[base] = ll;
                }
            }
        }
    }
}

// ----------------------------------------------------------------------------
// PERSISTENT LSTM scan with SMEM-RESIDENT Whh slice.
// SMEM: [W: 128 rows x 512 halfs, pitch 1040 = 133120 B]
//       [A: hi 32x512 pitch 1040 = 33280 B][A lo = 33280 B]  (gsm overlays A)
// One cp.async batch + one sync per step; MMA loop is sync-free.
// ----------------------------------------------------------------------------
#define S_A     133120u
#define S_ALO   33280u
#define LSTM_SMEM 199680

__global__ __launch_bounds__(256, 1)
void lstm_persist(const __half* __restrict__ Wh,
                  const float* __restrict__ xg,
                  const int*   __restrict__ done,
                  __half* __restrict__ hmhi, __half* __restrict__ hmlo,
                  float* __restrict__ c_buf,
                  const float* __restrict__ h2,
                  __half* __restrict__ nhhi, __half* __restrict__ nhlo,
                  int T)
{
    extern __shared__ __align__(16) char smem[];
    const uint32_t sb = smem_u32(smem);
    float* gsm = (float*)(smem + S_A);   // overlay on A region (A dead by then)

    const int tid = threadIdx.x;
    const int lane = tid & 31, wid = tid >> 5;
    const int n0 = blockIdx.x * 128;
    const int lbase = blockIdx.x * 32;
    const int r0 = blockIdx.y * 32;
    const int rb = blockIdx.y;
    const int wm16 = (wid & 1) * 16, wn32 = (wid >> 1) * 32;

    // load resident W slice: 128 rows x 512 halfs, pitch 1040 B
#pragma unroll
    for (int j = 0; j < 32; j++) {
        int p = tid + j * 256;
        int row = p >> 6, c8 = (p & 63) * 8;
        cp16(sb + (uint32_t)row * 1040u + (uint32_t)c8 * 2u,
             Wh + (size_t)(n0 + row) * LH + c8);
    }
    CP_COMMIT(); CP_WAIT0();
    __syncthreads();

    for (int t = 0; t < T; t++) {
        if (t > 0) {
            if (tid == 0) {
                unsigned int need = (unsigned int)(16 * t);
                while (atomicAdd(&g_bar[rb], 0u) < need) { __nanosleep(100); }
            }
            __syncthreads();
            __threadfence();
        }

        const __half* hhi_in = hmhi + (size_t)(t & 1) * BB * LH;
        const __half* hlo_in = hmlo + (size_t)(t & 1) * BB * LH;
        const float* xg_t = xg + (size_t)t * BB * NG;
        const float* h2_t = h2 + (size_t)t * BB * LH;

        // load full h tile (hi+lo), one batch
#pragma unroll
        for (int j = 0; j < 16; j++) {
            int p = tid + j * 256;
            int hl = p >> 11;
            int q = p & 2047;
            int row = q >> 6, c8 = (q & 63) * 8;
            const __half* src = (hl ? hlo_in : hhi_in) + (size_t)(r0 + row) * LH + c8;
            cp16(sb + S_A + (uint32_t)hl * S_ALO + (uint32_t)row * 1040u + (uint32_t)c8 * 2u, src);
        }
        CP_COMMIT(); CP_WAIT0();
        __syncthreads();

        float acc[4][4];
#pragma unroll
        for (int a = 0; a < 4; a++)
#pragma unroll
            for (int b = 0; b < 4; b++) acc[a][b] = 0.0f;

        // sync-free MMA loop over 16 k-chunks
#pragma unroll 4
        for (int c = 0; c < 16; c++) {
#pragma unroll
            for (int ks = 0; ks < 2; ks++) {
                const uint32_t kcol = (uint32_t)c * 64u + (uint32_t)(ks * 16 + (lane >> 4) * 8) * 2u;
                uint32_t bh[4][2];
#pragma unroll
                for (int ng = 0; ng < 2; ng++) {
                    uint32_t row = (uint32_t)(wn32 + ng * 16 + ((lane >> 3) & 1) * 8 + (lane & 7));
                    uint32_t r4[4];
                    ldsm_x4(r4, sb + row * 1040u + kcol);
                    bh[ng * 2 + 0][0] = r4[0]; bh[ng * 2 + 0][1] = r4[2];
                    bh[ng * 2 + 1][0] = r4[1]; bh[ng * 2 + 1][1] = r4[3];
                }
                uint32_t aaddr = sb + S_A + (uint32_t)(wm16 + (lane & 15)) * 1040u + kcol;
                uint32_t ah[4], al[4];
                ldsm_x4(ah, aaddr);
                ldsm_x4(al, aaddr + S_ALO);
#pragma unroll
                for (int ni = 0; ni < 4; ni++) {
                    mma16816(acc[ni], ah, bh[ni][0], bh[ni][1]);
                    mma16816(acc[ni], al, bh[ni][0], bh[ni][1]);
                }
            }
        }
        __syncthreads();   // all A reads done before gsm overlay writes

#pragma unroll
        for (int ni = 0; ni < 4; ni++) {
            int col = wn32 + ni * 8 + (lane & 3) * 2;
            int row0 = wm16 + (lane >> 2);
            const float* xr0 = xg_t + (size_t)(r0 + row0) * NG + n0 + col;
            gsm[row0 * 132 + col]     = acc[ni][0] + xr0[0];
            gsm[row0 * 132 + col + 1] = acc[ni][1] + xr0[1];
            const float* xr1 = xr0 + 8 * NG;
            gsm[(row0 + 8) * 132 + col]     = acc[ni][2] + xr1[0];
            gsm[(row0 + 8) * 132 + col + 1] = acc[ni][3] + xr1[1];
        }
        __syncthreads();

        __half* hhi_out = hmhi + (size_t)((t + 1) & 1) * BB * LH;
        __half* hlo_out = hmlo + (size_t)((t + 1) & 1) * BB * LH;
        __half* nhhi_t = nhhi + (size_t)t * BB * LH;
        __half* nhlo_t = nhlo + (size_t)t * BB * LH;
        const int* done_next = (t + 1 < T) ? (done + (size_t)(t + 1) * BB) : nullptr;

        float hn_s[4];
#pragma unroll
        for (int q = 0; q < 4; q++) {
            int cell = tid + q * 256;
            int r = cell >> 5;
            int li = cell & 31;
            float iv = gsm[r * 132 + li];
            float fv = gsm[r * 132 + 32 + li];
            float gv = gsm[r * 132 + 64 + li];
            float ov = gsm[r * 132 + 96 + li];
            size_t gi = (size_t)(r0 + r) * LH + lbase + li;
            float cp = c_buf[gi];
            float cn = sigm(fv) * cp + sigm(iv) * tanhf(gv);
            float hn = sigm(ov) * tanhf(cn);
            hn_s[q] = hn;
            float mn = done_next ? (1.0f - (float)done_next[r0 + r]) : 1.0f;
            c_buf[gi] = cn * mn;
            float hm = hn * mn;
            __half hmh = __float2half_rn(hm);
            hhi_out[gi] = hmh;
            hlo_out[gi] = __float2half_rn(hm - __half2float(hmh));
        }
        __threadfence();
        __syncthreads();
        if (tid == 0) atomicAdd(&g_bar[rb], 1u);

        // deferred: nh = hn + h2 (not consumed by the scan)
#pragma unroll
        for (int q = 0; q < 4; q++) {
            int cell = tid + q * 256;
            int r = cell >> 5;
            int li = cell & 31;
            size_t gi = (size_t)(r0 + r) * LH + lbase + li;
            float nhv = hn_s[q] + h2_t[gi];
            __half nhh = __float2half_rn(nhv);
            nhhi_t[gi] = nhh;
            nhlo_t[gi] = __float2half_rn(nhv - __half2float(nhh));
        }
    }
}

// ----------------------------------------------------------------------------
// final combine: lp + ent + v
// ----------------------------------------------------------------------------
__global__ __launch_bounds__(256)
void heads_final_kernel(const float4* __restrict__ part, const __half* __restrict__ l16,
                        const int* __restrict__ action,
                        const float4* __restrict__ partc, const float* __restrict__ bc2,
                        float* __restrict__ out, int TBn)
{
    int row = blockIdx.x * 256 + threadIdx.x;
    if (row >= TBn) return;
    float4 p[8];
#pragma unroll
    for (int i = 0; i < 8; i++) p[i] = part[(size_t)row * 8 + i];
    float M = p[0].x;
#pragma unroll
    for (int i = 1; i < 8; i++) M = fmaxf(M, p[i].x);
    float S = 0.f, Tm = 0.f;
#pragma unroll
    for (int i = 0; i < 8; i++) {
        float e = expf(p[i].x - M);
        S += p[i].y * e;
        Tm += p[i].z * e;
    }
    float lse = M + logf(S);
    float la = __half2float(l16[(size_t)row * NAP + action[row]]);
    out[row] = la - lse;
    out[TBn + row] = lse - Tm / S;

    float v = bc2[0];
#pragma unroll
    for (int i = 0; i < 4; i++) {
        float4 c = partc[(size_t)row * 4 + i];
        v += c.x + c.y + c.z + c.w;
    }
    out[2 * TBn + row] = v;
}

// ----------------------------------------------------------------------------
// host launcher
// ----------------------------------------------------------------------------
extern "C" void kernel_launch(void* const* d_in, const int* in_sizes, int n_in,
                              void* d_out, int out_size)
{
    const float* x    = (const float*)d_in[0];
    const int*   done = (const int*)d_in[1];
    const int*   act  = (const int*)d_in[2];
    const float* W_t1 = (const float*)d_in[4];
    const float* b_t1 = (const float*)d_in[5];
    const float* W_t2 = (const float*)d_in[6];
    const float* b_t2 = (const float*)d_in[7];
    const float* Wih  = (const float*)d_in[8];
    const float* Whh  = (const float*)d_in[9];
    const float* bih  = (const float*)d_in[10];
    const float* bhh  = (const float*)d_in[11];
    const float* Wa1  = (const float*)d_in[12];
    const float* ba1  = (const float*)d_in[13];
    const float* Wa2  = (const float*)d_in[14];
    const float* ba2  = (const float*)d_in[15];
    const float* Wc1  = (const float*)d_in[16];
    const float* bc1  = (const float*)d_in[17];
    const float* Wc2  = (const float*)d_in[18];
    const float* bc2  = (const float*)d_in[19];
    const float* h0   = (const float*)d_in[20];
    const float* c0   = (const float*)d_in[21];

    const int TBn = in_sizes[0] / DI;   // 65536
    const int T = TBn / BB;             // 256
    float* out = (float*)d_out;

    float *h2, *xg, *cbuf, *biasp;
    float4 *part, *partc;
    __half* l16;
    cudaGetSymbolAddress((void**)&h2,    g_h2);
    cudaGetSymbolAddress((void**)&xg,    g_xg);
    cudaGetSymbolAddress((void**)&cbuf,  g_cbuf);
    cudaGetSymbolAddress((void**)&biasp, g_biasp);
    cudaGetSymbolAddress((void**)&part,  g_part);
    cudaGetSymbolAddress((void**)&partc, g_partc);
    cudaGetSymbolAddress((void**)&l16,   g_l16);

    __half *xhi, *xlo, *b1hi, *b1lo, *h2hi, *h2lo, *nhhi, *nhlo, *hmhi, *hmlo;
    __half *wt1h, *wt2h, *wihh, *whhh, *wa1h, *wa2h, *wc1h;
    cudaGetSymbolAddress((void**)&xhi,  g_x_hi);   cudaGetSymbolAddress((void**)&xlo,  g_x_lo);
    cudaGetSymbolAddress((void**)&b1hi, g_b1_hi);  cudaGetSymbolAddress((void**)&b1lo, g_b1_lo);
    cudaGetSymbolAddress((void**)&h2hi, g_h2_hi);  cudaGetSymbolAddress((void**)&h2lo, g_h2_lo);
    cudaGetSymbolAddress((void**)&nhhi, g_nh_hi);  cudaGetSymbolAddress((void**)&nhlo, g_nh_lo);
    cudaGetSymbolAddress((void**)&hmhi, g_hm_hi);  cudaGetSymbolAddress((void**)&hmlo, g_hm_lo);
    cudaGetSymbolAddress((void**)&wt1h, g_wt1_hi);
    cudaGetSymbolAddress((void**)&wt2h, g_wt2_hi);
    cudaGetSymbolAddress((void**)&wihh, g_wihp_hi);
    cudaGetSymbolAddress((void**)&whhh, g_whhp_hi);
    cudaGetSymbolAddress((void**)&wa1h, g_wa1_hi);
    cudaGetSymbolAddress((void**)&wa2h, g_wa2_hi);
    cudaGetSymbolAddress((void**)&wc1h, g_wc1_hi);

    cudaFuncSetAttribute(gemm16_kernel<0>, cudaFuncAttributeMaxDynamicSharedMemorySize, G_SMEM);
    cudaFuncSetAttribute(gemm16_kernel<1>, cudaFuncAttributeMaxDynamicSharedMemorySize, G_SMEM);
    cudaFuncSetAttribute(gemm16_kernel<2>, cudaFuncAttributeMaxDynamicSharedMemorySize, G_SMEM);
    cudaFuncSetAttribute(gemm16_kernel<3>, cudaFuncAttributeMaxDynamicSharedMemorySize, G_SMEM);
    cudaFuncSetAttribute(lstm_persist, cudaFuncAttributeMaxDynamicSharedMemorySize, LSTM_SMEM);

    const dim3 blk(256);

    splitx_kernel<<<TBn * DI / 4 / 256, blk>>>(x, xhi, xlo, TBn * DI / 4);
    prep_kernel<<<dim3(1024, 8), blk>>>(W_t1, W_t2, Wa1, Wc1, Wa2, Wih, Whh, bih, bhh);
    init_state_kernel<<<(BB * LH + 255) / 256, blk>>>(h0, c0, done, hmhi, hmlo, cbuf);

    const int MY = TBn / 128;
    // trunk (2-product)
    gemm16_kernel<1><<<dim3(4, MY), blk, G_SMEM>>>(
        xhi, xlo, wt1h, b_t1, nullptr, b1hi, b1lo, nullptr, nullptr, nullptr, TBn, LH, DI);
    gemm16_kernel<1><<<dim3(4, MY), blk, G_SMEM>>>(
        b1hi, b1lo, wt2h, b_t2, h2, h2hi, h2lo, nullptr, nullptr, nullptr, TBn, LH, LH);
    gemm16_kernel<0><<<dim3(16, MY), blk, G_SMEM>>>(
        h2hi, h2lo, wihh, biasp, xg, nullptr, nullptr, nullptr, nullptr, nullptr, TBn, NG, LH);

    // persistent lstm scan (2-product, W resident in SMEM)
    lstm_persist<<<dim3(16, 8), blk, LSTM_SMEM>>>(
        whhh, xg, done, hmhi, hmlo, cbuf, h2, nhhi, nhlo, T);

    // actor head + fused softmax partials
    gemm16_kernel<1><<<dim3(4, MY), blk, G_SMEM>>>(
        nhhi, nhlo, wa1h, ba1, nullptr, b1hi, b1lo, nullptr, nullptr, nullptr, TBn, LH, LH);
    gemm16_kernel<2><<<dim3(8, MY), blk, G_SMEM>>>(
        b1hi, b1lo, wa2h, ba2, nullptr, nullptr, nullptr, l16, part, nullptr, TBn, NA, LH);

    // critic head fully fused into GEMM epilogue
    gemm16_kernel<3><<<dim3(4, MY), blk, G_SMEM>>>(
        nhhi, nhlo, wc1h, bc1, nullptr, nullptr, nullptr, nullptr, partc, Wc2, TBn, LH, LH);

    // final combine: lp, ent, v
    heads_final_kernel<<<(TBn + 255) / 256, blk>>>(part, l16, act, partc, bc2, out, TBn);
}

// round 13
// speedup vs baseline: 4.0124x; 1.1870x over previous
#include <cuda_runtime.h>
#include <cuda_fp16.h>
#include <math.h>
#include <stdint.h>

// ----------------------------------------------------------------------------
// Problem constants
// ----------------------------------------------------------------------------
#define LH 512
#define DI 512
#define NA 1000
#define NAP 1024
#define NG 2048
#define BB 256
#define TBMAX 65536

// ----------------------------------------------------------------------------
// PTX helpers (base-target-safe)
// ----------------------------------------------------------------------------
__device__ __forceinline__ uint32_t smem_u32(const void* p) {
    uint32_t a;
    asm("{ .reg .u64 t; cvta.to.shared.u64 t, %1; cvt.u32.u64 %0, t; }" : "=r"(a) : "l"(p));
    return a;
}
__device__ __forceinline__ void ldsm_x4(uint32_t (&r)[4], uint32_t addr) {
    asm volatile("ldmatrix.sync.aligned.m8n8.x4.shared.b16 {%0,%1,%2,%3}, [%4];"
                 : "=r"(r[0]), "=r"(r[1]), "=r"(r[2]), "=r"(r[3]) : "r"(addr));
}
__device__ __forceinline__ void mma16816(float (&d)[4], const uint32_t (&a)[4],
                                         uint32_t b0, uint32_t b1) {
    asm volatile(
        "mma.sync.aligned.m16n8k16.row.col.f32.f16.f16.f32 "
        "{%0,%1,%2,%3},{%4,%5,%6,%7},{%8,%9},{%0,%1,%2,%3};"
        : "+f"(d[0]), "+f"(d[1]), "+f"(d[2]), "+f"(d[3])
        : "r"(a[0]), "r"(a[1]), "r"(a[2]), "r"(a[3]), "r"(b0), "r"(b1));
}
__device__ __forceinline__ void cp16(uint32_t dst, const void* src) {
    asm volatile("cp.async.cg.shared.global [%0], [%1], 16;" :: "r"(dst), "l"(src) : "memory");
}
#define CP_COMMIT() asm volatile("cp.async.commit_group;" ::: "memory")
#define CP_WAIT1()  asm volatile("cp.async.wait_group 1;" ::: "memory")
#define CP_WAIT0()  asm volatile("cp.async.wait_group 0;" ::: "memory")

__host__ __device__ __forceinline__ int perm_orig(int p) {
    return (((p & 127) >> 5) << 9) + ((p >> 7) << 5) + (p & 31);
}

// ----------------------------------------------------------------------------
// Scratch
// ----------------------------------------------------------------------------
__device__ __align__(16) float4 g_partc[(size_t)TBMAX * 4];     // critic partials
__device__ float g_h2  [(size_t)TBMAX * LH];
__device__ float g_xg  [(size_t)TBMAX * NG];
__device__ float g_cbuf[BB * LH];
__device__ float g_biasp[NG];
__device__ unsigned int g_bar[8];
__device__ __align__(16) float4 g_part[(size_t)TBMAX * 8];      // softmax partials
__device__ __align__(16) __half g_l16[(size_t)TBMAX * NAP];     // fp16 logits

__device__ __align__(16) __half g_x_hi [(size_t)TBMAX * DI], g_x_lo [(size_t)TBMAX * DI];
__device__ __align__(16) __half g_b1_hi[(size_t)TBMAX * LH], g_b1_lo[(size_t)TBMAX * LH];
__device__ __align__(16) __half g_h2_hi[(size_t)TBMAX * LH], g_h2_lo[(size_t)TBMAX * LH];
__device__ __align__(16) __half g_nh_hi[(size_t)TBMAX * LH];    // nh: hi only (heads 1-product)
__device__ __align__(16) __half g_hm_hi[2 * BB * LH];           // h: hi only (scan 1-product h)
__device__ __align__(16) __half g_wt1_hi[LH * DI];
__device__ __align__(16) __half g_wt2_hi[LH * LH];
__device__ __align__(16) __half g_wihp_hi[NG * LH];
__device__ __align__(16) __half g_whhp_hi[NG * LH];
__device__ __align__(16) __half g_wa1_hi[LH * LH];
__device__ __align__(16) __half g_wa2_hi[NAP * LH];
__device__ __align__(16) __half g_wc1_hi[LH * LH];

__device__ __forceinline__ float sigm(float x) { return 1.0f / (1.0f + expf(-x)); }

__device__ __forceinline__ void split_store4(float4 v, __half* H, __half* L, size_t idx) {
    __half2 a = __floats2half2_rn(v.x, v.y);
    __half2 b = __floats2half2_rn(v.z, v.w);
    float2 af = __half22float2(a), bf = __half22float2(b);
    __half2 al = __floats2half2_rn(v.x - af.x, v.y - af.y);
    __half2 bl = __floats2half2_rn(v.z - bf.x, v.w - bf.y);
    *(__half2*)&H[idx] = a;  *(__half2*)&H[idx + 2] = b;
    *(__half2*)&L[idx] = al; *(__half2*)&L[idx + 2] = bl;
}
__device__ __forceinline__ void hi_store4(float4 v, __half* H, size_t idx) {
    *(__half2*)&H[idx] = __floats2half2_rn(v.x, v.y);
    *(__half2*)&H[idx + 2] = __floats2half2_rn(v.z, v.w);
}

// ----------------------------------------------------------------------------
__global__ __launch_bounds__(256)
void splitx_kernel(const float* __restrict__ X, __half* __restrict__ H,
                   __half* __restrict__ L, int n4)
{
    int i = blockIdx.x * 256 + threadIdx.x;
    if (i < n4) split_store4(((const float4*)X)[i], H, L, (size_t)i * 4);
}

// ----------------------------------------------------------------------------
// weight prep (hi-only weights; permutation for Wih/Whh)
// ----------------------------------------------------------------------------
__global__ __launch_bounds__(256)
void prep_kernel(const float* __restrict__ W_t1, const float* __restrict__ W_t2,
                 const float* __restrict__ Wa1, const float* __restrict__ Wc1,
                 const float* __restrict__ Wa2,
                 const float* __restrict__ Wih, const float* __restrict__ Whh,
                 const float* __restrict__ bih, const float* __restrict__ bhh)
{
    const int i = blockIdx.x * 256 + threadIdx.x;
    const int sec = blockIdx.y;
    switch (sec) {
    case 0: if (i < LH * DI / 4) hi_store4(((const float4*)W_t1)[i], g_wt1_hi, (size_t)i * 4); break;
    case 1: if (i < LH * LH / 4) hi_store4(((const float4*)W_t2)[i], g_wt2_hi, (size_t)i * 4); break;
    case 2: if (i < LH * LH / 4) hi_store4(((const float4*)Wa1)[i], g_wa1_hi, (size_t)i * 4); break;
    case 3: if (i < LH * LH / 4) hi_store4(((const float4*)Wc1)[i], g_wc1_hi, (size_t)i * 4); break;
    case 4:
        if (i < NAP * LH / 4) {
            if (i < NA * LH / 4) hi_store4(((const float4*)Wa2)[i], g_wa2_hi, (size_t)i * 4);
            else {
                __half2 z = __floats2half2_rn(0.f, 0.f);
                *(__half2*)&g_wa2_hi[(size_t)i * 4] = z; *(__half2*)&g_wa2_hi[(size_t)i * 4 + 2] = z;
            }
        }
        break;
    case 5:
        if (i < NG * LH / 4) {
            int row = i >> 7, c4 = i & 127;
            hi_store4(((const float4*)(Wih + (size_t)perm_orig(row) * LH))[c4], g_wihp_hi, (size_t)i * 4);
        }
        break;
    case 6:
        if (i < NG * LH / 4) {
            int row = i >> 7, c4 = i & 127;
            hi_store4(((const float4*)(Whh + (size_t)perm_orig(row) * LH))[c4], g_whhp_hi, (size_t)i * 4);
        }
        break;
    case 7:
        if (i < NG) { int o = perm_orig(i); g_biasp[i] = bih[o] + bhh[o]; }
        break;
    }
}

// ----------------------------------------------------------------------------
__global__ __launch_bounds__(256)
void init_state_kernel(const float* __restrict__ h0, const float* __restrict__ c0,
                       const int* __restrict__ done0,
                       __half* __restrict__ hhi, float* __restrict__ c)
{
    int idx = blockIdx.x * 256 + threadIdx.x;
    if (blockIdx.x == 0 && threadIdx.x < 8) g_bar[threadIdx.x] = 0u;
    if (idx < BB * LH) {
        float m = 1.0f - (float)done0[idx >> 9];
        hhi[idx] = __float2half_rn(h0[idx] * m);
        c[idx] = c0[idx] * m;
    }
}

// ----------------------------------------------------------------------------
// HMMA GEMM: C = (Ahi [+Alo])@Bhi^T + b1
// MODE 0: linear -> C (+Chi/Clo)      MODE 1: tanh -> C/Chi/Clo
// MODE 2: fused softmax partials      MODE 3: fused critic dot partials (w2)
// ALO: include A_lo product (2-product) or pure-fp16 A (1-product)
// ----------------------------------------------------------------------------
#define ARR_BYTES 10240u
#define BUF_BYTES 30720u
#define G_SMEM 70656

template<int MODE, bool ALO>
__global__ __launch_bounds__(256, 2)
void gemm16_kernel(const __half* __restrict__ Ahi, const __half* __restrict__ Alo,
                   const __half* __restrict__ Bhi,
                   const float* __restrict__ b1,
                   float* __restrict__ C, __half* __restrict__ Chi, __half* __restrict__ Clo,
                   __half* __restrict__ C16, float4* __restrict__ part,
                   const float* __restrict__ w2,
                   int M, int N, int K)
{
    extern __shared__ __align__(16) char smem[];
    const uint32_t sb = smem_u32(smem);
    const int tid = threadIdx.x;
    const int lane = tid & 31, wid = tid >> 5;
    const int m0 = blockIdx.y * 128, n0 = blockIdx.x * 128;
    const int wm = (wid >> 2) * 64, wn = (wid & 3) * 32;

    float acc[4][4][4];
#pragma unroll
    for (int a = 0; a < 4; a++)
#pragma unroll
        for (int b = 0; b < 4; b++)
#pragma unroll
            for (int c = 0; c < 4; c++) acc[a][b][c] = 0.0f;

    const int NCH = K >> 5;
    const int NLD = ALO ? 6 : 4;   // 16B pieces / 256 threads

    auto issue_chunk = [&](int c) {
        const uint32_t bufb = (uint32_t)(c & 1) * BUF_BYTES;
        const int k0 = c * 32;
#pragma unroll
        for (int i = 0; i < 6; i++) {
            if (i >= NLD) break;
            int p = tid + i * 256;
            int sel = p >> 9;          // ALO: 0=Ahi 1=Alo 2=Bhi ; !ALO: 0=Ahi 1=Bhi
            int q = p & 511;
            int r = q >> 2;
            int ch = (q & 3) * 8;
            const __half* base;
            uint32_t darr;
            if (ALO) { base = (sel == 0 ? Ahi : sel == 1 ? Alo : Bhi); darr = (uint32_t)sel; }
            else     { base = (sel == 0 ? Ahi : Bhi); darr = (sel == 0 ? 0u : 2u); }
            int grow = ((ALO ? sel < 2 : sel == 0) ? m0 : n0) + r;
            const __half* src = base + (size_t)grow * K + k0 + ch;
            uint32_t dst = sb + bufb + darr * ARR_BYTES
                         + (uint32_t)r * 80u + (uint32_t)ch * 2u;
            cp16(dst, src);
        }
        CP_COMMIT();
    };

    issue_chunk(0);

    for (int c = 0; c < NCH; c++) {
        if (c + 1 < NCH) { issue_chunk(c + 1); CP_WAIT1(); }
        else             { CP_WAIT0(); }
        __syncthreads();

        const uint32_t abase = sb + (uint32_t)(c & 1) * BUF_BYTES;
#pragma unroll
        for (int ks = 0; ks < 2; ks++) {
            const uint32_t kcol = (uint32_t)(ks * 16 + (lane >> 4) * 8) * 2u;
            uint32_t bh[4][2];
#pragma unroll
            for (int ng = 0; ng < 2; ng++) {
                uint32_t row = (uint32_t)(wn + ng * 16 + ((lane >> 3) & 1) * 8 + (lane & 7));
                uint32_t addr = abase + 2u * ARR_BYTES + row * 80u + kcol;
                uint32_t r4[4];
                ldsm_x4(r4, addr);
                bh[ng * 2 + 0][0] = r4[0]; bh[ng * 2 + 0][1] = r4[2];
                bh[ng * 2 + 1][0] = r4[1]; bh[ng * 2 + 1][1] = r4[3];
            }
#pragma unroll
            for (int mi = 0; mi < 4; mi++) {
                uint32_t aaddr = abase + (uint32_t)(wm + mi * 16 + (lane & 15)) * 80u + kcol;
                uint32_t ah[4];
                ldsm_x4(ah, aaddr);
                uint32_t al[4];
                if (ALO) ldsm_x4(al, aaddr + ARR_BYTES);
#pragma unroll
                for (int ni = 0; ni < 4; ni++) {
                    mma16816(acc[mi][ni], ah, bh[ni][0], bh[ni][1]);
                    if (ALO) mma16816(acc[mi][ni], al, bh[ni][0], bh[ni][1]);
                }
            }
        }
        __syncthreads();
    }

    if (MODE == 2) {
        float* st = (float*)smem;                     // 128 x 132 fp32
        float3* pr = (float3*)(smem + 128 * 132 * 4); // 256 partials
#pragma unroll
        for (int ni = 0; ni < 4; ni++) {
            int col = n0 + wn + ni * 8 + (lane & 3) * 2;
            int jc = wn + ni * 8 + (lane & 3) * 2;
            if (col >= N) continue;
            float bb0 = b1[col], bb1 = b1[col + 1];
#pragma unroll
            for (int mi = 0; mi < 4; mi++) {
                int rloc = wm + mi * 16 + (lane >> 2);
#pragma unroll
                for (int h = 0; h < 2; h++) {
                    st[(rloc + h * 8) * 132 + jc]     = acc[mi][ni][h * 2 + 0] + bb0;
                    st[(rloc + h * 8) * 132 + jc + 1] = acc[mi][ni][h * 2 + 1] + bb1;
                }
            }
        }
        __syncthreads();
        {
            int rloc = tid >> 1;
            int half = tid & 1;
            float m = -3.402823e38f, s = 0.f, t = 0.f;
#pragma unroll 4
            for (int j = 0; j < 64; j++) {
                int jc = half * 64 + j;
                if (n0 + jc < N) m = fmaxf(m, st[rloc * 132 + jc]);
            }
#pragma unroll 4
            for (int j = 0; j < 64; j++) {
                int jc = half * 64 + j;
                if (n0 + jc < N) {
                    float l = st[rloc * 132 + jc];
                    float e = expf(l - m);
                    s += e; t += e * l;
                }
            }
            pr[tid] = make_float3(m, s, t);
        }
        __syncthreads();
        if (tid < 128) {
            float3 a = pr[tid * 2], b = pr[tid * 2 + 1];
            float m = fmaxf(a.x, b.x);
            float ea = expf(a.x - m), eb = expf(b.x - m);
            part[(size_t)(m0 + tid) * 8 + blockIdx.x] =
                make_float4(m, a.y * ea + b.y * eb, a.z * ea + b.z * eb, 0.f);
        }
        for (int i = tid; i < 128 * 64; i += 256) {
            int rloc = i >> 6;
            int j2 = (i & 63) * 2;
            int col = n0 + j2;
            if (col < N) {
                __half2 hv = __floats2half2_rn(st[rloc * 132 + j2],
                                               (col + 1 < N) ? st[rloc * 132 + j2 + 1] : 0.f);
                *(__half2*)&C16[(size_t)(m0 + rloc) * NAP + col] = hv;
            }
        }
        return;
    }

    if (MODE == 3) {
        float* smp = (float*)smem;  // 128 x 4
        float ps[8];
#pragma unroll
        for (int i = 0; i < 8; i++) ps[i] = 0.f;
#pragma unroll
        for (int ni = 0; ni < 4; ni++) {
            int col = n0 + wn + ni * 8 + (lane & 3) * 2;
            float bb0 = b1[col], bb1 = b1[col + 1];
            float w0 = w2[col], w1 = w2[col + 1];
#pragma unroll
            for (int mi = 0; mi < 4; mi++) {
#pragma unroll
                for (int h = 0; h < 2; h++) {
                    float v0 = tanhf(acc[mi][ni][h * 2 + 0] + bb0);
                    float v1 = tanhf(acc[mi][ni][h * 2 + 1] + bb1);
                    ps[mi * 2 + h] += v0 * w0 + v1 * w1;
                }
            }
        }
#pragma unroll
        for (int i = 0; i < 8; i++) {
            ps[i] += __shfl_xor_sync(0xffffffffu, ps[i], 1);
            ps[i] += __shfl_xor_sync(0xffffffffu, ps[i], 2);
        }
        if ((lane & 3) == 0) {
#pragma unroll
            for (int mi = 0; mi < 4; mi++)
#pragma unroll
                for (int h = 0; h < 2; h++) {
                    int rloc = wm + mi * 16 + (lane >> 2) + h * 8;
                    smp[rloc * 4 + (wid & 3)] = ps[mi * 2 + h];
                }
        }
        __syncthreads();
        if (tid < 128)
            part[(size_t)(m0 + tid) * 4 + blockIdx.x] =
                make_float4(smp[tid * 4], smp[tid * 4 + 1], smp[tid * 4 + 2], smp[tid * 4 + 3]);
        return;
    }

    // MODE 0/1 epilogue
#pragma unroll
    for (int ni = 0; ni < 4; ni++) {
        int col = n0 + wn + ni * 8 + (lane & 3) * 2;
        if (col >= N) continue;
        float bb0 = b1[col], bb1 = b1[col + 1];
#pragma unroll
        for (int mi = 0; mi < 4; mi++) {
            int r0 = m0 + wm + mi * 16 + (lane >> 2);
#pragma unroll
            for (int h = 0; h < 2; h++) {
                int rr = r0 + h * 8;
                float v0 = acc[mi][ni][h * 2 + 0] + bb0;
                float v1 = acc[mi][ni][h * 2 + 1] + bb1;
                if (MODE == 1) { v0 = tanhf(v0); v1 = tanhf(v1); }
                size_t base = (size_t)rr * N + col;
                if (C) *(float2*)&C[base] = make_float2(v0, v1);
                if (Chi) {
                    __half2 hh = __floats2half2_rn(v0, v1);
                    *(__half2*)&Chi[base] = hh;
                    if (Clo) {
                        float2 hf = __half22float2(hh);
                        *(__half2*)&Clo[base] = __floats2half2_rn(v0 - hf.x, v1 - hf.y);
                    }
                }
            }
        }
    }
}

// ----------------------------------------------------------------------------
// PERSISTENT LSTM scan, W resident in SMEM, h pure fp16 (1-product).
// SMEM: [W: 128 x 512 halfs, pitch 1040 = 133120 B][A hi: 32 x 512, 33280 B]
// gsm overlays A. One cp.async batch + one sync per step; MMA sync-free.
// ----------------------------------------------------------------------------
#define S_A     133120u
#define LSTM_SMEM 166400

__global__ __launch_bounds__(256, 1)
void lstm_persist(const __half* __restrict__ Wh,
                  const float* __restrict__ xg,
                  const int*   __restrict__ done,
                  __half* __restrict__ hmhi,
                  float* __restrict__ c_buf,
                  const float* __restrict__ h2,
                  __half* __restrict__ nhhi,
                  int T)
{
    extern __shared__ __align__(16) char smem[];
    const uint32_t sb = smem_u32(smem);
    float* gsm = (float*)(smem + S_A);   // overlay on A region

    const int tid = threadIdx.x;
    const int lane = tid & 31, wid = tid >> 5;
    const int n0 = blockIdx.x * 128;
    const int lbase = blockIdx.x * 32;
    const int r0 = blockIdx.y * 32;
    const int rb = blockIdx.y;
    const int wm16 = (wid & 1) * 16, wn32 = (wid >> 1) * 32;

    // resident W slice: 128 rows x 512 halfs, pitch 1040 B
#pragma unroll
    for (int j = 0; j < 32; j++) {
        int p = tid + j * 256;
        int row = p >> 6, c8 = (p & 63) * 8;
        cp16(sb + (uint32_t)row * 1040u + (uint32_t)c8 * 2u,
             Wh + (size_t)(n0 + row) * LH + c8);
    }
    CP_COMMIT(); CP_WAIT0();
    __syncthreads();

    for (int t = 0; t < T; t++) {
        if (t > 0) {
            if (tid == 0) {
                unsigned int need = (unsigned int)(16 * t);
                while (atomicAdd(&g_bar[rb], 0u) < need) { __nanosleep(100); }
            }
            __syncthreads();
            __threadfence();
        }

        const __half* hhi_in = hmhi + (size_t)(t & 1) * BB * LH;
        const float* xg_t = xg + (size_t)t * BB * NG;
        const float* h2_t = h2 + (size_t)t * BB * LH;

        // load h tile (hi only): 32 x 512 halfs = 2048 16B pieces
#pragma unroll
        for (int j = 0; j < 8; j++) {
            int p = tid + j * 256;
            int row = p >> 6, c8 = (p & 63) * 8;
            cp16(sb + S_A + (uint32_t)row * 1040u + (uint32_t)c8 * 2u,
                 hhi_in + (size_t)(r0 + row) * LH + c8);
        }
        CP_COMMIT(); CP_WAIT0();
        __syncthreads();

        float acc[4][4];
#pragma unroll
        for (int a = 0; a < 4; a++)
#pragma unroll
            for (int b = 0; b < 4; b++) acc[a][b] = 0.0f;

        // sync-free MMA loop
#pragma unroll 4
        for (int c = 0; c < 16; c++) {
#pragma unroll
            for (int ks = 0; ks < 2; ks++) {
                const uint32_t kcol = (uint32_t)c * 64u + (uint32_t)(ks * 16 + (lane >> 4) * 8) * 2u;
                uint32_t bh[4][2];
#pragma unroll
                for (int ng = 0; ng < 2; ng++) {
                    uint32_t row = (uint32_t)(wn32 + ng * 16 + ((lane >> 3) & 1) * 8 + (lane & 7));
                    uint32_t r4[4];
                    ldsm_x4(r4, sb + row * 1040u + kcol);
                    bh[ng * 2 + 0][0] = r4[0]; bh[ng * 2 + 0][1] = r4[2];
                    bh[ng * 2 + 1][0] = r4[1]; bh[ng * 2 + 1][1] = r4[3];
                }
                uint32_t ah[4];
                ldsm_x4(ah, sb + S_A + (uint32_t)(wm16 + (lane & 15)) * 1040u + kcol);
#pragma unroll
                for (int ni = 0; ni < 4; ni++)
                    mma16816(acc[ni], ah, bh[ni][0], bh[ni][1]);
            }
        }
        __syncthreads();   // A reads done before gsm overlay writes

#pragma unroll
        for (int ni = 0; ni < 4; ni++) {
            int col = wn32 + ni * 8 + (lane & 3) * 2;
            int row0 = wm16 + (lane >> 2);
            const float* xr0 = xg_t + (size_t)(r0 + row0) * NG + n0 + col;
            gsm[row0 * 132 + col]     = acc[ni][0] + xr0[0];
            gsm[row0 * 132 + col + 1] = acc[ni][1] + xr0[1];
            const float* xr1 = xr0 + 8 * NG;
            gsm[(row0 + 8) * 132 + col]     = acc[ni][2] + xr1[0];
            gsm[(row0 + 8) * 132 + col + 1] = acc[ni][3] + xr1[1];
        }
        __syncthreads();

        __half* hhi_out = hmhi + (size_t)((t + 1) & 1) * BB * LH;
        __half* nhhi_t = nhhi + (size_t)t * BB * LH;
        const int* done_next = (t + 1 < T) ? (done + (size_t)(t + 1) * BB) : nullptr;

        float hn_s[4];
#pragma unroll
        for (int q = 0; q < 4; q++) {
            int cell = tid + q * 256;
            int r = cell >> 5;
            int li = cell & 31;
            float iv = gsm[r * 132 + li];
            float fv = gsm[r * 132 + 32 + li];
            float gv = gsm[r * 132 + 64 + li];
            float ov = gsm[r * 132 + 96 + li];
            size_t gi = (size_t)(r0 + r) * LH + lbase + li;
            float cp = c_buf[gi];
            float cn = sigm(fv) * cp + sigm(iv) * tanhf(gv);
            float hn = sigm(ov) * tanhf(cn);
            hn_s[q] = hn;
            float mn = done_next ? (1.0f - (float)done_next[r0 + r]) : 1.0f;
            c_buf[gi] = cn * mn;
            hhi_out[gi] = __float2half_rn(hn * mn);
        }
        __threadfence();
        __syncthreads();
        if (tid == 0) atomicAdd(&g_bar[rb], 1u);

        // deferred: nh = hn + h2 (hi only; heads are 1-product)
#pragma unroll
        for (int q = 0; q < 4; q++) {
            int cell = tid + q * 256;
            int r = cell >> 5;
            int li = cell & 31;
            size_t gi = (size_t)(r0 + r) * LH + lbase + li;
            nhhi_t[gi] = __float2half_rn(hn_s[q] + h2_t[gi]);
        }
    }
}

// ----------------------------------------------------------------------------
// final combine: lp + ent + v
// ----------------------------------------------------------------------------
__global__ __launch_bounds__(256)
void heads_final_kernel(const float4* __restrict__ part, const __half* __restrict__ l16,
                        const int* __restrict__ action,
                        const float4* __restrict__ partc, const float* __restrict__ bc2,
                        float* __restrict__ out, int TBn)
{
    int row = blockIdx.x * 256 + threadIdx.x;
    if (row >= TBn) return;
    float4 p[8];
#pragma unroll
    for (int i = 0; i < 8; i++) p[i] = part[(size_t)row * 8 + i];
    float M = p[0].x;
#pragma unroll
    for (int i = 1; i < 8; i++) M = fmaxf(M, p[i].x);
    float S = 0.f, Tm = 0.f;
#pragma unroll
    for (int i = 0; i < 8; i++) {
        float e = expf(p[i].x - M);
        S += p[i].y * e;
        Tm += p[i].z * e;
    }
    float lse = M + logf(S);
    float la = __half2float(l16[(size_t)row * NAP + action[row]]);
    out[row] = la - lse;
    out[TBn + row] = lse - Tm / S;

    float v = bc2[0];
#pragma unroll
    for (int i = 0; i < 4; i++) {
        float4 c = partc[(size_t)row * 4 + i];
        v += c.x + c.y + c.z + c.w;
    }
    out[2 * TBn + row] = v;
}

// ----------------------------------------------------------------------------
// host launcher
// ----------------------------------------------------------------------------
extern "C" void kernel_launch(void* const* d_in, const int* in_sizes, int n_in,
                              void* d_out, int out_size)
{
    const float* x    = (const float*)d_in[0];
    const int*   done = (const int*)d_in[1];
    const int*   act  = (const int*)d_in[2];
    const float* W_t1 = (const float*)d_in[4];
    const float* b_t1 = (const float*)d_in[5];
    const float* W_t2 = (const float*)d_in[6];
    const float* b_t2 = (const float*)d_in[7];
    const float* Wih  = (const float*)d_in[8];
    const float* Whh  = (const float*)d_in[9];
    const float* bih  = (const float*)d_in[10];
    const float* bhh  = (const float*)d_in[11];
    const float* Wa1  = (const float*)d_in[12];
    const float* ba1  = (const float*)d_in[13];
    const float* Wa2  = (const float*)d_in[14];
    const float* ba2  = (const float*)d_in[15];
    const float* Wc1  = (const float*)d_in[16];
    const float* bc1  = (const float*)d_in[17];
    const float* Wc2  = (const float*)d_in[18];
    const float* bc2  = (const float*)d_in[19];
    const float* h0   = (const float*)d_in[20];
    const float* c0   = (const float*)d_in[21];

    const int TBn = in_sizes[0] / DI;   // 65536
    const int T = TBn / BB;             // 256
    float* out = (float*)d_out;

    float *h2, *xg, *cbuf, *biasp;
    float4 *part, *partc;
    __half* l16;
    cudaGetSymbolAddress((void**)&h2,    g_h2);
    cudaGetSymbolAddress((void**)&xg,    g_xg);
    cudaGetSymbolAddress((void**)&cbuf,  g_cbuf);
    cudaGetSymbolAddress((void**)&biasp, g_biasp);
    cudaGetSymbolAddress((void**)&part,  g_part);
    cudaGetSymbolAddress((void**)&partc, g_partc);
    cudaGetSymbolAddress((void**)&l16,   g_l16);

    __half *xhi, *xlo, *b1hi, *b1lo, *h2hi, *h2lo, *nhhi, *hmhi;
    __half *wt1h, *wt2h, *wihh, *whhh, *wa1h, *wa2h, *wc1h;
    cudaGetSymbolAddress((void**)&xhi,  g_x_hi);   cudaGetSymbolAddress((void**)&xlo,  g_x_lo);
    cudaGetSymbolAddress((void**)&b1hi, g_b1_hi);  cudaGetSymbolAddress((void**)&b1lo, g_b1_lo);
    cudaGetSymbolAddress((void**)&h2hi, g_h2_hi);  cudaGetSymbolAddress((void**)&h2lo, g_h2_lo);
    cudaGetSymbolAddress((void**)&nhhi, g_nh_hi);
    cudaGetSymbolAddress((void**)&hmhi, g_hm_hi);
    cudaGetSymbolAddress((void**)&wt1h, g_wt1_hi);
    cudaGetSymbolAddress((void**)&wt2h, g_wt2_hi);
    cudaGetSymbolAddress((void**)&wihh, g_wihp_hi);
    cudaGetSymbolAddress((void**)&whhh, g_whhp_hi);
    cudaGetSymbolAddress((void**)&wa1h, g_wa1_hi);
    cudaGetSymbolAddress((void**)&wa2h, g_wa2_hi);
    cudaGetSymbolAddress((void**)&wc1h, g_wc1_hi);

    cudaFuncSetAttribute((const void*)gemm16_kernel<0, true>,  cudaFuncAttributeMaxDynamicSharedMemorySize, G_SMEM);
    cudaFuncSetAttribute((const void*)gemm16_kernel<1, true>,  cudaFuncAttributeMaxDynamicSharedMemorySize, G_SMEM);
    cudaFuncSetAttribute((const void*)gemm16_kernel<1, false>, cudaFuncAttributeMaxDynamicSharedMemorySize, G_SMEM);
    cudaFuncSetAttribute((const void*)gemm16_kernel<2, false>, cudaFuncAttributeMaxDynamicSharedMemorySize, G_SMEM);
    cudaFuncSetAttribute((const void*)gemm16_kernel<3, false>, cudaFuncAttributeMaxDynamicSharedMemorySize, G_SMEM);
    cudaFuncSetAttribute((const void*)lstm_persist, cudaFuncAttributeMaxDynamicSharedMemorySize, LSTM_SMEM);

    const dim3 blk(256);

    splitx_kernel<<<TBn * DI / 4 / 256, blk>>>(x, xhi, xlo, TBn * DI / 4);
    prep_kernel<<<dim3(1024, 8), blk>>>(W_t1, W_t2, Wa1, Wc1, Wa2, Wih, Whh, bih, bhh);
    init_state_kernel<<<(BB * LH + 255) / 256, blk>>>(h0, c0, done, hmhi, cbuf);

    const int MY = TBn / 128;
    // trunk (2-product: feeds recurrence)
    gemm16_kernel<1, true><<<dim3(4, MY), blk, G_SMEM>>>(
        xhi, xlo, wt1h, b_t1, nullptr, b1hi, b1lo, nullptr, nullptr, nullptr, TBn, LH, DI);
    gemm16_kernel<1, true><<<dim3(4, MY), blk, G_SMEM>>>(
        b1hi, b1lo, wt2h, b_t2, h2, h2hi, h2lo, nullptr, nullptr, nullptr, TBn, LH, LH);
    gemm16_kernel<0, true><<<dim3(16, MY), blk, G_SMEM>>>(
        h2hi, h2lo, wihh, biasp, xg, nullptr, nullptr, nullptr, nullptr, nullptr, TBn, NG, LH);

    // persistent lstm scan (W resident, h fp16)
    lstm_persist<<<dim3(16, 8), blk, LSTM_SMEM>>>(
        whhh, xg, done, hmhi, cbuf, h2, nhhi, T);

    // actor head (1-product) + fused softmax partials
    gemm16_kernel<1, false><<<dim3(4, MY), blk, G_SMEM>>>(
        nhhi, nullptr, wa1h, ba1, nullptr, b1hi, nullptr, nullptr, nullptr, nullptr, TBn, LH, LH);
    gemm16_kernel<2, false><<<dim3(8, MY), blk, G_SMEM>>>(
        b1hi, nullptr, wa2h, ba2, nullptr, nullptr, nullptr, l16, part, nullptr, TBn, NA, LH);

    // critic head (1-product) fully fused
    gemm16_kernel<3, false><<<dim3(4, MY), blk, G_SMEM>>>(
        nhhi, nullptr, wc1h, bc1, nullptr, nullptr, nullptr, nullptr, partc, Wc2, TBn, LH, LH);

    // final combine: lp, ent, v
    heads_final_kernel<<<(TBn + 255) / 256, blk>>>(part, l16, act, partc, bc2, out, TBn);
}

// round 16
// speedup vs baseline: 4.7335x; 1.1797x over previous
#include <cuda_runtime.h>
#include <cuda_fp16.h>
#include <math.h>
#include <stdint.h>

// ----------------------------------------------------------------------------
// Problem constants
// ----------------------------------------------------------------------------
#define LH 512
#define DI 512
#define NA 1000
#define NAP 1024
#define NG 2048
#define BB 256
#define TBMAX 65536

// ----------------------------------------------------------------------------
// PTX helpers (base-target-safe)
// ----------------------------------------------------------------------------
__device__ __forceinline__ uint32_t smem_u32(const void* p) {
    uint32_t a;
    asm("{ .reg .u64 t; cvta.to.shared.u64 t, %1; cvt.u32.u64 %0, t; }" : "=r"(a) : "l"(p));
    return a;
}
__device__ __forceinline__ void ldsm_x4(uint32_t (&r)[4], uint32_t addr) {
    asm volatile("ldmatrix.sync.aligned.m8n8.x4.shared.b16 {%0,%1,%2,%3}, [%4];"
                 : "=r"(r[0]), "=r"(r[1]), "=r"(r[2]), "=r"(r[3]) : "r"(addr));
}
__device__ __forceinline__ void mma16816(float (&d)[4], const uint32_t (&a)[4],
                                         uint32_t b0, uint32_t b1) {
    asm volatile(
        "mma.sync.aligned.m16n8k16.row.col.f32.f16.f16.f32 "
        "{%0,%1,%2,%3},{%4,%5,%6,%7},{%8,%9},{%0,%1,%2,%3};"
        : "+f"(d[0]), "+f"(d[1]), "+f"(d[2]), "+f"(d[3])
        : "r"(a[0]), "r"(a[1]), "r"(a[2]), "r"(a[3]), "r"(b0), "r"(b1));
}
__device__ __forceinline__ void cp16(uint32_t dst, const void* src) {
    asm volatile("cp.async.cg.shared.global [%0], [%1], 16;" :: "r"(dst), "l"(src) : "memory");
}
#define CP_COMMIT() asm volatile("cp.async.commit_group;" ::: "memory")
#define CP_WAIT1()  asm volatile("cp.async.wait_group 1;" ::: "memory")
#define CP_WAIT0()  asm volatile("cp.async.wait_group 0;" ::: "memory")

__host__ __device__ __forceinline__ int perm_orig(int p) {
    return (((p & 127) >> 5) << 9) + ((p >> 7) << 5) + (p & 31);
}

// ----------------------------------------------------------------------------
// Scratch
// ----------------------------------------------------------------------------
__device__ __align__(16) float4 g_partc[(size_t)TBMAX * 4];     // critic partials
__device__ float g_h2  [(size_t)TBMAX * LH];
__device__ float g_xg  [(size_t)TBMAX * NG];
__device__ float g_cbuf[BB * LH];
__device__ float g_biasp[NG];
__device__ unsigned int g_bar[8];
__device__ __align__(16) float4 g_part[(size_t)TBMAX * 8];      // softmax partials
__device__ __align__(16) __half g_l16[(size_t)TBMAX * NAP];     // fp16 logits

// pure fp16 operands (no hi/lo splits anywhere)
__device__ __align__(16) __half g_x_hi [(size_t)TBMAX * DI];
__device__ __align__(16) __half g_b1_hi[(size_t)TBMAX * LH];
__device__ __align__(16) __half g_h2_hi[(size_t)TBMAX * LH];
__device__ __align__(16) __half g_nh_hi[(size_t)TBMAX * LH];
__device__ __align__(16) __half g_hm_hi[2 * BB * LH];
__device__ __align__(16) __half g_wt1_hi[LH * DI];
__device__ __align__(16) __half g_wt2_hi[LH * LH];
__device__ __align__(16) __half g_wihp_hi[NG * LH];
__device__ __align__(16) __half g_whhp_hi[NG * LH];
__device__ __align__(16) __half g_wa1_hi[LH * LH];
__device__ __align__(16) __half g_wa2_hi[NAP * LH];
__device__ __align__(16) __half g_wc1_hi[LH * LH];

__device__ __forceinline__ float sigm(float x) { return 1.0f / (1.0f + expf(-x)); }

__device__ __forceinline__ void hi_store4(float4 v, __half* H, size_t idx) {
    *(__half2*)&H[idx] = __floats2half2_rn(v.x, v.y);
    *(__half2*)&H[idx + 2] = __floats2half2_rn(v.z, v.w);
}

// ----------------------------------------------------------------------------
// x convert: fp32 -> fp16 (no split)
// ----------------------------------------------------------------------------
__global__ __launch_bounds__(256)
void convx_kernel(const float* __restrict__ X, __half* __restrict__ H, int n4)
{
    int i = blockIdx.x * 256 + threadIdx.x;
    if (i < n4) hi_store4(((const float4*)X)[i], H, (size_t)i * 4);
}

// ----------------------------------------------------------------------------
// weight prep (fp16; permutation for Wih/Whh)
// ----------------------------------------------------------------------------
__global__ __launch_bounds__(256)
void prep_kernel(const float* __restrict__ W_t1, const float* __restrict__ W_t2,
                 const float* __restrict__ Wa1, const float* __restrict__ Wc1,
                 const float* __restrict__ Wa2,
                 const float* __restrict__ Wih, const float* __restrict__ Whh,
                 const float* __restrict__ bih, const float* __restrict__ bhh)
{
    const int i = blockIdx.x * 256 + threadIdx.x;
    const int sec = blockIdx.y;
    switch (sec) {
    case 0: if (i < LH * DI / 4) hi_store4(((const float4*)W_t1)[i], g_wt1_hi, (size_t)i * 4); break;
    case 1: if (i < LH * LH / 4) hi_store4(((const float4*)W_t2)[i], g_wt2_hi, (size_t)i * 4); break;
    case 2: if (i < LH * LH / 4) hi_store4(((const float4*)Wa1)[i], g_wa1_hi, (size_t)i * 4); break;
    case 3: if (i < LH * LH / 4) hi_store4(((const float4*)Wc1)[i], g_wc1_hi, (size_t)i * 4); break;
    case 4:
        if (i < NAP * LH / 4) {
            if (i < NA * LH / 4) hi_store4(((const float4*)Wa2)[i], g_wa2_hi, (size_t)i * 4);
            else {
                __half2 z = __floats2half2_rn(0.f, 0.f);
                *(__half2*)&g_wa2_hi[(size_t)i * 4] = z; *(__half2*)&g_wa2_hi[(size_t)i * 4 + 2] = z;
            }
        }
        break;
    case 5:
        if (i < NG * LH / 4) {
            int row = i >> 7, c4 = i & 127;
            hi_store4(((const float4*)(Wih + (size_t)perm_orig(row) * LH))[c4], g_wihp_hi, (size_t)i * 4);
        }
        break;
    case 6:
        if (i < NG * LH / 4) {
            int row = i >> 7, c4 = i & 127;
            hi_store4(((const float4*)(Whh + (size_t)perm_orig(row) * LH))[c4], g_whhp_hi, (size_t)i * 4);
        }
        break;
    case 7:
        if (i < NG) { int o = perm_orig(i); g_biasp[i] = bih[o] + bhh[o]; }
        break;
    }
}

// ----------------------------------------------------------------------------
__global__ __launch_bounds__(256)
void init_state_kernel(const float* __restrict__ h0, const float* __restrict__ c0,
                       const int* __restrict__ done0,
                       __half* __restrict__ hhi, float* __restrict__ c)
{
    int idx = blockIdx.x * 256 + threadIdx.x;
    if (blockIdx.x == 0 && threadIdx.x < 8) g_bar[threadIdx.x] = 0u;
    if (idx < BB * LH) {
        float m = 1.0f - (float)done0[idx >> 9];
        hhi[idx] = __float2half_rn(h0[idx] * m);
        c[idx] = c0[idx] * m;
    }
}

// ----------------------------------------------------------------------------
// HMMA pure-fp16 GEMM: C = A@B^T + b1
// MODE 0: linear -> C (+Chi)      MODE 1: tanh -> C/Chi
// MODE 2: fused softmax partials  MODE 3: fused critic dot partials (w2)
// SMEM per buffer: [A][B] = 2 x 10240; double buffered (MODE2 overlay needs 70656)
// ----------------------------------------------------------------------------
#define ARR_BYTES 10240u
#define BUF_BYTES 20480u
#define G_SMEM 70656

template<int MODE>
__global__ __launch_bounds__(256, 2)
void gemm16_kernel(const __half* __restrict__ A, const __half* __restrict__ B,
                   const float* __restrict__ b1,
                   float* __restrict__ C, __half* __restrict__ Chi,
                   __half* __restrict__ C16, float4* __restrict__ part,
                   const float* __restrict__ w2,
                   int M, int N, int K)
{
    extern __shared__ __align__(16) char smem[];
    const uint32_t sb = smem_u32(smem);
    const int tid = threadIdx.x;
    const int lane = tid & 31, wid = tid >> 5;
    const int m0 = blockIdx.y * 128, n0 = blockIdx.x * 128;
    const int wm = (wid >> 2) * 64, wn = (wid & 3) * 32;

    float acc[4][4][4];
#pragma unroll
    for (int a = 0; a < 4; a++)
#pragma unroll
        for (int b = 0; b < 4; b++)
#pragma unroll
            for (int c = 0; c < 4; c++) acc[a][b][c] = 0.0f;

    const int NCH = K >> 5;

    auto issue_chunk = [&](int c) {
        const uint32_t bufb = (uint32_t)(c & 1) * BUF_BYTES;
        const int k0 = c * 32;
#pragma unroll
        for (int i = 0; i < 4; i++) {
            int p = tid + i * 256;
            int sel = p >> 9;          // 0=A, 1=B
            int q = p & 511;
            int r = q >> 2;
            int ch = (q & 3) * 8;
            int grow = (sel == 0 ? m0 : n0) + r;
            const __half* src = (sel == 0 ? A : B) + (size_t)grow * K + k0 + ch;
            uint32_t dst = sb + bufb + (uint32_t)sel * ARR_BYTES
                         + (uint32_t)r * 80u + (uint32_t)ch * 2u;
            cp16(dst, src);
        }
        CP_COMMIT();
    };

    issue_chunk(0);

    for (int c = 0; c < NCH; c++) {
        if (c + 1 < NCH) { issue_chunk(c + 1); CP_WAIT1(); }
        else             { CP_WAIT0(); }
        __syncthreads();

        const uint32_t abase = sb + (uint32_t)(c & 1) * BUF_BYTES;
#pragma unroll
        for (int ks = 0; ks < 2; ks++) {
            const uint32_t kcol = (uint32_t)(ks * 16 + (lane >> 4) * 8) * 2u;
            uint32_t bh[4][2];
#pragma unroll
            for (int ng = 0; ng < 2; ng++) {
                uint32_t row = (uint32_t)(wn + ng * 16 + ((lane >> 3) & 1) * 8 + (lane & 7));
                uint32_t addr = abase + ARR_BYTES + row * 80u + kcol;
                uint32_t r4[4];
                ldsm_x4(r4, addr);
                bh[ng * 2 + 0][0] = r4[0]; bh[ng * 2 + 0][1] = r4[2];
                bh[ng * 2 + 1][0] = r4[1]; bh[ng * 2 + 1][1] = r4[3];
            }
#pragma unroll
            for (int mi = 0; mi < 4; mi++) {
                uint32_t ah[4];
                ldsm_x4(ah, abase + (uint32_t)(wm + mi * 16 + (lane & 15)) * 80u + kcol);
#pragma unroll
                for (int ni = 0; ni < 4; ni++)
                    mma16816(acc[mi][ni], ah, bh[ni][0], bh[ni][1]);
            }
        }
        __syncthreads();
    }

    if (MODE == 2) {
        float* st = (float*)smem;                     // 128 x 132 fp32
        float3* pr = (float3*)(smem + 128 * 132 * 4); // 256 partials
#pragma unroll
        for (int ni = 0; ni < 4; ni++) {
            int col = n0 + wn + ni * 8 + (lane & 3) * 2;
            int jc = wn + ni * 8 + (lane & 3) * 2;
            if (col >= N) continue;
            float bb0 = b1[col], bb1 = b1[col + 1];
#pragma unroll
            for (int mi = 0; mi < 4; mi++) {
                int rloc = wm + mi * 16 + (lane >> 2);
#pragma unroll
                for (int h = 0; h < 2; h++) {
                    st[(rloc + h * 8) * 132 + jc]     = acc[mi][ni][h * 2 + 0] + bb0;
                    st[(rloc + h * 8) * 132 + jc + 1] = acc[mi][ni][h * 2 + 1] + bb1;
                }
            }
        }
        __syncthreads();
        {
            int rloc = tid >> 1;
            int half = tid & 1;
            float m = -3.402823e38f, s = 0.f, t = 0.f;
#pragma unroll 4
            for (int j = 0; j < 64; j++) {
                int jc = half * 64 + j;
                if (n0 + jc < N) m = fmaxf(m, st[rloc * 132 + jc]);
            }
#pragma unroll 4
            for (int j = 0; j < 64; j++) {
                int jc = half * 64 + j;
                if (n0 + jc < N) {
                    float l = st[rloc * 132 + jc];
                    float e = expf(l - m);
                    s += e; t += e * l;
                }
            }
            pr[tid] = make_float3(m, s, t);
        }
        __syncthreads();
        if (tid < 128) {
            float3 a = pr[tid * 2], b = pr[tid * 2 + 1];
            float m = fmaxf(a.x, b.x);
            float ea = expf(a.x - m), eb = expf(b.x - m);
            part[(size_t)(m0 + tid) * 8 + blockIdx.x] =
                make_float4(m, a.y * ea + b.y * eb, a.z * ea + b.z * eb, 0.f);
        }
        for (int i = tid; i < 128 * 64; i += 256) {
            int rloc = i >> 6;
            int j2 = (i & 63) * 2;
            int col = n0 + j2;
            if (col < N) {
                __half2 hv = __floats2half2_rn(st[rloc * 132 + j2],
                                               (col + 1 < N) ? st[rloc * 132 + j2 + 1] : 0.f);
                *(__half2*)&C16[(size_t)(m0 + rloc) * NAP + col] = hv;
            }
        }
        return;
    }

    if (MODE == 3) {
        float* smp = (float*)smem;  // 128 x 4
        float ps[8];
#pragma unroll
        for (int i = 0; i < 8; i++) ps[i] = 0.f;
#pragma unroll
        for (int ni = 0; ni < 4; ni++) {
            int col = n0 + wn + ni * 8 + (lane & 3) * 2;
            float bb0 = b1[col], bb1 = b1[col + 1];
            float w0 = w2[col], w1 = w2[col + 1];
#pragma unroll
            for (int mi = 0; mi < 4; mi++) {
#pragma unroll
                for (int h = 0; h < 2; h++) {
                    float v0 = tanhf(acc[mi][ni][h * 2 + 0] + bb0);
                    float v1 = tanhf(acc[mi][ni][h * 2 + 1] + bb1);
                    ps[mi * 2 + h] += v0 * w0 + v1 * w1;
                }
            }
        }
#pragma unroll
        for (int i = 0; i < 8; i++) {
            ps[i] += __shfl_xor_sync(0xffffffffu, ps[i], 1);
            ps[i] += __shfl_xor_sync(0xffffffffu, ps[i], 2);
        }
        if ((lane & 3) == 0) {
#pragma unroll
            for (int mi = 0; mi < 4; mi++)
#pragma unroll
                for (int h = 0; h < 2; h++) {
                    int rloc = wm + mi * 16 + (lane >> 2) + h * 8;
                    smp[rloc * 4 + (wid & 3)] = ps[mi * 2 + h];
                }
        }
        __syncthreads();
        if (tid < 128)
            part[(size_t)(m0 + tid) * 4 + blockIdx.x] =
                make_float4(smp[tid * 4], smp[tid * 4 + 1], smp[tid * 4 + 2], smp[tid * 4 + 3]);
        return;
    }

    // MODE 0/1 epilogue
#pragma unroll
    for (int ni = 0; ni < 4; ni++) {
        int col = n0 + wn + ni * 8 + (lane & 3) * 2;
        if (col >= N) continue;
        float bb0 = b1[col], bb1 = b1[col + 1];
#pragma unroll
        for (int mi = 0; mi < 4; mi++) {
            int r0 = m0 + wm + mi * 16 + (lane >> 2);
#pragma unroll
            for (int h = 0; h < 2; h++) {
                int rr = r0 + h * 8;
                float v0 = acc[mi][ni][h * 2 + 0] + bb0;
                float v1 = acc[mi][ni][h * 2 + 1] + bb1;
                if (MODE == 1) { v0 = tanhf(v0); v1 = tanhf(v1); }
                size_t base = (size_t)rr * N + col;
                if (C) *(float2*)&C[base] = make_float2(v0, v1);
                if (Chi) *(__half2*)&Chi[base] = __floats2half2_rn(v0, v1);
            }
        }
    }
}

// ----------------------------------------------------------------------------
// PERSISTENT LSTM scan, W resident in SMEM, h pure fp16 (unchanged round 13).
// ----------------------------------------------------------------------------
#define S_A     133120u
#define LSTM_SMEM 166400

__global__ __launch_bounds__(256, 1)
void lstm_persist(const __half* __restrict__ Wh,
                  const float* __restrict__ xg,
                  const int*   __restrict__ done,
                  __half* __restrict__ hmhi,
                  float* __restrict__ c_buf,
                  const float* __restrict__ h2,
                  __half* __restrict__ nhhi,
                  int T)
{
    extern __shared__ __align__(16) char smem[];
    const uint32_t sb = smem_u32(smem);
    float* gsm = (float*)(smem + S_A);   // overlay on A region

    const int tid = threadIdx.x;
    const int lane = tid & 31, wid = tid >> 5;
    const int n0 = blockIdx.x * 128;
    const int lbase = blockIdx.x * 32;
    const int r0 = blockIdx.y * 32;
    const int rb = blockIdx.y;
    const int wm16 = (wid & 1) * 16, wn32 = (wid >> 1) * 32;

    // resident W slice: 128 rows x 512 halfs, pitch 1040 B
#pragma unroll
    for (int j = 0; j < 32; j++) {
        int p = tid + j * 256;
        int row = p >> 6, c8 = (p & 63) * 8;
        cp16(sb + (uint32_t)row * 1040u + (uint32_t)c8 * 2u,
             Wh + (size_t)(n0 + row) * LH + c8);
    }
    CP_COMMIT(); CP_WAIT0();
    __syncthreads();

    for (int t = 0; t < T; t++) {
        if (t > 0) {
            if (tid == 0) {
                unsigned int need = (unsigned int)(16 * t);
                while (atomicAdd(&g_bar[rb], 0u) < need) { __nanosleep(100); }
            }
            __syncthreads();
            __threadfence();
        }

        const __half* hhi_in = hmhi + (size_t)(t & 1) * BB * LH;
        const float* xg_t = xg + (size_t)t * BB * NG;
        const float* h2_t = h2 + (size_t)t * BB * LH;

        // load h tile (hi only)
#pragma unroll
        for (int j = 0; j < 8; j++) {
            int p = tid + j * 256;
            int row = p >> 6, c8 = (p & 63) * 8;
            cp16(sb + S_A + (uint32_t)row * 1040u + (uint32_t)c8 * 2u,
                 hhi_in + (size_t)(r0 + row) * LH + c8);
        }
        CP_COMMIT(); CP_WAIT0();
        __syncthreads();

        float acc[4][4];
#pragma unroll
        for (int a = 0; a < 4; a++)
#pragma unroll
            for (int b = 0; b < 4; b++) acc[a][b] = 0.0f;

#pragma unroll 4
        for (int c = 0; c < 16; c++) {
#pragma unroll
            for (int ks = 0; ks < 2; ks++) {
                const uint32_t kcol = (uint32_t)c * 64u + (uint32_t)(ks * 16 + (lane >> 4) * 8) * 2u;
                uint32_t bh[4][2];
#pragma unroll
                for (int ng = 0; ng < 2; ng++) {
                    uint32_t row = (uint32_t)(wn32 + ng * 16 + ((lane >> 3) & 1) * 8 + (lane & 7));
                    uint32_t r4[4];
                    ldsm_x4(r4, sb + row * 1040u + kcol);
                    bh[ng * 2 + 0][0] = r4[0]; bh[ng * 2 + 0][1] = r4[2];
                    bh[ng * 2 + 1][0] = r4[1]; bh[ng * 2 + 1][1] = r4[3];
                }
                uint32_t ah[4];
                ldsm_x4(ah, sb + S_A + (uint32_t)(wm16 + (lane & 15)) * 1040u + kcol);
#pragma unroll
                for (int ni = 0; ni < 4; ni++)
                    mma16816(acc[ni], ah, bh[ni][0], bh[ni][1]);
            }
        }
        __syncthreads();

#pragma unroll
        for (int ni = 0; ni < 4; ni++) {
            int col = wn32 + ni * 8 + (lane & 3) * 2;
            int row0 = wm16 + (lane >> 2);
            const float* xr0 = xg_t + (size_t)(r0 + row0) * NG + n0 + col;
            gsm[row0 * 132 + col]     = acc[ni][0] + xr0[0];
            gsm[row0 * 132 + col + 1] = acc[ni][1] + xr0[1];
            const float* xr1 = xr0 + 8 * NG;
            gsm[(row0 + 8) * 132 + col]     = acc[ni][2] + xr1[0];
            gsm[(row0 + 8) * 132 + col + 1] = acc[ni][3] + xr1[1];
        }
        __syncthreads();

        __half* hhi_out = hmhi + (size_t)((t + 1) & 1) * BB * LH;
        __half* nhhi_t = nhhi + (size_t)t * BB * LH;
        const int* done_next = (t + 1 < T) ? (done + (size_t)(t + 1) * BB) : nullptr;

        float hn_s[4];
#pragma unroll
        for (int q = 0; q < 4; q++) {
            int cell = tid + q * 256;
            int r = cell >> 5;
            int li = cell & 31;
            float iv = gsm[r * 132 + li];
            float fv = gsm[r * 132 + 32 + li];
            float gv = gsm[r * 132 + 64 + li];
            float ov = gsm[r * 132 + 96 + li];
            size_t gi = (size_t)(r0 + r) * LH + lbase + li;
            float cp = c_buf[gi];
            float cn = sigm(fv) * cp + sigm(iv) * tanhf(gv);
            float hn = sigm(ov) * tanhf(cn);
            hn_s[q] = hn;
            float mn = done_next ? (1.0f - (float)done_next[r0 + r]) : 1.0f;
            c_buf[gi] = cn * mn;
            hhi_out[gi] = __float2half_rn(hn * mn);
        }
        __threadfence();
        __syncthreads();
        if (tid == 0) atomicAdd(&g_bar[rb], 1u);

        // deferred: nh = hn + h2
#pragma unroll
        for (int q = 0; q < 4; q++) {
            int cell = tid + q * 256;
            int r = cell >> 5;
            int li = cell & 31;
            size_t gi = (size_t)(r0 + r) * LH + lbase + li;
            nhhi_t[gi] = __float2half_rn(hn_s[q] + h2_t[gi]);
        }
    }
}

// ----------------------------------------------------------------------------
// final combine: lp + ent + v
// ----------------------------------------------------------------------------
__global__ __launch_bounds__(256)
void heads_final_kernel(const float4* __restrict__ part, const __half* __restrict__ l16,
                        const int* __restrict__ action,
                        const float4* __restrict__ partc, const float* __restrict__ bc2,
                        float* __restrict__ out, int TBn)
{
    int row = blockIdx.x * 256 + threadIdx.x;
    if (row >= TBn) return;
    float4 p[8];
#pragma unroll
    for (int i = 0; i < 8; i++) p[i] = part[(size_t)row * 8 + i];
    float M = p[0].x;
#pragma unroll
    for (int i = 1; i < 8; i++) M = fmaxf(M, p[i].x);
    float S = 0.f, Tm = 0.f;
#pragma unroll
    for (int i = 0; i < 8; i++) {
        float e = expf(p[i].x - M);
        S += p[i].y * e;
        Tm += p[i].z * e;
    }
    float lse = M + logf(S);
    float la = __half2float(l16[(size_t)row * NAP + action[row]]);
    out[row] = la - lse;
    out[TBn + row] = lse - Tm / S;

    float v = bc2[0];
#pragma unroll
    for (int i = 0; i < 4; i++) {
        float4 c = partc[(size_t)row * 4 + i];
        v += c.x + c.y + c.z + c.w;
    }
    out[2 * TBn + row] = v;
}

// ----------------------------------------------------------------------------
// host launcher
// ----------------------------------------------------------------------------
extern "C" void kernel_launch(void* const* d_in, const int* in_sizes, int n_in,
                              void* d_out, int out_size)
{
    const float* x    = (const float*)d_in[0];
    const int*   done = (const int*)d_in[1];
    const int*   act  = (const int*)d_in[2];
    const float* W_t1 = (const float*)d_in[4];
    const float* b_t1 = (const float*)d_in[5];
    const float* W_t2 = (const float*)d_in[6];
    const float* b_t2 = (const float*)d_in[7];
    const float* Wih  = (const float*)d_in[8];
    const float* Whh  = (const float*)d_in[9];
    const float* bih  = (const float*)d_in[10];
    const float* bhh  = (const float*)d_in[11];
    const float* Wa1  = (const float*)d_in[12];
    const float* ba1  = (const float*)d_in[13];
    const float* Wa2  = (const float*)d_in[14];
    const float* ba2  = (const float*)d_in[15];
    const float* Wc1  = (const float*)d_in[16];
    const float* bc1  = (const float*)d_in[17];
    const float* Wc2  = (const float*)d_in[18];
    const float* bc2  = (const float*)d_in[19];
    const float* h0   = (const float*)d_in[20];
    const float* c0   = (const float*)d_in[21];

    const int TBn = in_sizes[0] / DI;   // 65536
    const int T = TBn / BB;             // 256
    float* out = (float*)d_out;

    float *h2, *xg, *cbuf, *biasp;
    float4 *part, *partc;
    __half* l16;
    cudaGetSymbolAddress((void**)&h2,    g_h2);
    cudaGetSymbolAddress((void**)&xg,    g_xg);
    cudaGetSymbolAddress((void**)&cbuf,  g_cbuf);
    cudaGetSymbolAddress((void**)&biasp, g_biasp);
    cudaGetSymbolAddress((void**)&part,  g_part);
    cudaGetSymbolAddress((void**)&partc, g_partc);
    cudaGetSymbolAddress((void**)&l16,   g_l16);

    __half *xhi, *b1hi, *h2hi, *nhhi, *hmhi;
    __half *wt1h, *wt2h, *wihh, *whhh, *wa1h, *wa2h, *wc1h;
    cudaGetSymbolAddress((void**)&xhi,  g_x_hi);
    cudaGetSymbolAddress((void**)&b1hi, g_b1_hi);
    cudaGetSymbolAddress((void**)&h2hi, g_h2_hi);
    cudaGetSymbolAddress((void**)&nhhi, g_nh_hi);
    cudaGetSymbolAddress((void**)&hmhi, g_hm_hi);
    cudaGetSymbolAddress((void**)&wt1h, g_wt1_hi);
    cudaGetSymbolAddress((void**)&wt2h, g_wt2_hi);
    cudaGetSymbolAddress((void**)&wihh, g_wihp_hi);
    cudaGetSymbolAddress((void**)&whhh, g_whhp_hi);
    cudaGetSymbolAddress((void**)&wa1h, g_wa1_hi);
    cudaGetSymbolAddress((void**)&wa2h, g_wa2_hi);
    cudaGetSymbolAddress((void**)&wc1h, g_wc1_hi);

    cudaFuncSetAttribute((const void*)gemm16_kernel<0>, cudaFuncAttributeMaxDynamicSharedMemorySize, G_SMEM);
    cudaFuncSetAttribute((const void*)gemm16_kernel<1>, cudaFuncAttributeMaxDynamicSharedMemorySize, G_SMEM);
    cudaFuncSetAttribute((const void*)gemm16_kernel<2>, cudaFuncAttributeMaxDynamicSharedMemorySize, G_SMEM);
    cudaFuncSetAttribute((const void*)gemm16_kernel<3>, cudaFuncAttributeMaxDynamicSharedMemorySize, G_SMEM);
    cudaFuncSetAttribute((const void*)lstm_persist, cudaFuncAttributeMaxDynamicSharedMemorySize, LSTM_SMEM);

    const dim3 blk(256);

    convx_kernel<<<TBn * DI / 4 / 256, blk>>>(x, xhi, TBn * DI / 4);
    prep_kernel<<<dim3(1024, 8), blk>>>(W_t1, W_t2, Wa1, Wc1, Wa2, Wih, Whh, bih, bhh);
    init_state_kernel<<<(BB * LH + 255) / 256, blk>>>(h0, c0, done, hmhi, cbuf);

    const int MY = TBn / 128;
    // trunk (pure fp16)
    gemm16_kernel<1><<<dim3(4, MY), blk, G_SMEM>>>(
        xhi, wt1h, b_t1, nullptr, b1hi, nullptr, nullptr, nullptr, TBn, LH, DI);
    gemm16_kernel<1><<<dim3(4, MY), blk, G_SMEM>>>(
        b1hi, wt2h, b_t2, h2, h2hi, nullptr, nullptr, nullptr, TBn, LH, LH);
    gemm16_kernel<0><<<dim3(16, MY), blk, G_SMEM>>>(
        h2hi, wihh, biasp, xg, nullptr, nullptr, nullptr, nullptr, TBn, NG, LH);

    // persistent lstm scan (W resident, h fp16)
    lstm_persist<<<dim3(16, 8), blk, LSTM_SMEM>>>(
        whhh, xg, done, hmhi, cbuf, h2, nhhi, T);

    // actor head + fused softmax partials
    gemm16_kernel<1><<<dim3(4, MY), blk, G_SMEM>>>(
        nhhi, wa1h, ba1, nullptr, b1hi, nullptr, nullptr, nullptr, TBn, LH, LH);
    gemm16_kernel<2><<<dim3(8, MY), blk, G_SMEM>>>(
        b1hi, wa2h, ba2, nullptr, nullptr, l16, part, nullptr, TBn, NA, LH);

    // critic head fully fused
    gemm16_kernel<3><<<dim3(4, MY), blk, G_SMEM>>>(
        nhhi, wc1h, bc1, nullptr, nullptr, nullptr, partc, Wc2, TBn, LH, LH);

    // final combine: lp, ent, v
    heads_final_kernel<<<(TBn + 255) / 256, blk>>>(part, l16, act, partc, bc2, out, TBn);
}